// round 10
// baseline (speedup 1.0000x reference)
#include <cuda_runtime.h>
#include <cuda_fp16.h>
#include <math.h>
#include <stdint.h>

// Problem constants
#define Bsz 16
#define SEQ 1024
#define HID 1152
#define NH 16
#define HD 72
#define MLPD 4608
#define ROWS (Bsz * SEQ)          // 16384
#define MODW (6 * HID)            // 6912
#define EPS 1e-6f

// ---------------- scratch (device globals; allocation-free) ----------------
__device__ float  g_mod[Bsz * MODW];
__device__ __half g_xn16[ROWS * HID];
__device__ __half g_qkv16[ROWS * 3 * HID];
__device__ __half g_o16[ROWS * HID];
__device__ float  g_x1[ROWS * HID];
__device__ __half g_h16[ROWS * MLPD];
// fp16 transposed weights [N][K]
__device__ __half g_wqkvT16[3 * HID * HID];
__device__ __half g_wprojT16[HID * HID];
__device__ __half g_w1T16[HID * MLPD];
__device__ __half g_w2T16[MLPD * HID];

__device__ __forceinline__ void mma_f16(
    float& c0, float& c1, float& c2, float& c3,
    unsigned a0, unsigned a1, unsigned a2, unsigned a3,
    unsigned b0, unsigned b1)
{
    asm volatile(
        "mma.sync.aligned.m16n8k16.row.col.f32.f16.f16.f32 "
        "{%0,%1,%2,%3}, {%4,%5,%6,%7}, {%8,%9}, {%0,%1,%2,%3};"
        : "+f"(c0), "+f"(c1), "+f"(c2), "+f"(c3)
        : "r"(a0), "r"(a1), "r"(a2), "r"(a3), "r"(b0), "r"(b1));
}

__device__ __forceinline__ void ldsm_x4(
    unsigned& r0, unsigned& r1, unsigned& r2, unsigned& r3, uint32_t addr)
{
    asm volatile("ldmatrix.sync.aligned.m8n8.x4.shared.b16 {%0,%1,%2,%3}, [%4];"
                 : "=r"(r0), "=r"(r1), "=r"(r2), "=r"(r3) : "r"(addr));
}

__device__ __forceinline__ void ldsm_x2(
    unsigned& r0, unsigned& r1, uint32_t addr)
{
    asm volatile("ldmatrix.sync.aligned.m8n8.x2.shared.b16 {%0,%1}, [%2];"
                 : "=r"(r0), "=r"(r1) : "r"(addr));
}

__device__ __forceinline__ float ex2f(float x) {
    float r;
    asm("ex2.approx.f32 %0, %1;" : "=f"(r) : "f"(x));
    return r;
}

__device__ __forceinline__ void cp16s(uint32_t dst, const void* src) {
    asm volatile("cp.async.cg.shared.global [%0], [%1], 16;" :: "r"(dst), "l"(src));
}
__device__ __forceinline__ void cp_commit() {
    asm volatile("cp.async.commit_group;");
}
template <int N> __device__ __forceinline__ void cp_wait() {
    asm volatile("cp.async.wait_group %0;" :: "n"(N));
}
__device__ __forceinline__ uint32_t smem_u32(const void* p) {
    uint32_t a;
    asm("{ .reg .u64 t; cvta.to.shared.u64 t, %1; cvt.u32.u64 %0, t; }"
        : "=r"(a) : "l"(p));
    return a;
}
__device__ __forceinline__ unsigned h2u(__half2 h) {
    return *reinterpret_cast<unsigned*>(&h);
}

// ------- kernel 0: weight convert+transpose fp32 [K][N] -> fp16 [N][K] ------
__global__ __launch_bounds__(256) void wcvt_kernel(
    const float* __restrict__ w, __half* __restrict__ wt, int K, int N)
{
    __shared__ float t[32][33];
    int n0 = blockIdx.x * 32, k0 = blockIdx.y * 32;
    int tx = threadIdx.x & 31, ty = threadIdx.x >> 5;
    #pragma unroll
    for (int j = 0; j < 32; j += 8)
        t[ty + j][tx] = w[(size_t)(k0 + ty + j) * N + n0 + tx];
    __syncthreads();
    #pragma unroll
    for (int j = 0; j < 32; j += 8)
        wt[(size_t)(n0 + ty + j) * K + k0 + tx] = __float2half(t[tx][ty + j]);
}

// ------- kernel 1: mod = swish(c) @ w_mod + b_mod (batch-reuse version) -----
// One 128-col stripe per CTA; w_mod element loaded ONCE, used for all 16
// batches. k-dim split across two 128-thread halves, combined via smem.
#define MOD_SMEM ((Bsz * HID + 128 * 17) * 4)
__global__ __launch_bounds__(256) void mod_kernel(
    const float* __restrict__ c, const float* __restrict__ w_mod,
    const float* __restrict__ b_mod, float* __restrict__ mod)
{
    extern __shared__ float sm[];
    float* sc  = sm;                  // [16][1152] swish(c)
    float* red = sm + Bsz * HID;      // [128][17] partials (padded)
    int tid = threadIdx.x;
    for (int i = tid; i < Bsz * HID; i += 256) {
        float v = c[i];
        sc[i] = v / (1.f + __expf(-v));
    }
    __syncthreads();
    int cl = tid & 127;
    int kh = tid >> 7;                // 0 or 1: k-half
    int col = blockIdx.x * 128 + cl;
    float acc[Bsz];
    #pragma unroll
    for (int b = 0; b < Bsz; ++b) acc[b] = 0.f;
    int k0 = kh * (HID / 2);
    #pragma unroll 4
    for (int k = k0; k < k0 + HID / 2; ++k) {
        float w = w_mod[(size_t)k * MODW + col];
        #pragma unroll
        for (int b = 0; b < Bsz; ++b)
            acc[b] = fmaf(sc[b * HID + k], w, acc[b]);
    }
    if (kh) {
        #pragma unroll
        for (int b = 0; b < Bsz; ++b) red[cl * 17 + b] = acc[b];
    }
    __syncthreads();
    if (!kh) {
        float bm = b_mod[col];
        #pragma unroll
        for (int b = 0; b < Bsz; ++b)
            mod[b * MODW + col] = acc[b] + red[cl * 17 + b] + bm;
    }
}

// --------- kernel 2: LN(x) * (1+sc) + sh  (per row), fp16 output ------------
__global__ __launch_bounds__(256) void ln_mod_kernel(
    const float* __restrict__ x, const float* __restrict__ mod,
    int shOff, int scOff, __half* __restrict__ out)
{
    __shared__ float buf[HID];
    __shared__ float red[16];
    int row = blockIdx.x;
    int b = row >> 10;
    int tid = threadIdx.x;
    const float* xr = x + (size_t)row * HID;
    float s = 0.f, s2 = 0.f;
    for (int i = tid; i < 288; i += 256) {
        float4 v = *(const float4*)(xr + i * 4);
        *(float4*)(buf + i * 4) = v;
        s  += v.x + v.y + v.z + v.w;
        s2 += v.x * v.x + v.y * v.y + v.z * v.z + v.w * v.w;
    }
    #pragma unroll
    for (int o = 16; o; o >>= 1) {
        s  += __shfl_xor_sync(0xffffffffu, s,  o);
        s2 += __shfl_xor_sync(0xffffffffu, s2, o);
    }
    if ((tid & 31) == 0) { red[tid >> 5] = s; red[8 + (tid >> 5)] = s2; }
    __syncthreads();
    float S = 0.f, S2 = 0.f;
    #pragma unroll
    for (int w = 0; w < 8; ++w) { S += red[w]; S2 += red[8 + w]; }
    float mean = S * (1.f / HID);
    float var  = S2 * (1.f / HID) - mean * mean;
    float rstd = rsqrtf(var + EPS);
    const float* mrow = mod + b * MODW;
    __half* orow = out + (size_t)row * HID;
    for (int i = tid; i < 288; i += 256) {
        float4 v   = *(const float4*)(buf + i * 4);
        float4 sc4 = *(const float4*)(mrow + scOff + i * 4);
        float4 sh4 = *(const float4*)(mrow + shOff + i * 4);
        float o0 = fmaf((v.x - mean) * rstd, 1.f + sc4.x, sh4.x);
        float o1 = fmaf((v.y - mean) * rstd, 1.f + sc4.y, sh4.y);
        float o2 = fmaf((v.z - mean) * rstd, 1.f + sc4.z, sh4.z);
        float o3 = fmaf((v.w - mean) * rstd, 1.f + sc4.w, sh4.w);
        uint2 pk;
        pk.x = h2u(__floats2half2_rn(o0, o1));
        pk.y = h2u(__floats2half2_rn(o2, o3));
        *(uint2*)(orow + i * 4) = pk;
    }
}

// --------------- kernel 3: per-head LN of q and k (fp16, half2) -------------
__global__ __launch_bounds__(256) void qkln_kernel(
    __half* __restrict__ qkv, const float* __restrict__ g_q,
    const float* __restrict__ g_k)
{
    int warp = blockIdx.x * 8 + (threadIdx.x >> 5);
    int lane = threadIdx.x & 31;
    int h  = warp & 15;
    int qk = (warp >> 4) & 1;
    int bn = warp >> 5;
    __half2* p2 = (__half2*)(qkv + (size_t)bn * (3 * HID) + qk * HID + h * HD);
    float2 va = __half22float2(p2[lane]);
    float2 vb = (lane < 4) ? __half22float2(p2[32 + lane]) : make_float2(0.f, 0.f);
    float s  = va.x + va.y + vb.x + vb.y;
    float s2 = va.x * va.x + va.y * va.y + vb.x * vb.x + vb.y * vb.y;
    #pragma unroll
    for (int o = 16; o; o >>= 1) {
        s  += __shfl_xor_sync(0xffffffffu, s,  o);
        s2 += __shfl_xor_sync(0xffffffffu, s2, o);
    }
    float mean = s * (1.f / HD);
    float var  = s2 * (1.f / HD) - mean * mean;
    float rstd = rsqrtf(var + EPS);
    const float* g = qk ? g_k : g_q;
    float2 ga = *(const float2*)(g + 2 * lane);
    p2[lane] = __floats2half2_rn((va.x - mean) * rstd * ga.x,
                                 (va.y - mean) * rstd * ga.y);
    if (lane < 4) {
        float2 gb = *(const float2*)(g + 64 + 2 * lane);
        p2[32 + lane] = __floats2half2_rn((vb.x - mean) * rstd * gb.x,
                                          (vb.y - mean) * rstd * gb.y);
    }
}

// --------------- kernel 4: flash attention (fp16 mma + ldmatrix) ------------
#define AQ 128
#define AK 64
#define QH 88     // halves stride for qs/ks
#define VH 72     // halves stride for vst (dim-major, 72 rows)
#define ATTN_SMEM ((AQ * QH + AK * QH + HD * VH) * 2)
// softmax in base-2 domain: scale * log2(e)
#define SC2 0.17002324f

__global__ __launch_bounds__(256) void attn_kernel(
    const __half* __restrict__ qkv, __half* __restrict__ o)
{
    extern __shared__ __half smh[];
    __half* qs  = smh;                 // [128][88]
    __half* ks  = qs + AQ * QH;        // [64][88]
    __half* vst = ks + AK * QH;        // [72][72]

    int tid = threadIdx.x;
    int lane = tid & 31;
    int warp = tid >> 5;
    int grp = lane >> 2;
    int t4 = lane & 3;
    int m0 = warp * 16;
    int lsel = lane & 15;
    int ksel = (lane >> 4) * 8;

    int q0 = blockIdx.x * AQ;
    int h = blockIdx.y, b = blockIdx.z;
    const size_t baseBN = (size_t)b * SEQ * (3 * HID);
    const int hoff = h * HD;

    uint32_t qsA = smem_u32(qs);
    uint32_t ksA = smem_u32(ks);
    uint32_t vsA = smem_u32(vst);
    // x2 address for V dims 64..71
    uint32_t vsX2 = vsA + ((64 + (lane & 7)) * VH + ((lane >> 3) & 1) * 8) * 2;

    for (int idx = tid; idx < AQ * 9; idx += 256) {
        int r = idx / 9, c = (idx - r * 9) * 8;
        *(float4*)(qs + r * QH + c) =
            *(const float4*)(qkv + baseBN + (size_t)(q0 + r) * (3 * HID) + hoff + c);
    }
    // zero pads: qs/ks cols 72..79 (read by the 5th k16 S-step)
    for (int idx = tid; idx < AQ + AK; idx += 256) {
        __half* base = (idx < AQ) ? (qs + idx * QH) : (ks + (idx - AQ) * QH);
        *(float4*)(base + 72) = make_float4(0.f, 0.f, 0.f, 0.f);
    }

    float accO[9][4];
    #pragma unroll
    for (int di = 0; di < 9; ++di)
        #pragma unroll
        for (int e = 0; e < 4; ++e) accO[di][e] = 0.f;
    float mi0 = -INFINITY, mi1 = -INFINITY;
    float li0 = 0.f, li1 = 0.f;

    for (int kt = 0; kt < SEQ / AK; ++kt) {
        __syncthreads();
        int k0 = kt * AK;
        for (int idx = tid; idx < AK * 9; idx += 256) {
            int r = idx / 9, c = (idx - r * 9) * 8;
            *(float4*)(ks + r * QH + c) = *(const float4*)(
                qkv + baseBN + (size_t)(k0 + r) * (3 * HID) + HID + hoff + c);
        }
        for (int idx = tid; idx < AK * 36; idx += 256) {
            int key = idx / 36, d2 = (idx - key * 36) * 2;
            __half2 v = *(const __half2*)(
                qkv + baseBN + (size_t)(k0 + key) * (3 * HID) + 2 * HID + hoff + d2);
            vst[d2 * VH + key]       = __low2half(v);
            vst[(d2 + 1) * VH + key] = __high2half(v);
        }
        __syncthreads();

        // ---- S = Q K^T : ldmatrix-fed, 5 k16 steps ----
        float sacc[8][4];
        #pragma unroll
        for (int ni = 0; ni < 8; ++ni)
            #pragma unroll
            for (int e = 0; e < 4; ++e) sacc[ni][e] = 0.f;
        #pragma unroll
        for (int ksb = 0; ksb < 5; ++ksb) {
            int k16 = ksb * 16;
            unsigned a0, a1, a2, a3;
            ldsm_x4(a0, a1, a2, a3, qsA + ((m0 + lsel) * QH + k16 + ksel) * 2);
            unsigned bf[8][2];
            #pragma unroll
            for (int p = 0; p < 4; ++p)
                ldsm_x4(bf[2 * p][0], bf[2 * p + 1][0], bf[2 * p][1], bf[2 * p + 1][1],
                        ksA + ((p * 16 + lsel) * QH + k16 + ksel) * 2);
            #pragma unroll
            for (int ni = 0; ni < 8; ++ni)
                mma_f16(sacc[ni][0], sacc[ni][1], sacc[ni][2], sacc[ni][3],
                        a0, a1, a2, a3, bf[ni][0], bf[ni][1]);
        }

        // ---- online softmax (base-2 domain); P fragments in registers ----
        float rmax0 = -INFINITY, rmax1 = -INFINITY;
        #pragma unroll
        for (int ni = 0; ni < 8; ++ni) {
            sacc[ni][0] *= SC2; sacc[ni][1] *= SC2;
            sacc[ni][2] *= SC2; sacc[ni][3] *= SC2;
            rmax0 = fmaxf(rmax0, fmaxf(sacc[ni][0], sacc[ni][1]));
            rmax1 = fmaxf(rmax1, fmaxf(sacc[ni][2], sacc[ni][3]));
        }
        #pragma unroll
        for (int off = 1; off < 4; off <<= 1) {
            rmax0 = fmaxf(rmax0, __shfl_xor_sync(0xffffffffu, rmax0, off));
            rmax1 = fmaxf(rmax1, __shfl_xor_sync(0xffffffffu, rmax1, off));
        }
        float newm0 = fmaxf(mi0, rmax0);
        float newm1 = fmaxf(mi1, rmax1);
        float alpha0 = ex2f(mi0 - newm0);
        float alpha1 = ex2f(mi1 - newm1);
        mi0 = newm0; mi1 = newm1;
        float rsum0 = 0.f, rsum1 = 0.f;
        unsigned ph0[8], ph1[8];
        #pragma unroll
        for (int ni = 0; ni < 8; ++ni) {
            float p0 = ex2f(sacc[ni][0] - newm0);
            float p1 = ex2f(sacc[ni][1] - newm0);
            float p2 = ex2f(sacc[ni][2] - newm1);
            float p3 = ex2f(sacc[ni][3] - newm1);
            rsum0 += p0 + p1; rsum1 += p2 + p3;
            ph0[ni] = h2u(__floats2half2_rn(p0, p1));
            ph1[ni] = h2u(__floats2half2_rn(p2, p3));
        }
        #pragma unroll
        for (int off = 1; off < 4; off <<= 1) {
            rsum0 += __shfl_xor_sync(0xffffffffu, rsum0, off);
            rsum1 += __shfl_xor_sync(0xffffffffu, rsum1, off);
        }
        li0 = li0 * alpha0 + rsum0;
        li1 = li1 * alpha1 + rsum1;
        #pragma unroll
        for (int di = 0; di < 9; ++di) {
            accO[di][0] *= alpha0; accO[di][1] *= alpha0;
            accO[di][2] *= alpha1; accO[di][3] *= alpha1;
        }

        // ---- O += P V : 4 x4 + 1 x2 ldmatrix per kb (9 n8 tiles) ----
        #pragma unroll
        for (int kb = 0; kb < 4; ++kb) {
            unsigned a0 = ph0[2 * kb],     a2 = ph0[2 * kb + 1];
            unsigned a1 = ph1[2 * kb],     a3 = ph1[2 * kb + 1];
            unsigned vf[9][2];
            #pragma unroll
            for (int p = 0; p < 4; ++p)
                ldsm_x4(vf[2 * p][0], vf[2 * p + 1][0], vf[2 * p][1], vf[2 * p + 1][1],
                        vsA + ((p * 16 + lsel) * VH + kb * 16 + ksel) * 2);
            ldsm_x2(vf[8][0], vf[8][1], vsX2 + kb * 16 * 2);
            #pragma unroll
            for (int di = 0; di < 9; ++di)
                mma_f16(accO[di][0], accO[di][1], accO[di][2], accO[di][3],
                        a0, a1, a2, a3, vf[di][0], vf[di][1]);
        }
    }

    float inv0 = 1.f / li0, inv1 = 1.f / li1;
    int row0 = q0 + m0 + grp;
    size_t b0a = ((size_t)b * SEQ + row0) * HID + hoff;
    size_t b1a = ((size_t)b * SEQ + row0 + 8) * HID + hoff;
    #pragma unroll
    for (int di = 0; di < 9; ++di) {
        int d = di * 8 + t4 * 2;
        *(__half2*)(o + b0a + d) = __floats2half2_rn(accO[di][0] * inv0, accO[di][1] * inv0);
        *(__half2*)(o + b1a + d) = __floats2half2_rn(accO[di][2] * inv1, accO[di][3] * inv1);
    }
}

// --------------- kernel 5: FP16 GEMM 128x128x64, 3 stages, ldmatrix ---------
#define TBK 64
#define ASTRH 72                          // halves per smem row (64 + 8 pad)
#define TILE_H_BYTES (128 * ASTRH * 2)    // 18432
#define NSTAGE 3
#define GEMM_SMEM (NSTAGE * 2 * TILE_H_BYTES)   // 110592

template <int EPI, typename OutT>
__global__ __launch_bounds__(256) void hgemm_kernel(
    const __half* __restrict__ A, const __half* __restrict__ BT,
    const float* __restrict__ bias, const float* __restrict__ res,
    const float* __restrict__ gate, OutT* __restrict__ C,
    int M, int N, int K)
{
    extern __shared__ char smc[];
    uint32_t sbase = smem_u32(smc);

    int tid = threadIdx.x;
    int lane = tid & 31;
    int warp = tid >> 5;
    int m0 = (warp & 1) * 64;
    int n0 = (warp >> 1) * 32;
    int grp = lane >> 2;
    int t4 = lane & 3;
    int lsel = lane & 15;
    int ksel = (lane >> 4) * 8;

    int cRow = blockIdx.y, cCol = blockIdx.x;
    const __half* Ab = A + (size_t)cRow * 128 * K;
    const __half* Bb = BT + (size_t)cCol * 128 * K;

    float acc[4][4][4];
    #pragma unroll
    for (int mi = 0; mi < 4; ++mi)
        #pragma unroll
        for (int ni = 0; ni < 4; ++ni)
            #pragma unroll
            for (int e = 0; e < 4; ++e) acc[mi][ni][e] = 0.f;

    int KT = K / TBK;    // 18 or 72

    auto load_stage = [&](int kt, int s) {
        uint32_t aBase = sbase + s * TILE_H_BYTES;
        uint32_t bBase = sbase + (NSTAGE + s) * TILE_H_BYTES;
        const __half* Asrc = Ab + kt * TBK;
        const __half* Bsrc = Bb + kt * TBK;
        #pragma unroll
        for (int j = 0; j < 4; ++j) {
            int idx = tid + j * 256;
            int r = idx >> 3, c = idx & 7;
            cp16s(aBase + r * (ASTRH * 2) + c * 16, Asrc + (size_t)r * K + c * 8);
            cp16s(bBase + r * (ASTRH * 2) + c * 16, Bsrc + (size_t)r * K + c * 8);
        }
    };

    #pragma unroll
    for (int s = 0; s < NSTAGE - 1; ++s) {
        load_stage(s, s);
        cp_commit();
    }

    int st = 0;                  // compute stage
    int ps = NSTAGE - 1;         // prefetch stage
    for (int kt = 0; kt < KT; ++kt) {
        cp_wait<NSTAGE - 2>();
        __syncthreads();

        int pf = kt + NSTAGE - 1;
        if (pf < KT) load_stage(pf, ps);
        cp_commit();

        uint32_t aBase = sbase + st * TILE_H_BYTES;
        uint32_t bBase = sbase + (NSTAGE + st) * TILE_H_BYTES;
        #pragma unroll
        for (int ks = 0; ks < 4; ++ks) {
            int k16 = ks * 16;
            unsigned af[4][4], bf[4][2];
            #pragma unroll
            for (int mi = 0; mi < 4; ++mi)
                ldsm_x4(af[mi][0], af[mi][1], af[mi][2], af[mi][3],
                        aBase + ((m0 + mi * 16 + lsel) * ASTRH + k16 + ksel) * 2);
            ldsm_x4(bf[0][0], bf[1][0], bf[0][1], bf[1][1],
                    bBase + ((n0 + lsel) * ASTRH + k16 + ksel) * 2);
            ldsm_x4(bf[2][0], bf[3][0], bf[2][1], bf[3][1],
                    bBase + ((n0 + 16 + lsel) * ASTRH + k16 + ksel) * 2);
            #pragma unroll
            for (int mi = 0; mi < 4; ++mi)
                #pragma unroll
                for (int ni = 0; ni < 4; ++ni)
                    mma_f16(acc[mi][ni][0], acc[mi][ni][1], acc[mi][ni][2], acc[mi][ni][3],
                            af[mi][0], af[mi][1], af[mi][2], af[mi][3],
                            bf[ni][0], bf[ni][1]);
        }
        if (++st == NSTAGE) st = 0;
        if (++ps == NSTAGE) ps = 0;
    }

    // ---- epilogue ----
    #pragma unroll
    for (int mi = 0; mi < 4; ++mi) {
        #pragma unroll
        for (int half_ = 0; half_ < 2; ++half_) {
            int row = cRow * 128 + m0 + mi * 16 + grp + half_ * 8;
            int gb = (row >> 10) * MODW;
            #pragma unroll
            for (int ni = 0; ni < 4; ++ni) {
                int col = cCol * 128 + n0 + ni * 8 + t4 * 2;
                float v0 = acc[mi][ni][half_ * 2 + 0] + bias[col];
                float v1 = acc[mi][ni][half_ * 2 + 1] + bias[col + 1];
                if (EPI == 1) {
                    float i0 = 0.7978845608028654f * (v0 + 0.044715f * v0 * v0 * v0);
                    float i1 = 0.7978845608028654f * (v1 + 0.044715f * v1 * v1 * v1);
                    v0 = v0 / (1.f + __expf(-2.f * i0));
                    v1 = v1 / (1.f + __expf(-2.f * i1));
                } else if (EPI == 2) {
                    v0 = fmaf(gate[gb + col],     v0, res[(size_t)row * N + col]);
                    v1 = fmaf(gate[gb + col + 1], v1, res[(size_t)row * N + col + 1]);
                }
                OutT* dst = C + (size_t)row * N + col;
                if (sizeof(OutT) == 2) {
                    *(__half2*)dst = __floats2half2_rn(v0, v1);
                } else {
                    *(float2*)dst = make_float2(v0, v1);
                }
            }
        }
    }
}

// ---------------------------- launcher --------------------------------------
extern "C" void kernel_launch(void* const* d_in, const int* in_sizes, int n_in,
                              void* d_out, int out_size)
{
    const float* x      = (const float*)d_in[0];
    const float* c      = (const float*)d_in[1];
    const float* w_mod  = (const float*)d_in[2];
    const float* b_mod  = (const float*)d_in[3];
    const float* w_qkv  = (const float*)d_in[4];
    const float* b_qkv  = (const float*)d_in[5];
    const float* gq     = (const float*)d_in[6];
    const float* gk     = (const float*)d_in[7];
    const float* w_proj = (const float*)d_in[8];
    const float* b_proj = (const float*)d_in[9];
    const float* w1     = (const float*)d_in[10];
    const float* b1     = (const float*)d_in[11];
    const float* w2     = (const float*)d_in[12];
    const float* b2     = (const float*)d_in[13];
    float* out = (float*)d_out;

    float *p_mod, *p_x1;
    __half *p_xn16, *p_qkv16, *p_o16, *p_h16, *p_wqkvT, *p_wprojT, *p_w1T, *p_w2T;
    cudaGetSymbolAddress((void**)&p_mod, g_mod);
    cudaGetSymbolAddress((void**)&p_xn16, g_xn16);
    cudaGetSymbolAddress((void**)&p_qkv16, g_qkv16);
    cudaGetSymbolAddress((void**)&p_o16, g_o16);
    cudaGetSymbolAddress((void**)&p_x1,  g_x1);
    cudaGetSymbolAddress((void**)&p_h16, g_h16);
    cudaGetSymbolAddress((void**)&p_wqkvT, g_wqkvT16);
    cudaGetSymbolAddress((void**)&p_wprojT, g_wprojT16);
    cudaGetSymbolAddress((void**)&p_w1T, g_w1T16);
    cudaGetSymbolAddress((void**)&p_w2T, g_w2T16);

    cudaFuncSetAttribute(attn_kernel,
                         cudaFuncAttributeMaxDynamicSharedMemorySize, ATTN_SMEM);
    cudaFuncSetAttribute(mod_kernel,
                         cudaFuncAttributeMaxDynamicSharedMemorySize, MOD_SMEM);
    cudaFuncSetAttribute(hgemm_kernel<0, __half>,
                         cudaFuncAttributeMaxDynamicSharedMemorySize, GEMM_SMEM);
    cudaFuncSetAttribute(hgemm_kernel<1, __half>,
                         cudaFuncAttributeMaxDynamicSharedMemorySize, GEMM_SMEM);
    cudaFuncSetAttribute(hgemm_kernel<2, float>,
                         cudaFuncAttributeMaxDynamicSharedMemorySize, GEMM_SMEM);

    // 0. convert+transpose weights to fp16 [N][K]
    wcvt_kernel<<<dim3(3 * HID / 32, HID / 32), 256>>>(w_qkv, p_wqkvT, HID, 3 * HID);
    wcvt_kernel<<<dim3(HID / 32, HID / 32), 256>>>(w_proj, p_wprojT, HID, HID);
    wcvt_kernel<<<dim3(MLPD / 32, HID / 32), 256>>>(w1, p_w1T, HID, MLPD);
    wcvt_kernel<<<dim3(HID / 32, MLPD / 32), 256>>>(w2, p_w2T, MLPD, HID);

    // 1. adaLN modulation (batch-reuse)
    mod_kernel<<<MODW / 128, 256, MOD_SMEM>>>(c, w_mod, b_mod, p_mod);
    // 2. LN + modulate (MSA) -> fp16
    ln_mod_kernel<<<ROWS, 256>>>(x, p_mod, 0, HID, p_xn16);
    // 3. QKV GEMM -> fp16 qkv
    hgemm_kernel<0, __half><<<dim3(3 * HID / 128, ROWS / 128), 256, GEMM_SMEM>>>(
        p_xn16, p_wqkvT, b_qkv, nullptr, nullptr, p_qkv16, ROWS, 3 * HID, HID);
    // 4. per-head LN of q,k
    qkln_kernel<<<ROWS * 32 / 8, 256>>>(p_qkv16, gq, gk);
    // 5. attention -> fp16 o
    attn_kernel<<<dim3(SEQ / AQ, NH, Bsz), 256, ATTN_SMEM>>>(p_qkv16, p_o16);
    // 6. proj + gated residual -> fp32 x1
    hgemm_kernel<2, float><<<dim3(HID / 128, ROWS / 128), 256, GEMM_SMEM>>>(
        p_o16, p_wprojT, b_proj, x, p_mod + 2 * HID, p_x1, ROWS, HID, HID);
    // 7. LN + modulate (MLP) -> fp16
    ln_mod_kernel<<<ROWS, 256>>>(p_x1, p_mod, 3 * HID, 4 * HID, p_xn16);
    // 8. MLP up + gelu -> fp16 h
    hgemm_kernel<1, __half><<<dim3(MLPD / 128, ROWS / 128), 256, GEMM_SMEM>>>(
        p_xn16, p_w1T, b1, nullptr, nullptr, p_h16, ROWS, MLPD, HID);
    // 9. MLP down + gated residual -> fp32 out
    hgemm_kernel<2, float><<<dim3(HID / 128, ROWS / 128), 256, GEMM_SMEM>>>(
        p_h16, p_w2T, b2, p_x1, p_mod + 5 * HID, out, ROWS, HID, MLPD);
}

// round 11
// speedup vs baseline: 1.1205x; 1.1205x over previous
#include <cuda_runtime.h>
#include <cuda_fp16.h>
#include <math.h>
#include <stdint.h>

// Problem constants
#define Bsz 16
#define SEQ 1024
#define HID 1152
#define NH 16
#define HD 72
#define MLPD 4608
#define ROWS (Bsz * SEQ)          // 16384
#define MODW (6 * HID)            // 6912
#define EPS 1e-6f

// ---------------- scratch (device globals; allocation-free) ----------------
__device__ float  g_mod[Bsz * MODW];
__device__ __half g_xn16[ROWS * HID];
__device__ __half g_qkv16[ROWS * 3 * HID];
__device__ __half g_o16[ROWS * HID];
__device__ float  g_x1[ROWS * HID];
__device__ __half g_h16[ROWS * MLPD];
// fp16 transposed weights [N][K]
__device__ __half g_wqkvT16[3 * HID * HID];
__device__ __half g_wprojT16[HID * HID];
__device__ __half g_w1T16[HID * MLPD];
__device__ __half g_w2T16[MLPD * HID];

__device__ __forceinline__ void mma_f16(
    float& c0, float& c1, float& c2, float& c3,
    unsigned a0, unsigned a1, unsigned a2, unsigned a3,
    unsigned b0, unsigned b1)
{
    asm volatile(
        "mma.sync.aligned.m16n8k16.row.col.f32.f16.f16.f32 "
        "{%0,%1,%2,%3}, {%4,%5,%6,%7}, {%8,%9}, {%0,%1,%2,%3};"
        : "+f"(c0), "+f"(c1), "+f"(c2), "+f"(c3)
        : "r"(a0), "r"(a1), "r"(a2), "r"(a3), "r"(b0), "r"(b1));
}

__device__ __forceinline__ void ldsm_x4(
    unsigned& r0, unsigned& r1, unsigned& r2, unsigned& r3, uint32_t addr)
{
    asm volatile("ldmatrix.sync.aligned.m8n8.x4.shared.b16 {%0,%1,%2,%3}, [%4];"
                 : "=r"(r0), "=r"(r1), "=r"(r2), "=r"(r3) : "r"(addr));
}

__device__ __forceinline__ void ldsm_x4t(
    unsigned& r0, unsigned& r1, unsigned& r2, unsigned& r3, uint32_t addr)
{
    asm volatile("ldmatrix.sync.aligned.m8n8.x4.trans.shared.b16 {%0,%1,%2,%3}, [%4];"
                 : "=r"(r0), "=r"(r1), "=r"(r2), "=r"(r3) : "r"(addr));
}

__device__ __forceinline__ void ldsm_x2t(
    unsigned& r0, unsigned& r1, uint32_t addr)
{
    asm volatile("ldmatrix.sync.aligned.m8n8.x2.trans.shared.b16 {%0,%1}, [%2];"
                 : "=r"(r0), "=r"(r1) : "r"(addr));
}

__device__ __forceinline__ void cp16s(uint32_t dst, const void* src) {
    asm volatile("cp.async.cg.shared.global [%0], [%1], 16;" :: "r"(dst), "l"(src));
}
__device__ __forceinline__ void cp_commit() {
    asm volatile("cp.async.commit_group;");
}
template <int N> __device__ __forceinline__ void cp_wait() {
    asm volatile("cp.async.wait_group %0;" :: "n"(N));
}
__device__ __forceinline__ uint32_t smem_u32(const void* p) {
    uint32_t a;
    asm("{ .reg .u64 t; cvta.to.shared.u64 t, %1; cvt.u32.u64 %0, t; }"
        : "=r"(a) : "l"(p));
    return a;
}
__device__ __forceinline__ unsigned h2u(__half2 h) {
    return *reinterpret_cast<unsigned*>(&h);
}

// ------- kernel 0: weight convert+transpose fp32 [K][N] -> fp16 [N][K] ------
__global__ __launch_bounds__(256) void wcvt_kernel(
    const float* __restrict__ w, __half* __restrict__ wt, int K, int N)
{
    __shared__ float t[32][33];
    int n0 = blockIdx.x * 32, k0 = blockIdx.y * 32;
    int tx = threadIdx.x & 31, ty = threadIdx.x >> 5;
    #pragma unroll
    for (int j = 0; j < 32; j += 8)
        t[ty + j][tx] = w[(size_t)(k0 + ty + j) * N + n0 + tx];
    __syncthreads();
    #pragma unroll
    for (int j = 0; j < 32; j += 8)
        wt[(size_t)(n0 + ty + j) * K + k0 + tx] = __float2half(t[tx][ty + j]);
}

// ---------------- kernel 1: mod = swish(c) @ w_mod + b_mod ----------------
__global__ __launch_bounds__(128) void mod_kernel(
    const float* __restrict__ c, const float* __restrict__ w_mod,
    const float* __restrict__ b_mod, float* __restrict__ mod)
{
    __shared__ float sc[HID];
    int b = blockIdx.y;
    for (int i = threadIdx.x; i < HID; i += blockDim.x) {
        float v = c[b * HID + i];
        sc[i] = v / (1.0f + expf(-v));
    }
    __syncthreads();
    int col = blockIdx.x * blockDim.x + threadIdx.x;
    float acc = b_mod[col];
    #pragma unroll 4
    for (int k = 0; k < HID; ++k)
        acc = fmaf(sc[k], w_mod[(size_t)k * MODW + col], acc);
    mod[b * MODW + col] = acc;
}

// --------- kernel 2: LN(x) * (1+sc) + sh  (per row), fp16 output ------------
__global__ __launch_bounds__(256) void ln_mod_kernel(
    const float* __restrict__ x, const float* __restrict__ mod,
    int shOff, int scOff, __half* __restrict__ out)
{
    __shared__ float buf[HID];
    __shared__ float red[16];
    int row = blockIdx.x;
    int b = row >> 10;
    int tid = threadIdx.x;
    const float* xr = x + (size_t)row * HID;
    float s = 0.f, s2 = 0.f;
    for (int i = tid; i < 288; i += 256) {
        float4 v = *(const float4*)(xr + i * 4);
        *(float4*)(buf + i * 4) = v;
        s  += v.x + v.y + v.z + v.w;
        s2 += v.x * v.x + v.y * v.y + v.z * v.z + v.w * v.w;
    }
    #pragma unroll
    for (int o = 16; o; o >>= 1) {
        s  += __shfl_xor_sync(0xffffffffu, s,  o);
        s2 += __shfl_xor_sync(0xffffffffu, s2, o);
    }
    if ((tid & 31) == 0) { red[tid >> 5] = s; red[8 + (tid >> 5)] = s2; }
    __syncthreads();
    float S = 0.f, S2 = 0.f;
    #pragma unroll
    for (int w = 0; w < 8; ++w) { S += red[w]; S2 += red[8 + w]; }
    float mean = S * (1.f / HID);
    float var  = S2 * (1.f / HID) - mean * mean;
    float rstd = rsqrtf(var + EPS);
    const float* mrow = mod + b * MODW;
    __half* orow = out + (size_t)row * HID;
    for (int i = tid; i < 288; i += 256) {
        float4 v   = *(const float4*)(buf + i * 4);
        float4 sc4 = *(const float4*)(mrow + scOff + i * 4);
        float4 sh4 = *(const float4*)(mrow + shOff + i * 4);
        float o0 = fmaf((v.x - mean) * rstd, 1.f + sc4.x, sh4.x);
        float o1 = fmaf((v.y - mean) * rstd, 1.f + sc4.y, sh4.y);
        float o2 = fmaf((v.z - mean) * rstd, 1.f + sc4.z, sh4.z);
        float o3 = fmaf((v.w - mean) * rstd, 1.f + sc4.w, sh4.w);
        uint2 pk;
        pk.x = h2u(__floats2half2_rn(o0, o1));
        pk.y = h2u(__floats2half2_rn(o2, o3));
        *(uint2*)(orow + i * 4) = pk;
    }
}

// --------------- kernel 3: per-head LN of q and k (fp16, half2) -------------
__global__ __launch_bounds__(256) void qkln_kernel(
    __half* __restrict__ qkv, const float* __restrict__ g_q,
    const float* __restrict__ g_k)
{
    int warp = blockIdx.x * 8 + (threadIdx.x >> 5);
    int lane = threadIdx.x & 31;
    int h  = warp & 15;
    int qk = (warp >> 4) & 1;
    int bn = warp >> 5;
    __half2* p2 = (__half2*)(qkv + (size_t)bn * (3 * HID) + qk * HID + h * HD);
    float2 va = __half22float2(p2[lane]);
    float2 vb = (lane < 4) ? __half22float2(p2[32 + lane]) : make_float2(0.f, 0.f);
    float s  = va.x + va.y + vb.x + vb.y;
    float s2 = va.x * va.x + va.y * va.y + vb.x * vb.x + vb.y * vb.y;
    #pragma unroll
    for (int o = 16; o; o >>= 1) {
        s  += __shfl_xor_sync(0xffffffffu, s,  o);
        s2 += __shfl_xor_sync(0xffffffffu, s2, o);
    }
    float mean = s * (1.f / HD);
    float var  = s2 * (1.f / HD) - mean * mean;
    float rstd = rsqrtf(var + EPS);
    const float* g = qk ? g_k : g_q;
    float2 ga = *(const float2*)(g + 2 * lane);
    p2[lane] = __floats2half2_rn((va.x - mean) * rstd * ga.x,
                                 (va.y - mean) * rstd * ga.y);
    if (lane < 4) {
        float2 gb = *(const float2*)(g + 64 + 2 * lane);
        p2[32 + lane] = __floats2half2_rn((vb.x - mean) * rstd * gb.x,
                                          (vb.y - mean) * rstd * gb.y);
    }
}

// ------- kernel 4: flash attention (cp.async K/V pipeline + trans ldsm) -----
#define AQ 128
#define AK 64
#define QH 88     // halves stride for qs/ks/vs rows
#define KVBUF_H (AK * QH)                  // halves per K or V buffer
#define ATTN_SMEM ((AQ * QH + 4 * KVBUF_H) * 2)   // 67584 bytes

__global__ __launch_bounds__(256) void attn_kernel(
    const __half* __restrict__ qkv, __half* __restrict__ o)
{
    extern __shared__ __half smh[];
    __half* qs = smh;                      // [128][88]
    __half* kv = qs + AQ * QH;             // [2][ks 64x88, vs 64x88]

    int tid = threadIdx.x;
    int lane = tid & 31;
    int warp = tid >> 5;
    int grp = lane >> 2;
    int t4 = lane & 3;
    int m0 = warp * 16;
    int lsel = lane & 15;
    int ksel = (lane >> 4) * 8;

    int q0 = blockIdx.x * AQ;
    int h = blockIdx.y, b = blockIdx.z;
    const size_t baseBN = (size_t)b * SEQ * (3 * HID);
    const int hoff = h * HD;
    const float scale = 0.11785113019775793f;

    uint32_t qsA = smem_u32(qs);
    uint32_t kvA = smem_u32(kv);
    // trans-ldmatrix per-lane relative offsets (into a V buffer, halves)
    //   x4: row = ((lane>>3)&1)*8 + (lane&7), col-base = (lane>>4)*8
    int vrow4 = ((lane >> 3) & 1) * 8 + (lane & 7);
    int vcol4 = (lane >> 4) * 8;
    uint32_t vrel4 = (uint32_t)(vrow4 * QH + vcol4) * 2;
    //   x2 (lanes 0..15 meaningful): row same formula on lane&15, col = 64
    int vrow2 = (((lane & 15) >> 3) & 1) * 8 + (lane & 7);
    uint32_t vrel2 = (uint32_t)(vrow2 * QH + 64) * 2;

    // load Q tile (9 x 16B chunks per row)
    for (int idx = tid; idx < AQ * 9; idx += 256) {
        int r = idx / 9, c = (idx - r * 9) * 8;
        *(float4*)(qs + r * QH + c) =
            *(const float4*)(qkv + baseBN + (size_t)(q0 + r) * (3 * HID) + hoff + c);
    }
    // zero pads: qs cols 72..79, and ks cols 72..79 in BOTH buffers
    // (cp.async never writes cols >= 72, so these stay zero)
    for (int idx = tid; idx < AQ + 2 * AK; idx += 256) {
        __half* base;
        if (idx < AQ)            base = qs + idx * QH;
        else if (idx < AQ + AK)  base = kv + (idx - AQ) * QH;               // ks buf 0
        else                     base = kv + 2 * KVBUF_H + (idx - AQ - AK) * QH; // ks buf 1
        *(float4*)(base + 72) = make_float4(0.f, 0.f, 0.f, 0.f);
    }

    // K/V tile loader: 1152 x 16B chunks (K first 576, V next 576)
    auto load_kv = [&](int kt, int bi) {
        uint32_t kD = kvA + (uint32_t)bi * (2 * KVBUF_H * 2);
        uint32_t vD = kD + KVBUF_H * 2;
        const __half* base = qkv + baseBN + (size_t)(kt * AK) * (3 * HID) + hoff;
        for (int idx = tid; idx < 1152; idx += 256) {
            int isv = idx >= 576;
            int j = isv ? idx - 576 : idx;
            int r = j / 9, c = (j - r * 9) * 8;
            const __half* src = base + (size_t)r * (3 * HID) + (isv ? 2 * HID : HID) + c;
            cp16s((isv ? vD : kD) + (uint32_t)(r * QH + c) * 2, src);
        }
    };

    float accO[9][4];
    #pragma unroll
    for (int di = 0; di < 9; ++di)
        #pragma unroll
        for (int e = 0; e < 4; ++e) accO[di][e] = 0.f;
    float mi0 = -INFINITY, mi1 = -INFINITY;
    float li0 = 0.f, li1 = 0.f;

    load_kv(0, 0);
    cp_commit();

    for (int kt = 0; kt < SEQ / AK; ++kt) {
        cp_wait<0>();
        __syncthreads();   // tile kt resident; all warps done with other buffer

        if (kt + 1 < SEQ / AK) {
            load_kv(kt + 1, (kt + 1) & 1);
        }
        cp_commit();

        uint32_t ksCur = kvA + (uint32_t)(kt & 1) * (2 * KVBUF_H * 2);
        uint32_t vsCur = ksCur + KVBUF_H * 2;

        // ---- S = Q K^T : ldmatrix-fed, 5 k16 steps ----
        float sacc[8][4];
        #pragma unroll
        for (int ni = 0; ni < 8; ++ni)
            #pragma unroll
            for (int e = 0; e < 4; ++e) sacc[ni][e] = 0.f;
        #pragma unroll
        for (int ksb = 0; ksb < 5; ++ksb) {
            int k16 = ksb * 16;
            unsigned a0, a1, a2, a3;
            ldsm_x4(a0, a1, a2, a3, qsA + ((m0 + lsel) * QH + k16 + ksel) * 2);
            unsigned bf[8][2];
            #pragma unroll
            for (int p = 0; p < 4; ++p)
                ldsm_x4(bf[2 * p][0], bf[2 * p + 1][0], bf[2 * p][1], bf[2 * p + 1][1],
                        ksCur + ((p * 16 + lsel) * QH + k16 + ksel) * 2);
            #pragma unroll
            for (int ni = 0; ni < 8; ++ni)
                mma_f16(sacc[ni][0], sacc[ni][1], sacc[ni][2], sacc[ni][3],
                        a0, a1, a2, a3, bf[ni][0], bf[ni][1]);
        }

        // ---- online softmax; P fragments in registers ----
        float rmax0 = -INFINITY, rmax1 = -INFINITY;
        #pragma unroll
        for (int ni = 0; ni < 8; ++ni) {
            sacc[ni][0] *= scale; sacc[ni][1] *= scale;
            sacc[ni][2] *= scale; sacc[ni][3] *= scale;
            rmax0 = fmaxf(rmax0, fmaxf(sacc[ni][0], sacc[ni][1]));
            rmax1 = fmaxf(rmax1, fmaxf(sacc[ni][2], sacc[ni][3]));
        }
        #pragma unroll
        for (int off = 1; off < 4; off <<= 1) {
            rmax0 = fmaxf(rmax0, __shfl_xor_sync(0xffffffffu, rmax0, off));
            rmax1 = fmaxf(rmax1, __shfl_xor_sync(0xffffffffu, rmax1, off));
        }
        float newm0 = fmaxf(mi0, rmax0);
        float newm1 = fmaxf(mi1, rmax1);
        float alpha0 = __expf(mi0 - newm0);
        float alpha1 = __expf(mi1 - newm1);
        mi0 = newm0; mi1 = newm1;
        float rsum0 = 0.f, rsum1 = 0.f;
        unsigned ph0[8], ph1[8];
        #pragma unroll
        for (int ni = 0; ni < 8; ++ni) {
            float p0 = __expf(sacc[ni][0] - newm0);
            float p1 = __expf(sacc[ni][1] - newm0);
            float p2 = __expf(sacc[ni][2] - newm1);
            float p3 = __expf(sacc[ni][3] - newm1);
            rsum0 += p0 + p1; rsum1 += p2 + p3;
            ph0[ni] = h2u(__floats2half2_rn(p0, p1));
            ph1[ni] = h2u(__floats2half2_rn(p2, p3));
        }
        #pragma unroll
        for (int off = 1; off < 4; off <<= 1) {
            rsum0 += __shfl_xor_sync(0xffffffffu, rsum0, off);
            rsum1 += __shfl_xor_sync(0xffffffffu, rsum1, off);
        }
        li0 = li0 * alpha0 + rsum0;
        li1 = li1 * alpha1 + rsum1;
        #pragma unroll
        for (int di = 0; di < 9; ++di) {
            accO[di][0] *= alpha0; accO[di][1] *= alpha0;
            accO[di][2] *= alpha1; accO[di][3] *= alpha1;
        }

        // ---- O += P V : V row-major, trans-ldmatrix B fragments ----
        #pragma unroll
        for (int kb = 0; kb < 4; ++kb) {
            unsigned a0 = ph0[2 * kb],     a2 = ph0[2 * kb + 1];
            unsigned a1 = ph1[2 * kb],     a3 = ph1[2 * kb + 1];
            uint32_t vkb = vsCur + (uint32_t)(kb * 16 * QH) * 2;
            unsigned vf[9][2];
            #pragma unroll
            for (int p = 0; p < 4; ++p)
                ldsm_x4t(vf[2 * p][0], vf[2 * p][1], vf[2 * p + 1][0], vf[2 * p + 1][1],
                         vkb + vrel4 + (uint32_t)(p * 16) * 2);
            ldsm_x2t(vf[8][0], vf[8][1], vkb + vrel2);
            #pragma unroll
            for (int di = 0; di < 9; ++di)
                mma_f16(accO[di][0], accO[di][1], accO[di][2], accO[di][3],
                        a0, a1, a2, a3, vf[di][0], vf[di][1]);
        }
    }

    float inv0 = 1.f / li0, inv1 = 1.f / li1;
    int row0 = q0 + m0 + grp;
    size_t b0a = ((size_t)b * SEQ + row0) * HID + hoff;
    size_t b1a = ((size_t)b * SEQ + row0 + 8) * HID + hoff;
    #pragma unroll
    for (int di = 0; di < 9; ++di) {
        int d = di * 8 + t4 * 2;
        *(__half2*)(o + b0a + d) = __floats2half2_rn(accO[di][0] * inv0, accO[di][1] * inv0);
        *(__half2*)(o + b1a + d) = __floats2half2_rn(accO[di][2] * inv1, accO[di][3] * inv1);
    }
}

// --------------- kernel 5: FP16 GEMM 128x128x64, 3 stages, ldmatrix ---------
#define TBK 64
#define ASTRH 72                          // halves per smem row (64 + 8 pad)
#define TILE_H_BYTES (128 * ASTRH * 2)    // 18432
#define NSTAGE 3
#define GEMM_SMEM (NSTAGE * 2 * TILE_H_BYTES)   // 110592

template <int EPI, typename OutT>
__global__ __launch_bounds__(256) void hgemm_kernel(
    const __half* __restrict__ A, const __half* __restrict__ BT,
    const float* __restrict__ bias, const float* __restrict__ res,
    const float* __restrict__ gate, OutT* __restrict__ C,
    int M, int N, int K)
{
    extern __shared__ char smc[];
    uint32_t sbase = smem_u32(smc);

    int tid = threadIdx.x;
    int lane = tid & 31;
    int warp = tid >> 5;
    int m0 = (warp & 1) * 64;
    int n0 = (warp >> 1) * 32;
    int grp = lane >> 2;
    int t4 = lane & 3;
    int lsel = lane & 15;
    int ksel = (lane >> 4) * 8;

    int cRow = blockIdx.y, cCol = blockIdx.x;
    const __half* Ab = A + (size_t)cRow * 128 * K;
    const __half* Bb = BT + (size_t)cCol * 128 * K;

    float acc[4][4][4];
    #pragma unroll
    for (int mi = 0; mi < 4; ++mi)
        #pragma unroll
        for (int ni = 0; ni < 4; ++ni)
            #pragma unroll
            for (int e = 0; e < 4; ++e) acc[mi][ni][e] = 0.f;

    int KT = K / TBK;    // 18 or 72

    auto load_stage = [&](int kt, int s) {
        uint32_t aBase = sbase + s * TILE_H_BYTES;
        uint32_t bBase = sbase + (NSTAGE + s) * TILE_H_BYTES;
        const __half* Asrc = Ab + kt * TBK;
        const __half* Bsrc = Bb + kt * TBK;
        #pragma unroll
        for (int j = 0; j < 4; ++j) {
            int idx = tid + j * 256;
            int r = idx >> 3, c = idx & 7;
            cp16s(aBase + r * (ASTRH * 2) + c * 16, Asrc + (size_t)r * K + c * 8);
            cp16s(bBase + r * (ASTRH * 2) + c * 16, Bsrc + (size_t)r * K + c * 8);
        }
    };

    #pragma unroll
    for (int s = 0; s < NSTAGE - 1; ++s) {
        load_stage(s, s);
        cp_commit();
    }

    for (int kt = 0; kt < KT; ++kt) {
        cp_wait<NSTAGE - 2>();
        __syncthreads();

        int pf = kt + NSTAGE - 1;
        if (pf < KT) load_stage(pf, pf % NSTAGE);
        cp_commit();

        int st = kt % NSTAGE;
        uint32_t aBase = sbase + st * TILE_H_BYTES;
        uint32_t bBase = sbase + (NSTAGE + st) * TILE_H_BYTES;
        #pragma unroll
        for (int ks = 0; ks < 4; ++ks) {
            int k16 = ks * 16;
            unsigned af[4][4], bf[4][2];
            #pragma unroll
            for (int mi = 0; mi < 4; ++mi)
                ldsm_x4(af[mi][0], af[mi][1], af[mi][2], af[mi][3],
                        aBase + ((m0 + mi * 16 + lsel) * ASTRH + k16 + ksel) * 2);
            ldsm_x4(bf[0][0], bf[1][0], bf[0][1], bf[1][1],
                    bBase + ((n0 + lsel) * ASTRH + k16 + ksel) * 2);
            ldsm_x4(bf[2][0], bf[3][0], bf[2][1], bf[3][1],
                    bBase + ((n0 + 16 + lsel) * ASTRH + k16 + ksel) * 2);
            #pragma unroll
            for (int mi = 0; mi < 4; ++mi)
                #pragma unroll
                for (int ni = 0; ni < 4; ++ni)
                    mma_f16(acc[mi][ni][0], acc[mi][ni][1], acc[mi][ni][2], acc[mi][ni][3],
                            af[mi][0], af[mi][1], af[mi][2], af[mi][3],
                            bf[ni][0], bf[ni][1]);
        }
    }

    // ---- epilogue ----
    #pragma unroll
    for (int mi = 0; mi < 4; ++mi) {
        #pragma unroll
        for (int half_ = 0; half_ < 2; ++half_) {
            int row = cRow * 128 + m0 + mi * 16 + grp + half_ * 8;
            int gb = (row >> 10) * MODW;
            #pragma unroll
            for (int ni = 0; ni < 4; ++ni) {
                int col = cCol * 128 + n0 + ni * 8 + t4 * 2;
                float v0 = acc[mi][ni][half_ * 2 + 0] + bias[col];
                float v1 = acc[mi][ni][half_ * 2 + 1] + bias[col + 1];
                if (EPI == 1) {
                    float i0 = 0.7978845608028654f * (v0 + 0.044715f * v0 * v0 * v0);
                    float i1 = 0.7978845608028654f * (v1 + 0.044715f * v1 * v1 * v1);
                    v0 = v0 / (1.f + __expf(-2.f * i0));
                    v1 = v1 / (1.f + __expf(-2.f * i1));
                } else if (EPI == 2) {
                    v0 = fmaf(gate[gb + col],     v0, res[(size_t)row * N + col]);
                    v1 = fmaf(gate[gb + col + 1], v1, res[(size_t)row * N + col + 1]);
                }
                OutT* dst = C + (size_t)row * N + col;
                if (sizeof(OutT) == 2) {
                    *(__half2*)dst = __floats2half2_rn(v0, v1);
                } else {
                    *(float2*)dst = make_float2(v0, v1);
                }
            }
        }
    }
}

// ---------------------------- launcher --------------------------------------
extern "C" void kernel_launch(void* const* d_in, const int* in_sizes, int n_in,
                              void* d_out, int out_size)
{
    const float* x      = (const float*)d_in[0];
    const float* c      = (const float*)d_in[1];
    const float* w_mod  = (const float*)d_in[2];
    const float* b_mod  = (const float*)d_in[3];
    const float* w_qkv  = (const float*)d_in[4];
    const float* b_qkv  = (const float*)d_in[5];
    const float* gq     = (const float*)d_in[6];
    const float* gk     = (const float*)d_in[7];
    const float* w_proj = (const float*)d_in[8];
    const float* b_proj = (const float*)d_in[9];
    const float* w1     = (const float*)d_in[10];
    const float* b1     = (const float*)d_in[11];
    const float* w2     = (const float*)d_in[12];
    const float* b2     = (const float*)d_in[13];
    float* out = (float*)d_out;

    float *p_mod, *p_x1;
    __half *p_xn16, *p_qkv16, *p_o16, *p_h16, *p_wqkvT, *p_wprojT, *p_w1T, *p_w2T;
    cudaGetSymbolAddress((void**)&p_mod, g_mod);
    cudaGetSymbolAddress((void**)&p_xn16, g_xn16);
    cudaGetSymbolAddress((void**)&p_qkv16, g_qkv16);
    cudaGetSymbolAddress((void**)&p_o16, g_o16);
    cudaGetSymbolAddress((void**)&p_x1,  g_x1);
    cudaGetSymbolAddress((void**)&p_h16, g_h16);
    cudaGetSymbolAddress((void**)&p_wqkvT, g_wqkvT16);
    cudaGetSymbolAddress((void**)&p_wprojT, g_wprojT16);
    cudaGetSymbolAddress((void**)&p_w1T, g_w1T16);
    cudaGetSymbolAddress((void**)&p_w2T, g_w2T16);

    cudaFuncSetAttribute(attn_kernel,
                         cudaFuncAttributeMaxDynamicSharedMemorySize, ATTN_SMEM);
    cudaFuncSetAttribute(hgemm_kernel<0, __half>,
                         cudaFuncAttributeMaxDynamicSharedMemorySize, GEMM_SMEM);
    cudaFuncSetAttribute(hgemm_kernel<1, __half>,
                         cudaFuncAttributeMaxDynamicSharedMemorySize, GEMM_SMEM);
    cudaFuncSetAttribute(hgemm_kernel<2, float>,
                         cudaFuncAttributeMaxDynamicSharedMemorySize, GEMM_SMEM);

    // 0. convert+transpose weights to fp16 [N][K]
    wcvt_kernel<<<dim3(3 * HID / 32, HID / 32), 256>>>(w_qkv, p_wqkvT, HID, 3 * HID);
    wcvt_kernel<<<dim3(HID / 32, HID / 32), 256>>>(w_proj, p_wprojT, HID, HID);
    wcvt_kernel<<<dim3(MLPD / 32, HID / 32), 256>>>(w1, p_w1T, HID, MLPD);
    wcvt_kernel<<<dim3(HID / 32, MLPD / 32), 256>>>(w2, p_w2T, MLPD, HID);

    // 1. adaLN modulation
    mod_kernel<<<dim3(MODW / 128, Bsz), 128>>>(c, w_mod, b_mod, p_mod);
    // 2. LN + modulate (MSA) -> fp16
    ln_mod_kernel<<<ROWS, 256>>>(x, p_mod, 0, HID, p_xn16);
    // 3. QKV GEMM -> fp16 qkv
    hgemm_kernel<0, __half><<<dim3(3 * HID / 128, ROWS / 128), 256, GEMM_SMEM>>>(
        p_xn16, p_wqkvT, b_qkv, nullptr, nullptr, p_qkv16, ROWS, 3 * HID, HID);
    // 4. per-head LN of q,k
    qkln_kernel<<<ROWS * 32 / 8, 256>>>(p_qkv16, gq, gk);
    // 5. attention -> fp16 o
    attn_kernel<<<dim3(SEQ / AQ, NH, Bsz), 256, ATTN_SMEM>>>(p_qkv16, p_o16);
    // 6. proj + gated residual -> fp32 x1
    hgemm_kernel<2, float><<<dim3(HID / 128, ROWS / 128), 256, GEMM_SMEM>>>(
        p_o16, p_wprojT, b_proj, x, p_mod + 2 * HID, p_x1, ROWS, HID, HID);
    // 7. LN + modulate (MLP) -> fp16
    ln_mod_kernel<<<ROWS, 256>>>(p_x1, p_mod, 3 * HID, 4 * HID, p_xn16);
    // 8. MLP up + gelu -> fp16 h
    hgemm_kernel<1, __half><<<dim3(MLPD / 128, ROWS / 128), 256, GEMM_SMEM>>>(
        p_xn16, p_w1T, b1, nullptr, nullptr, p_h16, ROWS, MLPD, HID);
    // 9. MLP down + gated residual -> fp32 out
    hgemm_kernel<2, float><<<dim3(HID / 128, ROWS / 128), 256, GEMM_SMEM>>>(
        p_h16, p_w2T, b2, p_x1, p_mod + 5 * HID, out, ROWS, HID, MLPD);
}

// round 12
// speedup vs baseline: 1.1608x; 1.0359x over previous
#include <cuda_runtime.h>
#include <cuda_fp16.h>
#include <math.h>
#include <stdint.h>

// Problem constants
#define Bsz 16
#define SEQ 1024
#define HID 1152
#define NH 16
#define HD 72
#define MLPD 4608
#define ROWS (Bsz * SEQ)          // 16384
#define MODW (6 * HID)            // 6912
#define EPS 1e-6f

// ---------------- scratch (device globals; allocation-free) ----------------
__device__ float  g_mod[Bsz * MODW];
__device__ __half g_xn16[ROWS * HID];
__device__ __half g_qkv16[ROWS * 3 * HID];
__device__ __half g_o16[ROWS * HID];
__device__ float  g_x1[ROWS * HID];
__device__ __half g_h16[ROWS * MLPD];
// fp16 transposed weights [N][K]
__device__ __half g_wqkvT16[3 * HID * HID];
__device__ __half g_wprojT16[HID * HID];
__device__ __half g_w1T16[HID * MLPD];
__device__ __half g_w2T16[MLPD * HID];

__device__ __forceinline__ void mma_f16(
    float& c0, float& c1, float& c2, float& c3,
    unsigned a0, unsigned a1, unsigned a2, unsigned a3,
    unsigned b0, unsigned b1)
{
    asm volatile(
        "mma.sync.aligned.m16n8k16.row.col.f32.f16.f16.f32 "
        "{%0,%1,%2,%3}, {%4,%5,%6,%7}, {%8,%9}, {%0,%1,%2,%3};"
        : "+f"(c0), "+f"(c1), "+f"(c2), "+f"(c3)
        : "r"(a0), "r"(a1), "r"(a2), "r"(a3), "r"(b0), "r"(b1));
}

__device__ __forceinline__ void ldsm_x4(
    unsigned& r0, unsigned& r1, unsigned& r2, unsigned& r3, uint32_t addr)
{
    asm volatile("ldmatrix.sync.aligned.m8n8.x4.shared.b16 {%0,%1,%2,%3}, [%4];"
                 : "=r"(r0), "=r"(r1), "=r"(r2), "=r"(r3) : "r"(addr));
}

__device__ __forceinline__ void ldsm_x4t(
    unsigned& r0, unsigned& r1, unsigned& r2, unsigned& r3, uint32_t addr)
{
    asm volatile("ldmatrix.sync.aligned.m8n8.x4.trans.shared.b16 {%0,%1,%2,%3}, [%4];"
                 : "=r"(r0), "=r"(r1), "=r"(r2), "=r"(r3) : "r"(addr));
}

__device__ __forceinline__ void ldsm_x2t(
    unsigned& r0, unsigned& r1, uint32_t addr)
{
    asm volatile("ldmatrix.sync.aligned.m8n8.x2.trans.shared.b16 {%0,%1}, [%2];"
                 : "=r"(r0), "=r"(r1) : "r"(addr));
}

__device__ __forceinline__ void cp16s(uint32_t dst, const void* src) {
    asm volatile("cp.async.cg.shared.global [%0], [%1], 16;" :: "r"(dst), "l"(src));
}
__device__ __forceinline__ void cp_commit() {
    asm volatile("cp.async.commit_group;");
}
template <int N> __device__ __forceinline__ void cp_wait() {
    asm volatile("cp.async.wait_group %0;" :: "n"(N));
}
__device__ __forceinline__ uint32_t smem_u32(const void* p) {
    uint32_t a;
    asm("{ .reg .u64 t; cvta.to.shared.u64 t, %1; cvt.u32.u64 %0, t; }"
        : "=r"(a) : "l"(p));
    return a;
}
__device__ __forceinline__ unsigned h2u(__half2 h) {
    return *reinterpret_cast<unsigned*>(&h);
}

// ------- kernel 0: weight convert+transpose fp32 [K][N] -> fp16 [N][K] ------
__global__ __launch_bounds__(256) void wcvt_kernel(
    const float* __restrict__ w, __half* __restrict__ wt, int K, int N)
{
    __shared__ float t[32][33];
    int n0 = blockIdx.x * 32, k0 = blockIdx.y * 32;
    int tx = threadIdx.x & 31, ty = threadIdx.x >> 5;
    #pragma unroll
    for (int j = 0; j < 32; j += 8)
        t[ty + j][tx] = w[(size_t)(k0 + ty + j) * N + n0 + tx];
    __syncthreads();
    #pragma unroll
    for (int j = 0; j < 32; j += 8)
        wt[(size_t)(n0 + ty + j) * K + k0 + tx] = __float2half(t[tx][ty + j]);
}

// ------- kernel 1: mod = swish(c) @ w_mod + b_mod (batch-reuse) -------------
// 216 CTAs x 32-col stripes. Each w_mod element loaded ONCE (32 MB total, vs
// 512 MB in the per-batch version). swish(c) stored transposed [k][b] so the
// 16 batch factors per k are 4 x LDS.128. k split across 8 thread-groups,
// combined via smem.
#define MODKG 8
#define MODKL (HID / MODKG)      // 144
#define MOD_SMEM ((Bsz * HID + MODKG * 32 * Bsz) * 4)   // 90112 bytes
__global__ __launch_bounds__(256) void mod_kernel(
    const float* __restrict__ c, const float* __restrict__ w_mod,
    const float* __restrict__ b_mod, float* __restrict__ mod)
{
    extern __shared__ float sm[];
    float* sct = sm;                   // [1152][16] swish(c) transposed
    float* red = sm + Bsz * HID;       // [8][32][16] partials
    int tid = threadIdx.x;
    for (int i = tid; i < Bsz * HID; i += 256) {
        int b = i / HID, k = i - b * HID;
        float v = c[i];
        sct[k * Bsz + b] = v / (1.f + expf(-v));
    }
    __syncthreads();
    int cl = tid & 31;
    int kg = tid >> 5;                 // 0..7
    int col = blockIdx.x * 32 + cl;
    float acc[Bsz];
    #pragma unroll
    for (int b = 0; b < Bsz; ++b) acc[b] = 0.f;
    int k0 = kg * MODKL;
    for (int k = k0; k < k0 + MODKL; ++k) {
        float w = w_mod[(size_t)k * MODW + col];
        const float4* s4 = (const float4*)(sct + k * Bsz);
        #pragma unroll
        for (int b4 = 0; b4 < 4; ++b4) {
            float4 s = s4[b4];
            acc[4 * b4 + 0] = fmaf(s.x, w, acc[4 * b4 + 0]);
            acc[4 * b4 + 1] = fmaf(s.y, w, acc[4 * b4 + 1]);
            acc[4 * b4 + 2] = fmaf(s.z, w, acc[4 * b4 + 2]);
            acc[4 * b4 + 3] = fmaf(s.w, w, acc[4 * b4 + 3]);
        }
    }
    #pragma unroll
    for (int b = 0; b < Bsz; ++b)
        red[(kg * 32 + cl) * Bsz + b] = acc[b];
    __syncthreads();
    // 512 (col,b) tasks over 256 threads: 2 each
    #pragma unroll
    for (int t = 0; t < 2; ++t) {
        int task = tid + t * 256;
        int tc = task >> 4;            // col-lane 0..31
        int tb = task & 15;            // batch
        float s = b_mod[blockIdx.x * 32 + tc];
        #pragma unroll
        for (int g = 0; g < MODKG; ++g)
            s += red[(g * 32 + tc) * Bsz + tb];
        mod[tb * MODW + blockIdx.x * 32 + tc] = s;
    }
}

// --------- kernel 2: LN(x) * (1+sc) + sh  (per row), fp16 output ------------
__global__ __launch_bounds__(256) void ln_mod_kernel(
    const float* __restrict__ x, const float* __restrict__ mod,
    int shOff, int scOff, __half* __restrict__ out)
{
    __shared__ float buf[HID];
    __shared__ float red[16];
    int row = blockIdx.x;
    int b = row >> 10;
    int tid = threadIdx.x;
    const float* xr = x + (size_t)row * HID;
    float s = 0.f, s2 = 0.f;
    for (int i = tid; i < 288; i += 256) {
        float4 v = *(const float4*)(xr + i * 4);
        *(float4*)(buf + i * 4) = v;
        s  += v.x + v.y + v.z + v.w;
        s2 += v.x * v.x + v.y * v.y + v.z * v.z + v.w * v.w;
    }
    #pragma unroll
    for (int o = 16; o; o >>= 1) {
        s  += __shfl_xor_sync(0xffffffffu, s,  o);
        s2 += __shfl_xor_sync(0xffffffffu, s2, o);
    }
    if ((tid & 31) == 0) { red[tid >> 5] = s; red[8 + (tid >> 5)] = s2; }
    __syncthreads();
    float S = 0.f, S2 = 0.f;
    #pragma unroll
    for (int w = 0; w < 8; ++w) { S += red[w]; S2 += red[8 + w]; }
    float mean = S * (1.f / HID);
    float var  = S2 * (1.f / HID) - mean * mean;
    float rstd = rsqrtf(var + EPS);
    const float* mrow = mod + b * MODW;
    __half* orow = out + (size_t)row * HID;
    for (int i = tid; i < 288; i += 256) {
        float4 v   = *(const float4*)(buf + i * 4);
        float4 sc4 = *(const float4*)(mrow + scOff + i * 4);
        float4 sh4 = *(const float4*)(mrow + shOff + i * 4);
        float o0 = fmaf((v.x - mean) * rstd, 1.f + sc4.x, sh4.x);
        float o1 = fmaf((v.y - mean) * rstd, 1.f + sc4.y, sh4.y);
        float o2 = fmaf((v.z - mean) * rstd, 1.f + sc4.z, sh4.z);
        float o3 = fmaf((v.w - mean) * rstd, 1.f + sc4.w, sh4.w);
        uint2 pk;
        pk.x = h2u(__floats2half2_rn(o0, o1));
        pk.y = h2u(__floats2half2_rn(o2, o3));
        *(uint2*)(orow + i * 4) = pk;
    }
}

// --------------- kernel 3: per-head LN of q and k (fp16, half2) -------------
__global__ __launch_bounds__(256) void qkln_kernel(
    __half* __restrict__ qkv, const float* __restrict__ g_q,
    const float* __restrict__ g_k)
{
    int warp = blockIdx.x * 8 + (threadIdx.x >> 5);
    int lane = threadIdx.x & 31;
    int h  = warp & 15;
    int qk = (warp >> 4) & 1;
    int bn = warp >> 5;
    __half2* p2 = (__half2*)(qkv + (size_t)bn * (3 * HID) + qk * HID + h * HD);
    float2 va = __half22float2(p2[lane]);
    float2 vb = (lane < 4) ? __half22float2(p2[32 + lane]) : make_float2(0.f, 0.f);
    float s  = va.x + va.y + vb.x + vb.y;
    float s2 = va.x * va.x + va.y * va.y + vb.x * vb.x + vb.y * vb.y;
    #pragma unroll
    for (int o = 16; o; o >>= 1) {
        s  += __shfl_xor_sync(0xffffffffu, s,  o);
        s2 += __shfl_xor_sync(0xffffffffu, s2, o);
    }
    float mean = s * (1.f / HD);
    float var  = s2 * (1.f / HD) - mean * mean;
    float rstd = rsqrtf(var + EPS);
    const float* g = qk ? g_k : g_q;
    float2 ga = *(const float2*)(g + 2 * lane);
    p2[lane] = __floats2half2_rn((va.x - mean) * rstd * ga.x,
                                 (va.y - mean) * rstd * ga.y);
    if (lane < 4) {
        float2 gb = *(const float2*)(g + 64 + 2 * lane);
        p2[32 + lane] = __floats2half2_rn((vb.x - mean) * rstd * gb.x,
                                          (vb.y - mean) * rstd * gb.y);
    }
}

// ------- kernel 4: flash attention (cp.async K/V pipeline + trans ldsm) -----
#define AQ 128
#define AK 64
#define QH 88     // halves stride for qs/ks/vs rows
#define KVBUF_H (AK * QH)                  // halves per K or V buffer
#define ATTN_SMEM ((AQ * QH + 4 * KVBUF_H) * 2)   // 67584 bytes

__global__ __launch_bounds__(256) void attn_kernel(
    const __half* __restrict__ qkv, __half* __restrict__ o)
{
    extern __shared__ __half smh[];
    __half* qs = smh;                      // [128][88]
    __half* kv = qs + AQ * QH;             // [2][ks 64x88, vs 64x88]

    int tid = threadIdx.x;
    int lane = tid & 31;
    int warp = tid >> 5;
    int grp = lane >> 2;
    int t4 = lane & 3;
    int m0 = warp * 16;
    int lsel = lane & 15;
    int ksel = (lane >> 4) * 8;

    int q0 = blockIdx.x * AQ;
    int h = blockIdx.y, b = blockIdx.z;
    const size_t baseBN = (size_t)b * SEQ * (3 * HID);
    const int hoff = h * HD;
    const float scale = 0.11785113019775793f;

    uint32_t qsA = smem_u32(qs);
    uint32_t kvA = smem_u32(kv);
    // trans-ldmatrix per-lane relative offsets (into a V buffer, halves)
    int vrow4 = ((lane >> 3) & 1) * 8 + (lane & 7);
    int vcol4 = (lane >> 4) * 8;
    uint32_t vrel4 = (uint32_t)(vrow4 * QH + vcol4) * 2;
    int vrow2 = (((lane & 15) >> 3) & 1) * 8 + (lane & 7);
    uint32_t vrel2 = (uint32_t)(vrow2 * QH + 64) * 2;

    // load Q tile (9 x 16B chunks per row)
    for (int idx = tid; idx < AQ * 9; idx += 256) {
        int r = idx / 9, c = (idx - r * 9) * 8;
        *(float4*)(qs + r * QH + c) =
            *(const float4*)(qkv + baseBN + (size_t)(q0 + r) * (3 * HID) + hoff + c);
    }
    // zero pads: qs cols 72..79, and ks cols 72..79 in BOTH buffers
    for (int idx = tid; idx < AQ + 2 * AK; idx += 256) {
        __half* base;
        if (idx < AQ)            base = qs + idx * QH;
        else if (idx < AQ + AK)  base = kv + (idx - AQ) * QH;
        else                     base = kv + 2 * KVBUF_H + (idx - AQ - AK) * QH;
        *(float4*)(base + 72) = make_float4(0.f, 0.f, 0.f, 0.f);
    }

    // K/V tile loader: 1152 x 16B chunks (K first 576, V next 576)
    auto load_kv = [&](int kt, int bi) {
        uint32_t kD = kvA + (uint32_t)bi * (2 * KVBUF_H * 2);
        uint32_t vD = kD + KVBUF_H * 2;
        const __half* base = qkv + baseBN + (size_t)(kt * AK) * (3 * HID) + hoff;
        for (int idx = tid; idx < 1152; idx += 256) {
            int isv = idx >= 576;
            int j = isv ? idx - 576 : idx;
            int r = j / 9, c = (j - r * 9) * 8;
            const __half* src = base + (size_t)r * (3 * HID) + (isv ? 2 * HID : HID) + c;
            cp16s((isv ? vD : kD) + (uint32_t)(r * QH + c) * 2, src);
        }
    };

    float accO[9][4];
    #pragma unroll
    for (int di = 0; di < 9; ++di)
        #pragma unroll
        for (int e = 0; e < 4; ++e) accO[di][e] = 0.f;
    float mi0 = -INFINITY, mi1 = -INFINITY;
    float li0 = 0.f, li1 = 0.f;

    load_kv(0, 0);
    cp_commit();

    for (int kt = 0; kt < SEQ / AK; ++kt) {
        cp_wait<0>();
        __syncthreads();

        if (kt + 1 < SEQ / AK) {
            load_kv(kt + 1, (kt + 1) & 1);
        }
        cp_commit();

        uint32_t ksCur = kvA + (uint32_t)(kt & 1) * (2 * KVBUF_H * 2);
        uint32_t vsCur = ksCur + KVBUF_H * 2;

        // ---- S = Q K^T : ldmatrix-fed, 5 k16 steps ----
        float sacc[8][4];
        #pragma unroll
        for (int ni = 0; ni < 8; ++ni)
            #pragma unroll
            for (int e = 0; e < 4; ++e) sacc[ni][e] = 0.f;
        #pragma unroll
        for (int ksb = 0; ksb < 5; ++ksb) {
            int k16 = ksb * 16;
            unsigned a0, a1, a2, a3;
            ldsm_x4(a0, a1, a2, a3, qsA + ((m0 + lsel) * QH + k16 + ksel) * 2);
            unsigned bf[8][2];
            #pragma unroll
            for (int p = 0; p < 4; ++p)
                ldsm_x4(bf[2 * p][0], bf[2 * p + 1][0], bf[2 * p][1], bf[2 * p + 1][1],
                        ksCur + ((p * 16 + lsel) * QH + k16 + ksel) * 2);
            #pragma unroll
            for (int ni = 0; ni < 8; ++ni)
                mma_f16(sacc[ni][0], sacc[ni][1], sacc[ni][2], sacc[ni][3],
                        a0, a1, a2, a3, bf[ni][0], bf[ni][1]);
        }

        // ---- online softmax; P fragments in registers ----
        float rmax0 = -INFINITY, rmax1 = -INFINITY;
        #pragma unroll
        for (int ni = 0; ni < 8; ++ni) {
            sacc[ni][0] *= scale; sacc[ni][1] *= scale;
            sacc[ni][2] *= scale; sacc[ni][3] *= scale;
            rmax0 = fmaxf(rmax0, fmaxf(sacc[ni][0], sacc[ni][1]));
            rmax1 = fmaxf(rmax1, fmaxf(sacc[ni][2], sacc[ni][3]));
        }
        #pragma unroll
        for (int off = 1; off < 4; off <<= 1) {
            rmax0 = fmaxf(rmax0, __shfl_xor_sync(0xffffffffu, rmax0, off));
            rmax1 = fmaxf(rmax1, __shfl_xor_sync(0xffffffffu, rmax1, off));
        }
        float newm0 = fmaxf(mi0, rmax0);
        float newm1 = fmaxf(mi1, rmax1);
        float alpha0 = __expf(mi0 - newm0);
        float alpha1 = __expf(mi1 - newm1);
        mi0 = newm0; mi1 = newm1;
        float rsum0 = 0.f, rsum1 = 0.f;
        unsigned ph0[8], ph1[8];
        #pragma unroll
        for (int ni = 0; ni < 8; ++ni) {
            float p0 = __expf(sacc[ni][0] - newm0);
            float p1 = __expf(sacc[ni][1] - newm0);
            float p2 = __expf(sacc[ni][2] - newm1);
            float p3 = __expf(sacc[ni][3] - newm1);
            rsum0 += p0 + p1; rsum1 += p2 + p3;
            ph0[ni] = h2u(__floats2half2_rn(p0, p1));
            ph1[ni] = h2u(__floats2half2_rn(p2, p3));
        }
        #pragma unroll
        for (int off = 1; off < 4; off <<= 1) {
            rsum0 += __shfl_xor_sync(0xffffffffu, rsum0, off);
            rsum1 += __shfl_xor_sync(0xffffffffu, rsum1, off);
        }
        li0 = li0 * alpha0 + rsum0;
        li1 = li1 * alpha1 + rsum1;
        #pragma unroll
        for (int di = 0; di < 9; ++di) {
            accO[di][0] *= alpha0; accO[di][1] *= alpha0;
            accO[di][2] *= alpha1; accO[di][3] *= alpha1;
        }

        // ---- O += P V : V row-major, trans-ldmatrix B fragments ----
        #pragma unroll
        for (int kb = 0; kb < 4; ++kb) {
            unsigned a0 = ph0[2 * kb],     a2 = ph0[2 * kb + 1];
            unsigned a1 = ph1[2 * kb],     a3 = ph1[2 * kb + 1];
            uint32_t vkb = vsCur + (uint32_t)(kb * 16 * QH) * 2;
            unsigned vf[9][2];
            #pragma unroll
            for (int p = 0; p < 4; ++p)
                ldsm_x4t(vf[2 * p][0], vf[2 * p][1], vf[2 * p + 1][0], vf[2 * p + 1][1],
                         vkb + vrel4 + (uint32_t)(p * 16) * 2);
            ldsm_x2t(vf[8][0], vf[8][1], vkb + vrel2);
            #pragma unroll
            for (int di = 0; di < 9; ++di)
                mma_f16(accO[di][0], accO[di][1], accO[di][2], accO[di][3],
                        a0, a1, a2, a3, vf[di][0], vf[di][1]);
        }
    }

    float inv0 = 1.f / li0, inv1 = 1.f / li1;
    int row0 = q0 + m0 + grp;
    size_t b0a = ((size_t)b * SEQ + row0) * HID + hoff;
    size_t b1a = ((size_t)b * SEQ + row0 + 8) * HID + hoff;
    #pragma unroll
    for (int di = 0; di < 9; ++di) {
        int d = di * 8 + t4 * 2;
        *(__half2*)(o + b0a + d) = __floats2half2_rn(accO[di][0] * inv0, accO[di][1] * inv0);
        *(__half2*)(o + b1a + d) = __floats2half2_rn(accO[di][2] * inv1, accO[di][3] * inv1);
    }
}

// --------------- kernel 5: FP16 GEMM 128x128x64, 3 stages, ldmatrix ---------
#define TBK 64
#define ASTRH 72                          // halves per smem row (64 + 8 pad)
#define TILE_H_BYTES (128 * ASTRH * 2)    // 18432
#define NSTAGE 3
#define GEMM_SMEM (NSTAGE * 2 * TILE_H_BYTES)   // 110592

template <int EPI, typename OutT>
__global__ __launch_bounds__(256) void hgemm_kernel(
    const __half* __restrict__ A, const __half* __restrict__ BT,
    const float* __restrict__ bias, const float* __restrict__ res,
    const float* __restrict__ gate, OutT* __restrict__ C,
    int M, int N, int K)
{
    extern __shared__ char smc[];
    uint32_t sbase = smem_u32(smc);

    int tid = threadIdx.x;
    int lane = tid & 31;
    int warp = tid >> 5;
    int m0 = (warp & 1) * 64;
    int n0 = (warp >> 1) * 32;
    int grp = lane >> 2;
    int t4 = lane & 3;
    int lsel = lane & 15;
    int ksel = (lane >> 4) * 8;

    int cRow = blockIdx.y, cCol = blockIdx.x;
    const __half* Ab = A + (size_t)cRow * 128 * K;
    const __half* Bb = BT + (size_t)cCol * 128 * K;

    float acc[4][4][4];
    #pragma unroll
    for (int mi = 0; mi < 4; ++mi)
        #pragma unroll
        for (int ni = 0; ni < 4; ++ni)
            #pragma unroll
            for (int e = 0; e < 4; ++e) acc[mi][ni][e] = 0.f;

    int KT = K / TBK;    // 18 or 72

    auto load_stage = [&](int kt, int s) {
        uint32_t aBase = sbase + s * TILE_H_BYTES;
        uint32_t bBase = sbase + (NSTAGE + s) * TILE_H_BYTES;
        const __half* Asrc = Ab + kt * TBK;
        const __half* Bsrc = Bb + kt * TBK;
        #pragma unroll
        for (int j = 0; j < 4; ++j) {
            int idx = tid + j * 256;
            int r = idx >> 3, c = idx & 7;
            cp16s(aBase + r * (ASTRH * 2) + c * 16, Asrc + (size_t)r * K + c * 8);
            cp16s(bBase + r * (ASTRH * 2) + c * 16, Bsrc + (size_t)r * K + c * 8);
        }
    };

    #pragma unroll
    for (int s = 0; s < NSTAGE - 1; ++s) {
        load_stage(s, s);
        cp_commit();
    }

    for (int kt = 0; kt < KT; ++kt) {
        cp_wait<NSTAGE - 2>();
        __syncthreads();

        int pf = kt + NSTAGE - 1;
        if (pf < KT) load_stage(pf, pf % NSTAGE);
        cp_commit();

        int st = kt % NSTAGE;
        uint32_t aBase = sbase + st * TILE_H_BYTES;
        uint32_t bBase = sbase + (NSTAGE + st) * TILE_H_BYTES;
        #pragma unroll
        for (int ks = 0; ks < 4; ++ks) {
            int k16 = ks * 16;
            unsigned af[4][4], bf[4][2];
            #pragma unroll
            for (int mi = 0; mi < 4; ++mi)
                ldsm_x4(af[mi][0], af[mi][1], af[mi][2], af[mi][3],
                        aBase + ((m0 + mi * 16 + lsel) * ASTRH + k16 + ksel) * 2);
            ldsm_x4(bf[0][0], bf[1][0], bf[0][1], bf[1][1],
                    bBase + ((n0 + lsel) * ASTRH + k16 + ksel) * 2);
            ldsm_x4(bf[2][0], bf[3][0], bf[2][1], bf[3][1],
                    bBase + ((n0 + 16 + lsel) * ASTRH + k16 + ksel) * 2);
            #pragma unroll
            for (int mi = 0; mi < 4; ++mi)
                #pragma unroll
                for (int ni = 0; ni < 4; ++ni)
                    mma_f16(acc[mi][ni][0], acc[mi][ni][1], acc[mi][ni][2], acc[mi][ni][3],
                            af[mi][0], af[mi][1], af[mi][2], af[mi][3],
                            bf[ni][0], bf[ni][1]);
        }
    }

    // ---- epilogue ----
    #pragma unroll
    for (int mi = 0; mi < 4; ++mi) {
        #pragma unroll
        for (int half_ = 0; half_ < 2; ++half_) {
            int row = cRow * 128 + m0 + mi * 16 + grp + half_ * 8;
            int gb = (row >> 10) * MODW;
            #pragma unroll
            for (int ni = 0; ni < 4; ++ni) {
                int col = cCol * 128 + n0 + ni * 8 + t4 * 2;
                float v0 = acc[mi][ni][half_ * 2 + 0] + bias[col];
                float v1 = acc[mi][ni][half_ * 2 + 1] + bias[col + 1];
                if (EPI == 1) {
                    float i0 = 0.7978845608028654f * (v0 + 0.044715f * v0 * v0 * v0);
                    float i1 = 0.7978845608028654f * (v1 + 0.044715f * v1 * v1 * v1);
                    v0 = v0 / (1.f + __expf(-2.f * i0));
                    v1 = v1 / (1.f + __expf(-2.f * i1));
                } else if (EPI == 2) {
                    v0 = fmaf(gate[gb + col],     v0, res[(size_t)row * N + col]);
                    v1 = fmaf(gate[gb + col + 1], v1, res[(size_t)row * N + col + 1]);
                }
                OutT* dst = C + (size_t)row * N + col;
                if (sizeof(OutT) == 2) {
                    *(__half2*)dst = __floats2half2_rn(v0, v1);
                } else {
                    *(float2*)dst = make_float2(v0, v1);
                }
            }
        }
    }
}

// ---------------------------- launcher --------------------------------------
extern "C" void kernel_launch(void* const* d_in, const int* in_sizes, int n_in,
                              void* d_out, int out_size)
{
    const float* x      = (const float*)d_in[0];
    const float* c      = (const float*)d_in[1];
    const float* w_mod  = (const float*)d_in[2];
    const float* b_mod  = (const float*)d_in[3];
    const float* w_qkv  = (const float*)d_in[4];
    const float* b_qkv  = (const float*)d_in[5];
    const float* gq     = (const float*)d_in[6];
    const float* gk     = (const float*)d_in[7];
    const float* w_proj = (const float*)d_in[8];
    const float* b_proj = (const float*)d_in[9];
    const float* w1     = (const float*)d_in[10];
    const float* b1     = (const float*)d_in[11];
    const float* w2     = (const float*)d_in[12];
    const float* b2     = (const float*)d_in[13];
    float* out = (float*)d_out;

    float *p_mod, *p_x1;
    __half *p_xn16, *p_qkv16, *p_o16, *p_h16, *p_wqkvT, *p_wprojT, *p_w1T, *p_w2T;
    cudaGetSymbolAddress((void**)&p_mod, g_mod);
    cudaGetSymbolAddress((void**)&p_xn16, g_xn16);
    cudaGetSymbolAddress((void**)&p_qkv16, g_qkv16);
    cudaGetSymbolAddress((void**)&p_o16, g_o16);
    cudaGetSymbolAddress((void**)&p_x1,  g_x1);
    cudaGetSymbolAddress((void**)&p_h16, g_h16);
    cudaGetSymbolAddress((void**)&p_wqkvT, g_wqkvT16);
    cudaGetSymbolAddress((void**)&p_wprojT, g_wprojT16);
    cudaGetSymbolAddress((void**)&p_w1T, g_w1T16);
    cudaGetSymbolAddress((void**)&p_w2T, g_w2T16);

    cudaFuncSetAttribute(attn_kernel,
                         cudaFuncAttributeMaxDynamicSharedMemorySize, ATTN_SMEM);
    cudaFuncSetAttribute(mod_kernel,
                         cudaFuncAttributeMaxDynamicSharedMemorySize, MOD_SMEM);
    cudaFuncSetAttribute(hgemm_kernel<0, __half>,
                         cudaFuncAttributeMaxDynamicSharedMemorySize, GEMM_SMEM);
    cudaFuncSetAttribute(hgemm_kernel<1, __half>,
                         cudaFuncAttributeMaxDynamicSharedMemorySize, GEMM_SMEM);
    cudaFuncSetAttribute(hgemm_kernel<2, float>,
                         cudaFuncAttributeMaxDynamicSharedMemorySize, GEMM_SMEM);

    // 0. convert+transpose weights to fp16 [N][K]
    wcvt_kernel<<<dim3(3 * HID / 32, HID / 32), 256>>>(w_qkv, p_wqkvT, HID, 3 * HID);
    wcvt_kernel<<<dim3(HID / 32, HID / 32), 256>>>(w_proj, p_wprojT, HID, HID);
    wcvt_kernel<<<dim3(MLPD / 32, HID / 32), 256>>>(w1, p_w1T, HID, MLPD);
    wcvt_kernel<<<dim3(HID / 32, MLPD / 32), 256>>>(w2, p_w2T, MLPD, HID);

    // 1. adaLN modulation (batch-reuse: w_mod read once)
    mod_kernel<<<MODW / 32, 256, MOD_SMEM>>>(c, w_mod, b_mod, p_mod);
    // 2. LN + modulate (MSA) -> fp16
    ln_mod_kernel<<<ROWS, 256>>>(x, p_mod, 0, HID, p_xn16);
    // 3. QKV GEMM -> fp16 qkv
    hgemm_kernel<0, __half><<<dim3(3 * HID / 128, ROWS / 128), 256, GEMM_SMEM>>>(
        p_xn16, p_wqkvT, b_qkv, nullptr, nullptr, p_qkv16, ROWS, 3 * HID, HID);
    // 4. per-head LN of q,k
    qkln_kernel<<<ROWS * 32 / 8, 256>>>(p_qkv16, gq, gk);
    // 5. attention -> fp16 o
    attn_kernel<<<dim3(SEQ / AQ, NH, Bsz), 256, ATTN_SMEM>>>(p_qkv16, p_o16);
    // 6. proj + gated residual -> fp32 x1
    hgemm_kernel<2, float><<<dim3(HID / 128, ROWS / 128), 256, GEMM_SMEM>>>(
        p_o16, p_wprojT, b_proj, x, p_mod + 2 * HID, p_x1, ROWS, HID, HID);
    // 7. LN + modulate (MLP) -> fp16
    ln_mod_kernel<<<ROWS, 256>>>(p_x1, p_mod, 3 * HID, 4 * HID, p_xn16);
    // 8. MLP up + gelu -> fp16 h
    hgemm_kernel<1, __half><<<dim3(MLPD / 128, ROWS / 128), 256, GEMM_SMEM>>>(
        p_xn16, p_w1T, b1, nullptr, nullptr, p_h16, ROWS, MLPD, HID);
    // 9. MLP down + gated residual -> fp32 out
    hgemm_kernel<2, float><<<dim3(HID / 128, ROWS / 128), 256, GEMM_SMEM>>>(
        p_h16, p_w2T, b2, p_x1, p_mod + 5 * HID, out, ROWS, HID, MLPD);
}

// round 13
// speedup vs baseline: 1.1623x; 1.0013x over previous
#include <cuda_runtime.h>
#include <cuda_fp16.h>
#include <math.h>
#include <stdint.h>

// Problem constants
#define Bsz 16
#define SEQ 1024
#define HID 1152
#define NH 16
#define HD 72
#define MLPD 4608
#define ROWS (Bsz * SEQ)          // 16384
#define MODW (6 * HID)            // 6912
#define EPS 1e-6f

// ---------------- scratch (device globals; allocation-free) ----------------
__device__ float  g_mod[Bsz * MODW];
__device__ __half g_xn16[ROWS * HID];
__device__ __half g_qkv16[ROWS * 3 * HID];
__device__ __half g_o16[ROWS * HID];
__device__ float  g_x1[ROWS * HID];
__device__ __half g_h16[ROWS * MLPD];
// fp16 transposed weights [N][K]
__device__ __half g_wqkvT16[3 * HID * HID];
__device__ __half g_wprojT16[HID * HID];
__device__ __half g_w1T16[HID * MLPD];
__device__ __half g_w2T16[MLPD * HID];

__device__ __forceinline__ void mma_f16(
    float& c0, float& c1, float& c2, float& c3,
    unsigned a0, unsigned a1, unsigned a2, unsigned a3,
    unsigned b0, unsigned b1)
{
    asm volatile(
        "mma.sync.aligned.m16n8k16.row.col.f32.f16.f16.f32 "
        "{%0,%1,%2,%3}, {%4,%5,%6,%7}, {%8,%9}, {%0,%1,%2,%3};"
        : "+f"(c0), "+f"(c1), "+f"(c2), "+f"(c3)
        : "r"(a0), "r"(a1), "r"(a2), "r"(a3), "r"(b0), "r"(b1));
}

__device__ __forceinline__ void ldsm_x4(
    unsigned& r0, unsigned& r1, unsigned& r2, unsigned& r3, uint32_t addr)
{
    asm volatile("ldmatrix.sync.aligned.m8n8.x4.shared.b16 {%0,%1,%2,%3}, [%4];"
                 : "=r"(r0), "=r"(r1), "=r"(r2), "=r"(r3) : "r"(addr));
}

__device__ __forceinline__ void ldsm_x4t(
    unsigned& r0, unsigned& r1, unsigned& r2, unsigned& r3, uint32_t addr)
{
    asm volatile("ldmatrix.sync.aligned.m8n8.x4.trans.shared.b16 {%0,%1,%2,%3}, [%4];"
                 : "=r"(r0), "=r"(r1), "=r"(r2), "=r"(r3) : "r"(addr));
}

__device__ __forceinline__ void ldsm_x2t(
    unsigned& r0, unsigned& r1, uint32_t addr)
{
    asm volatile("ldmatrix.sync.aligned.m8n8.x2.trans.shared.b16 {%0,%1}, [%2];"
                 : "=r"(r0), "=r"(r1) : "r"(addr));
}

__device__ __forceinline__ void cp16s(uint32_t dst, const void* src) {
    asm volatile("cp.async.cg.shared.global [%0], [%1], 16;" :: "r"(dst), "l"(src));
}
__device__ __forceinline__ void cp_commit() {
    asm volatile("cp.async.commit_group;");
}
template <int N> __device__ __forceinline__ void cp_wait() {
    asm volatile("cp.async.wait_group %0;" :: "n"(N));
}
__device__ __forceinline__ uint32_t smem_u32(const void* p) {
    uint32_t a;
    asm("{ .reg .u64 t; cvta.to.shared.u64 t, %1; cvt.u32.u64 %0, t; }"
        : "=r"(a) : "l"(p));
    return a;
}
__device__ __forceinline__ unsigned h2u(__half2 h) {
    return *reinterpret_cast<unsigned*>(&h);
}

// --- kernel 0: ALL weight converts+transposes fp32 [K][N] -> fp16 [N][K] ----
// One launch; blockIdx.x range-dispatches across the 4 matrices.
// Tiles (32x32): wqkv 108x36=3888, wproj 36x36=1296, w1 144x36=5184,
// w2 36x144=5184. Total 15552.
#define WCVT_TILES 15552
__global__ __launch_bounds__(256) void wcvt_all_kernel(
    const float* __restrict__ wq, const float* __restrict__ wp,
    const float* __restrict__ w1p, const float* __restrict__ w2p,
    __half* __restrict__ oq, __half* __restrict__ op,
    __half* __restrict__ o1, __half* __restrict__ o2)
{
    __shared__ float t[32][33];
    int bid = blockIdx.x;
    const float* w; __half* wt; int K, N, tt;
    if (bid < 3888)       { w = wq;  wt = oq; K = HID;  N = 3 * HID; tt = bid; }
    else if (bid < 5184)  { w = wp;  wt = op; K = HID;  N = HID;     tt = bid - 3888; }
    else if (bid < 10368) { w = w1p; wt = o1; K = HID;  N = MLPD;    tt = bid - 5184; }
    else                  { w = w2p; wt = o2; K = MLPD; N = HID;     tt = bid - 10368; }
    int nT = N >> 5;
    int n0 = (tt % nT) * 32, k0 = (tt / nT) * 32;
    int tx = threadIdx.x & 31, ty = threadIdx.x >> 5;
    #pragma unroll
    for (int j = 0; j < 32; j += 8)
        t[ty + j][tx] = w[(size_t)(k0 + ty + j) * N + n0 + tx];
    __syncthreads();
    #pragma unroll
    for (int j = 0; j < 32; j += 8)
        wt[(size_t)(n0 + ty + j) * K + k0 + tx] = __float2half(t[tx][ty + j]);
}

// ------- kernel 1: mod = swish(c) @ w_mod + b_mod (batch-reuse) -------------
#define MODKG 8
#define MODKL (HID / MODKG)      // 144
#define MOD_SMEM ((Bsz * HID + MODKG * 32 * Bsz) * 4)   // 90112 bytes
__global__ __launch_bounds__(256) void mod_kernel(
    const float* __restrict__ c, const float* __restrict__ w_mod,
    const float* __restrict__ b_mod, float* __restrict__ mod)
{
    extern __shared__ float sm[];
    float* sct = sm;                   // [1152][16] swish(c) transposed
    float* red = sm + Bsz * HID;       // [8][32][16] partials
    int tid = threadIdx.x;
    for (int i = tid; i < Bsz * HID; i += 256) {
        int b = i / HID, k = i - b * HID;
        float v = c[i];
        sct[k * Bsz + b] = v / (1.f + expf(-v));
    }
    __syncthreads();
    int cl = tid & 31;
    int kg = tid >> 5;                 // 0..7
    int col = blockIdx.x * 32 + cl;
    float acc[Bsz];
    #pragma unroll
    for (int b = 0; b < Bsz; ++b) acc[b] = 0.f;
    int k0 = kg * MODKL;
    for (int k = k0; k < k0 + MODKL; ++k) {
        float w = w_mod[(size_t)k * MODW + col];
        const float4* s4 = (const float4*)(sct + k * Bsz);
        #pragma unroll
        for (int b4 = 0; b4 < 4; ++b4) {
            float4 s = s4[b4];
            acc[4 * b4 + 0] = fmaf(s.x, w, acc[4 * b4 + 0]);
            acc[4 * b4 + 1] = fmaf(s.y, w, acc[4 * b4 + 1]);
            acc[4 * b4 + 2] = fmaf(s.z, w, acc[4 * b4 + 2]);
            acc[4 * b4 + 3] = fmaf(s.w, w, acc[4 * b4 + 3]);
        }
    }
    #pragma unroll
    for (int b = 0; b < Bsz; ++b)
        red[(kg * 32 + cl) * Bsz + b] = acc[b];
    __syncthreads();
    #pragma unroll
    for (int t = 0; t < 2; ++t) {
        int task = tid + t * 256;
        int tc = task >> 4;
        int tb = task & 15;
        float s = b_mod[blockIdx.x * 32 + tc];
        #pragma unroll
        for (int g = 0; g < MODKG; ++g)
            s += red[(g * 32 + tc) * Bsz + tb];
        mod[tb * MODW + blockIdx.x * 32 + tc] = s;
    }
}

// --------- kernel 2: LN(x) * (1+sc) + sh  (per row), fp16 output ------------
__global__ __launch_bounds__(256) void ln_mod_kernel(
    const float* __restrict__ x, const float* __restrict__ mod,
    int shOff, int scOff, __half* __restrict__ out)
{
    __shared__ float buf[HID];
    __shared__ float red[16];
    int row = blockIdx.x;
    int b = row >> 10;
    int tid = threadIdx.x;
    const float* xr = x + (size_t)row * HID;
    float s = 0.f, s2 = 0.f;
    for (int i = tid; i < 288; i += 256) {
        float4 v = *(const float4*)(xr + i * 4);
        *(float4*)(buf + i * 4) = v;
        s  += v.x + v.y + v.z + v.w;
        s2 += v.x * v.x + v.y * v.y + v.z * v.z + v.w * v.w;
    }
    #pragma unroll
    for (int o = 16; o; o >>= 1) {
        s  += __shfl_xor_sync(0xffffffffu, s,  o);
        s2 += __shfl_xor_sync(0xffffffffu, s2, o);
    }
    if ((tid & 31) == 0) { red[tid >> 5] = s; red[8 + (tid >> 5)] = s2; }
    __syncthreads();
    float S = 0.f, S2 = 0.f;
    #pragma unroll
    for (int w = 0; w < 8; ++w) { S += red[w]; S2 += red[8 + w]; }
    float mean = S * (1.f / HID);
    float var  = S2 * (1.f / HID) - mean * mean;
    float rstd = rsqrtf(var + EPS);
    const float* mrow = mod + b * MODW;
    __half* orow = out + (size_t)row * HID;
    for (int i = tid; i < 288; i += 256) {
        float4 v   = *(const float4*)(buf + i * 4);
        float4 sc4 = *(const float4*)(mrow + scOff + i * 4);
        float4 sh4 = *(const float4*)(mrow + shOff + i * 4);
        float o0 = fmaf((v.x - mean) * rstd, 1.f + sc4.x, sh4.x);
        float o1 = fmaf((v.y - mean) * rstd, 1.f + sc4.y, sh4.y);
        float o2 = fmaf((v.z - mean) * rstd, 1.f + sc4.z, sh4.z);
        float o3 = fmaf((v.w - mean) * rstd, 1.f + sc4.w, sh4.w);
        uint2 pk;
        pk.x = h2u(__floats2half2_rn(o0, o1));
        pk.y = h2u(__floats2half2_rn(o2, o3));
        *(uint2*)(orow + i * 4) = pk;
    }
}

// --------------- kernel 3: per-head LN of q and k (fp16, half2) -------------
__global__ __launch_bounds__(256) void qkln_kernel(
    __half* __restrict__ qkv, const float* __restrict__ g_q,
    const float* __restrict__ g_k)
{
    int warp = blockIdx.x * 8 + (threadIdx.x >> 5);
    int lane = threadIdx.x & 31;
    int h  = warp & 15;
    int qk = (warp >> 4) & 1;
    int bn = warp >> 5;
    __half2* p2 = (__half2*)(qkv + (size_t)bn * (3 * HID) + qk * HID + h * HD);
    float2 va = __half22float2(p2[lane]);
    float2 vb = (lane < 4) ? __half22float2(p2[32 + lane]) : make_float2(0.f, 0.f);
    float s  = va.x + va.y + vb.x + vb.y;
    float s2 = va.x * va.x + va.y * va.y + vb.x * vb.x + vb.y * vb.y;
    #pragma unroll
    for (int o = 16; o; o >>= 1) {
        s  += __shfl_xor_sync(0xffffffffu, s,  o);
        s2 += __shfl_xor_sync(0xffffffffu, s2, o);
    }
    float mean = s * (1.f / HD);
    float var  = s2 * (1.f / HD) - mean * mean;
    float rstd = rsqrtf(var + EPS);
    const float* g = qk ? g_k : g_q;
    float2 ga = *(const float2*)(g + 2 * lane);
    p2[lane] = __floats2half2_rn((va.x - mean) * rstd * ga.x,
                                 (va.y - mean) * rstd * ga.y);
    if (lane < 4) {
        float2 gb = *(const float2*)(g + 64 + 2 * lane);
        p2[32 + lane] = __floats2half2_rn((vb.x - mean) * rstd * gb.x,
                                          (vb.y - mean) * rstd * gb.y);
    }
}

// ------- kernel 4: flash attention (cp.async K/V pipeline + trans ldsm) -----
#define AQ 128
#define AK 64
#define QH 88     // halves stride for qs/ks/vs rows
#define KVBUF_H (AK * QH)                  // halves per K or V buffer
#define ATTN_SMEM ((AQ * QH + 4 * KVBUF_H) * 2)   // 67584 bytes

__global__ __launch_bounds__(256) void attn_kernel(
    const __half* __restrict__ qkv, __half* __restrict__ o)
{
    extern __shared__ __half smh[];
    __half* qs = smh;                      // [128][88]
    __half* kv = qs + AQ * QH;             // [2][ks 64x88, vs 64x88]

    int tid = threadIdx.x;
    int lane = tid & 31;
    int warp = tid >> 5;
    int grp = lane >> 2;
    int t4 = lane & 3;
    int m0 = warp * 16;
    int lsel = lane & 15;
    int ksel = (lane >> 4) * 8;

    int q0 = blockIdx.x * AQ;
    int h = blockIdx.y, b = blockIdx.z;
    const size_t baseBN = (size_t)b * SEQ * (3 * HID);
    const int hoff = h * HD;
    const float scale = 0.11785113019775793f;

    uint32_t qsA = smem_u32(qs);
    uint32_t kvA = smem_u32(kv);
    int vrow4 = ((lane >> 3) & 1) * 8 + (lane & 7);
    int vcol4 = (lane >> 4) * 8;
    uint32_t vrel4 = (uint32_t)(vrow4 * QH + vcol4) * 2;
    int vrow2 = (((lane & 15) >> 3) & 1) * 8 + (lane & 7);
    uint32_t vrel2 = (uint32_t)(vrow2 * QH + 64) * 2;

    for (int idx = tid; idx < AQ * 9; idx += 256) {
        int r = idx / 9, c = (idx - r * 9) * 8;
        *(float4*)(qs + r * QH + c) =
            *(const float4*)(qkv + baseBN + (size_t)(q0 + r) * (3 * HID) + hoff + c);
    }
    for (int idx = tid; idx < AQ + 2 * AK; idx += 256) {
        __half* base;
        if (idx < AQ)            base = qs + idx * QH;
        else if (idx < AQ + AK)  base = kv + (idx - AQ) * QH;
        else                     base = kv + 2 * KVBUF_H + (idx - AQ - AK) * QH;
        *(float4*)(base + 72) = make_float4(0.f, 0.f, 0.f, 0.f);
    }

    auto load_kv = [&](int kt, int bi) {
        uint32_t kD = kvA + (uint32_t)bi * (2 * KVBUF_H * 2);
        uint32_t vD = kD + KVBUF_H * 2;
        const __half* base = qkv + baseBN + (size_t)(kt * AK) * (3 * HID) + hoff;
        for (int idx = tid; idx < 1152; idx += 256) {
            int isv = idx >= 576;
            int j = isv ? idx - 576 : idx;
            int r = j / 9, c = (j - r * 9) * 8;
            const __half* src = base + (size_t)r * (3 * HID) + (isv ? 2 * HID : HID) + c;
            cp16s((isv ? vD : kD) + (uint32_t)(r * QH + c) * 2, src);
        }
    };

    float accO[9][4];
    #pragma unroll
    for (int di = 0; di < 9; ++di)
        #pragma unroll
        for (int e = 0; e < 4; ++e) accO[di][e] = 0.f;
    float mi0 = -INFINITY, mi1 = -INFINITY;
    float li0 = 0.f, li1 = 0.f;

    load_kv(0, 0);
    cp_commit();

    for (int kt = 0; kt < SEQ / AK; ++kt) {
        cp_wait<0>();
        __syncthreads();

        if (kt + 1 < SEQ / AK) {
            load_kv(kt + 1, (kt + 1) & 1);
        }
        cp_commit();

        uint32_t ksCur = kvA + (uint32_t)(kt & 1) * (2 * KVBUF_H * 2);
        uint32_t vsCur = ksCur + KVBUF_H * 2;

        // ---- S = Q K^T ----
        float sacc[8][4];
        #pragma unroll
        for (int ni = 0; ni < 8; ++ni)
            #pragma unroll
            for (int e = 0; e < 4; ++e) sacc[ni][e] = 0.f;
        #pragma unroll
        for (int ksb = 0; ksb < 5; ++ksb) {
            int k16 = ksb * 16;
            unsigned a0, a1, a2, a3;
            ldsm_x4(a0, a1, a2, a3, qsA + ((m0 + lsel) * QH + k16 + ksel) * 2);
            unsigned bf[8][2];
            #pragma unroll
            for (int p = 0; p < 4; ++p)
                ldsm_x4(bf[2 * p][0], bf[2 * p + 1][0], bf[2 * p][1], bf[2 * p + 1][1],
                        ksCur + ((p * 16 + lsel) * QH + k16 + ksel) * 2);
            #pragma unroll
            for (int ni = 0; ni < 8; ++ni)
                mma_f16(sacc[ni][0], sacc[ni][1], sacc[ni][2], sacc[ni][3],
                        a0, a1, a2, a3, bf[ni][0], bf[ni][1]);
        }

        // ---- online softmax ----
        float rmax0 = -INFINITY, rmax1 = -INFINITY;
        #pragma unroll
        for (int ni = 0; ni < 8; ++ni) {
            sacc[ni][0] *= scale; sacc[ni][1] *= scale;
            sacc[ni][2] *= scale; sacc[ni][3] *= scale;
            rmax0 = fmaxf(rmax0, fmaxf(sacc[ni][0], sacc[ni][1]));
            rmax1 = fmaxf(rmax1, fmaxf(sacc[ni][2], sacc[ni][3]));
        }
        #pragma unroll
        for (int off = 1; off < 4; off <<= 1) {
            rmax0 = fmaxf(rmax0, __shfl_xor_sync(0xffffffffu, rmax0, off));
            rmax1 = fmaxf(rmax1, __shfl_xor_sync(0xffffffffu, rmax1, off));
        }
        float newm0 = fmaxf(mi0, rmax0);
        float newm1 = fmaxf(mi1, rmax1);
        float alpha0 = __expf(mi0 - newm0);
        float alpha1 = __expf(mi1 - newm1);
        mi0 = newm0; mi1 = newm1;
        float rsum0 = 0.f, rsum1 = 0.f;
        unsigned ph0[8], ph1[8];
        #pragma unroll
        for (int ni = 0; ni < 8; ++ni) {
            float p0 = __expf(sacc[ni][0] - newm0);
            float p1 = __expf(sacc[ni][1] - newm0);
            float p2 = __expf(sacc[ni][2] - newm1);
            float p3 = __expf(sacc[ni][3] - newm1);
            rsum0 += p0 + p1; rsum1 += p2 + p3;
            ph0[ni] = h2u(__floats2half2_rn(p0, p1));
            ph1[ni] = h2u(__floats2half2_rn(p2, p3));
        }
        #pragma unroll
        for (int off = 1; off < 4; off <<= 1) {
            rsum0 += __shfl_xor_sync(0xffffffffu, rsum0, off);
            rsum1 += __shfl_xor_sync(0xffffffffu, rsum1, off);
        }
        li0 = li0 * alpha0 + rsum0;
        li1 = li1 * alpha1 + rsum1;
        #pragma unroll
        for (int di = 0; di < 9; ++di) {
            accO[di][0] *= alpha0; accO[di][1] *= alpha0;
            accO[di][2] *= alpha1; accO[di][3] *= alpha1;
        }

        // ---- O += P V ----
        #pragma unroll
        for (int kb = 0; kb < 4; ++kb) {
            unsigned a0 = ph0[2 * kb],     a2 = ph0[2 * kb + 1];
            unsigned a1 = ph1[2 * kb],     a3 = ph1[2 * kb + 1];
            uint32_t vkb = vsCur + (uint32_t)(kb * 16 * QH) * 2;
            unsigned vf[9][2];
            #pragma unroll
            for (int p = 0; p < 4; ++p)
                ldsm_x4t(vf[2 * p][0], vf[2 * p][1], vf[2 * p + 1][0], vf[2 * p + 1][1],
                         vkb + vrel4 + (uint32_t)(p * 16) * 2);
            ldsm_x2t(vf[8][0], vf[8][1], vkb + vrel2);
            #pragma unroll
            for (int di = 0; di < 9; ++di)
                mma_f16(accO[di][0], accO[di][1], accO[di][2], accO[di][3],
                        a0, a1, a2, a3, vf[di][0], vf[di][1]);
        }
    }

    float inv0 = 1.f / li0, inv1 = 1.f / li1;
    int row0 = q0 + m0 + grp;
    size_t b0a = ((size_t)b * SEQ + row0) * HID + hoff;
    size_t b1a = ((size_t)b * SEQ + row0 + 8) * HID + hoff;
    #pragma unroll
    for (int di = 0; di < 9; ++di) {
        int d = di * 8 + t4 * 2;
        *(__half2*)(o + b0a + d) = __floats2half2_rn(accO[di][0] * inv0, accO[di][1] * inv0);
        *(__half2*)(o + b1a + d) = __floats2half2_rn(accO[di][2] * inv1, accO[di][3] * inv1);
    }
}

// --------------- kernel 5: FP16 GEMM 128x128x64, 3 stages, ldmatrix ---------
#define TBK 64
#define ASTRH 72                          // halves per smem row (64 + 8 pad)
#define TILE_H_BYTES (128 * ASTRH * 2)    // 18432
#define NSTAGE 3
#define GEMM_SMEM (NSTAGE * 2 * TILE_H_BYTES)   // 110592

template <int EPI, typename OutT>
__global__ __launch_bounds__(256) void hgemm_kernel(
    const __half* __restrict__ A, const __half* __restrict__ BT,
    const float* __restrict__ bias, const float* __restrict__ res,
    const float* __restrict__ gate, OutT* __restrict__ C,
    int M, int N, int K)
{
    extern __shared__ char smc[];
    uint32_t sbase = smem_u32(smc);

    int tid = threadIdx.x;
    int lane = tid & 31;
    int warp = tid >> 5;
    int m0 = (warp & 1) * 64;
    int n0 = (warp >> 1) * 32;
    int grp = lane >> 2;
    int t4 = lane & 3;
    int lsel = lane & 15;
    int ksel = (lane >> 4) * 8;

    int cRow = blockIdx.y, cCol = blockIdx.x;
    const __half* Ab = A + (size_t)cRow * 128 * K;
    const __half* Bb = BT + (size_t)cCol * 128 * K;

    float acc[4][4][4];
    #pragma unroll
    for (int mi = 0; mi < 4; ++mi)
        #pragma unroll
        for (int ni = 0; ni < 4; ++ni)
            #pragma unroll
            for (int e = 0; e < 4; ++e) acc[mi][ni][e] = 0.f;

    int KT = K / TBK;    // 18 or 72

    auto load_stage = [&](int kt, int s) {
        uint32_t aBase = sbase + s * TILE_H_BYTES;
        uint32_t bBase = sbase + (NSTAGE + s) * TILE_H_BYTES;
        const __half* Asrc = Ab + kt * TBK;
        const __half* Bsrc = Bb + kt * TBK;
        #pragma unroll
        for (int j = 0; j < 4; ++j) {
            int idx = tid + j * 256;
            int r = idx >> 3, c = idx & 7;
            cp16s(aBase + r * (ASTRH * 2) + c * 16, Asrc + (size_t)r * K + c * 8);
            cp16s(bBase + r * (ASTRH * 2) + c * 16, Bsrc + (size_t)r * K + c * 8);
        }
    };

    #pragma unroll
    for (int s = 0; s < NSTAGE - 1; ++s) {
        load_stage(s, s);
        cp_commit();
    }

    for (int kt = 0; kt < KT; ++kt) {
        cp_wait<NSTAGE - 2>();
        __syncthreads();

        int pf = kt + NSTAGE - 1;
        if (pf < KT) load_stage(pf, pf % NSTAGE);
        cp_commit();

        int st = kt % NSTAGE;
        uint32_t aBase = sbase + st * TILE_H_BYTES;
        uint32_t bBase = sbase + (NSTAGE + st) * TILE_H_BYTES;
        #pragma unroll
        for (int ks = 0; ks < 4; ++ks) {
            int k16 = ks * 16;
            unsigned af[4][4], bf[4][2];
            #pragma unroll
            for (int mi = 0; mi < 4; ++mi)
                ldsm_x4(af[mi][0], af[mi][1], af[mi][2], af[mi][3],
                        aBase + ((m0 + mi * 16 + lsel) * ASTRH + k16 + ksel) * 2);
            ldsm_x4(bf[0][0], bf[1][0], bf[0][1], bf[1][1],
                    bBase + ((n0 + lsel) * ASTRH + k16 + ksel) * 2);
            ldsm_x4(bf[2][0], bf[3][0], bf[2][1], bf[3][1],
                    bBase + ((n0 + 16 + lsel) * ASTRH + k16 + ksel) * 2);
            #pragma unroll
            for (int mi = 0; mi < 4; ++mi)
                #pragma unroll
                for (int ni = 0; ni < 4; ++ni)
                    mma_f16(acc[mi][ni][0], acc[mi][ni][1], acc[mi][ni][2], acc[mi][ni][3],
                            af[mi][0], af[mi][1], af[mi][2], af[mi][3],
                            bf[ni][0], bf[ni][1]);
        }
    }

    // ---- epilogue ----
    #pragma unroll
    for (int mi = 0; mi < 4; ++mi) {
        #pragma unroll
        for (int half_ = 0; half_ < 2; ++half_) {
            int row = cRow * 128 + m0 + mi * 16 + grp + half_ * 8;
            int gb = (row >> 10) * MODW;
            #pragma unroll
            for (int ni = 0; ni < 4; ++ni) {
                int col = cCol * 128 + n0 + ni * 8 + t4 * 2;
                float v0 = acc[mi][ni][half_ * 2 + 0] + bias[col];
                float v1 = acc[mi][ni][half_ * 2 + 1] + bias[col + 1];
                if (EPI == 1) {
                    float i0 = 0.7978845608028654f * (v0 + 0.044715f * v0 * v0 * v0);
                    float i1 = 0.7978845608028654f * (v1 + 0.044715f * v1 * v1 * v1);
                    v0 = v0 / (1.f + __expf(-2.f * i0));
                    v1 = v1 / (1.f + __expf(-2.f * i1));
                } else if (EPI == 2) {
                    v0 = fmaf(gate[gb + col],     v0, res[(size_t)row * N + col]);
                    v1 = fmaf(gate[gb + col + 1], v1, res[(size_t)row * N + col + 1]);
                }
                OutT* dst = C + (size_t)row * N + col;
                if (sizeof(OutT) == 2) {
                    *(__half2*)dst = __floats2half2_rn(v0, v1);
                } else {
                    *(float2*)dst = make_float2(v0, v1);
                }
            }
        }
    }
}

// ---------------------------- launcher --------------------------------------
extern "C" void kernel_launch(void* const* d_in, const int* in_sizes, int n_in,
                              void* d_out, int out_size)
{
    const float* x      = (const float*)d_in[0];
    const float* c      = (const float*)d_in[1];
    const float* w_mod  = (const float*)d_in[2];
    const float* b_mod  = (const float*)d_in[3];
    const float* w_qkv  = (const float*)d_in[4];
    const float* b_qkv  = (const float*)d_in[5];
    const float* gq     = (const float*)d_in[6];
    const float* gk     = (const float*)d_in[7];
    const float* w_proj = (const float*)d_in[8];
    const float* b_proj = (const float*)d_in[9];
    const float* w1     = (const float*)d_in[10];
    const float* b1     = (const float*)d_in[11];
    const float* w2     = (const float*)d_in[12];
    const float* b2     = (const float*)d_in[13];
    float* out = (float*)d_out;

    float *p_mod, *p_x1;
    __half *p_xn16, *p_qkv16, *p_o16, *p_h16, *p_wqkvT, *p_wprojT, *p_w1T, *p_w2T;
    cudaGetSymbolAddress((void**)&p_mod, g_mod);
    cudaGetSymbolAddress((void**)&p_xn16, g_xn16);
    cudaGetSymbolAddress((void**)&p_qkv16, g_qkv16);
    cudaGetSymbolAddress((void**)&p_o16, g_o16);
    cudaGetSymbolAddress((void**)&p_x1,  g_x1);
    cudaGetSymbolAddress((void**)&p_h16, g_h16);
    cudaGetSymbolAddress((void**)&p_wqkvT, g_wqkvT16);
    cudaGetSymbolAddress((void**)&p_wprojT, g_wprojT16);
    cudaGetSymbolAddress((void**)&p_w1T, g_w1T16);
    cudaGetSymbolAddress((void**)&p_w2T, g_w2T16);

    cudaFuncSetAttribute(attn_kernel,
                         cudaFuncAttributeMaxDynamicSharedMemorySize, ATTN_SMEM);
    cudaFuncSetAttribute(mod_kernel,
                         cudaFuncAttributeMaxDynamicSharedMemorySize, MOD_SMEM);
    cudaFuncSetAttribute(hgemm_kernel<0, __half>,
                         cudaFuncAttributeMaxDynamicSharedMemorySize, GEMM_SMEM);
    cudaFuncSetAttribute(hgemm_kernel<1, __half>,
                         cudaFuncAttributeMaxDynamicSharedMemorySize, GEMM_SMEM);
    cudaFuncSetAttribute(hgemm_kernel<2, float>,
                         cudaFuncAttributeMaxDynamicSharedMemorySize, GEMM_SMEM);

    // 0. convert+transpose ALL weights in one launch
    wcvt_all_kernel<<<WCVT_TILES, 256>>>(w_qkv, w_proj, w1, w2,
                                         p_wqkvT, p_wprojT, p_w1T, p_w2T);

    // 1. adaLN modulation (batch-reuse: w_mod read once)
    mod_kernel<<<MODW / 32, 256, MOD_SMEM>>>(c, w_mod, b_mod, p_mod);
    // 2. LN + modulate (MSA) -> fp16
    ln_mod_kernel<<<ROWS, 256>>>(x, p_mod, 0, HID, p_xn16);
    // 3. QKV GEMM -> fp16 qkv
    hgemm_kernel<0, __half><<<dim3(3 * HID / 128, ROWS / 128), 256, GEMM_SMEM>>>(
        p_xn16, p_wqkvT, b_qkv, nullptr, nullptr, p_qkv16, ROWS, 3 * HID, HID);
    // 4. per-head LN of q,k
    qkln_kernel<<<ROWS * 32 / 8, 256>>>(p_qkv16, gq, gk);
    // 5. attention -> fp16 o
    attn_kernel<<<dim3(SEQ / AQ, NH, Bsz), 256, ATTN_SMEM>>>(p_qkv16, p_o16);
    // 6. proj + gated residual -> fp32 x1
    hgemm_kernel<2, float><<<dim3(HID / 128, ROWS / 128), 256, GEMM_SMEM>>>(
        p_o16, p_wprojT, b_proj, x, p_mod + 2 * HID, p_x1, ROWS, HID, HID);
    // 7. LN + modulate (MLP) -> fp16
    ln_mod_kernel<<<ROWS, 256>>>(p_x1, p_mod, 3 * HID, 4 * HID, p_xn16);
    // 8. MLP up + gelu -> fp16 h
    hgemm_kernel<1, __half><<<dim3(MLPD / 128, ROWS / 128), 256, GEMM_SMEM>>>(
        p_xn16, p_w1T, b1, nullptr, nullptr, p_h16, ROWS, MLPD, HID);
    // 9. MLP down + gated residual -> fp32 out
    hgemm_kernel<2, float><<<dim3(HID / 128, ROWS / 128), 256, GEMM_SMEM>>>(
        p_h16, p_w2T, b2, p_x1, p_mod + 5 * HID, out, ROWS, HID, MLPD);
}

// round 14
// speedup vs baseline: 1.1752x; 1.0111x over previous
#include <cuda_runtime.h>
#include <cuda_fp16.h>
#include <math.h>
#include <stdint.h>

// Problem constants
#define Bsz 16
#define SEQ 1024
#define HID 1152
#define NH 16
#define HD 72
#define MLPD 4608
#define ROWS (Bsz * SEQ)          // 16384
#define MODW (6 * HID)            // 6912
#define EPS 1e-6f

// ---------------- scratch (device globals; allocation-free) ----------------
__device__ float  g_mod[Bsz * MODW];
__device__ __half g_xn16[ROWS * HID];
__device__ __half g_qkv16[ROWS * 3 * HID];
__device__ __half g_o16[ROWS * HID];
__device__ float  g_x1[ROWS * HID];
__device__ __half g_h16[ROWS * MLPD];
// fp16 transposed weights [N][K]
__device__ __half g_wqkvT16[3 * HID * HID];
__device__ __half g_wprojT16[HID * HID];
__device__ __half g_w1T16[HID * MLPD];
__device__ __half g_w2T16[MLPD * HID];

__device__ __forceinline__ void mma_f16(
    float& c0, float& c1, float& c2, float& c3,
    unsigned a0, unsigned a1, unsigned a2, unsigned a3,
    unsigned b0, unsigned b1)
{
    asm volatile(
        "mma.sync.aligned.m16n8k16.row.col.f32.f16.f16.f32 "
        "{%0,%1,%2,%3}, {%4,%5,%6,%7}, {%8,%9}, {%0,%1,%2,%3};"
        : "+f"(c0), "+f"(c1), "+f"(c2), "+f"(c3)
        : "r"(a0), "r"(a1), "r"(a2), "r"(a3), "r"(b0), "r"(b1));
}

__device__ __forceinline__ void ldsm_x4(
    unsigned& r0, unsigned& r1, unsigned& r2, unsigned& r3, uint32_t addr)
{
    asm volatile("ldmatrix.sync.aligned.m8n8.x4.shared.b16 {%0,%1,%2,%3}, [%4];"
                 : "=r"(r0), "=r"(r1), "=r"(r2), "=r"(r3) : "r"(addr));
}

__device__ __forceinline__ void ldsm_x4t(
    unsigned& r0, unsigned& r1, unsigned& r2, unsigned& r3, uint32_t addr)
{
    asm volatile("ldmatrix.sync.aligned.m8n8.x4.trans.shared.b16 {%0,%1,%2,%3}, [%4];"
                 : "=r"(r0), "=r"(r1), "=r"(r2), "=r"(r3) : "r"(addr));
}

__device__ __forceinline__ void ldsm_x2t(
    unsigned& r0, unsigned& r1, uint32_t addr)
{
    asm volatile("ldmatrix.sync.aligned.m8n8.x2.trans.shared.b16 {%0,%1}, [%2];"
                 : "=r"(r0), "=r"(r1) : "r"(addr));
}

__device__ __forceinline__ void cp16s(uint32_t dst, const void* src) {
    asm volatile("cp.async.cg.shared.global [%0], [%1], 16;" :: "r"(dst), "l"(src));
}
__device__ __forceinline__ void cp_commit() {
    asm volatile("cp.async.commit_group;");
}
template <int N> __device__ __forceinline__ void cp_wait() {
    asm volatile("cp.async.wait_group %0;" :: "n"(N));
}
__device__ __forceinline__ uint32_t smem_u32(const void* p) {
    uint32_t a;
    asm("{ .reg .u64 t; cvta.to.shared.u64 t, %1; cvt.u32.u64 %0, t; }"
        : "=r"(a) : "l"(p));
    return a;
}
__device__ __forceinline__ unsigned h2u(__half2 h) {
    return *reinterpret_cast<unsigned*>(&h);
}

// --- kernel 0: ALL weight converts+transposes fp32 [K][N] -> fp16 [N][K] ----
#define WCVT_TILES 15552
__global__ __launch_bounds__(256) void wcvt_all_kernel(
    const float* __restrict__ wq, const float* __restrict__ wp,
    const float* __restrict__ w1p, const float* __restrict__ w2p,
    __half* __restrict__ oq, __half* __restrict__ op,
    __half* __restrict__ o1, __half* __restrict__ o2)
{
    __shared__ float t[32][33];
    int bid = blockIdx.x;
    const float* w; __half* wt; int K, N, tt;
    if (bid < 3888)       { w = wq;  wt = oq; K = HID;  N = 3 * HID; tt = bid; }
    else if (bid < 5184)  { w = wp;  wt = op; K = HID;  N = HID;     tt = bid - 3888; }
    else if (bid < 10368) { w = w1p; wt = o1; K = HID;  N = MLPD;    tt = bid - 5184; }
    else                  { w = w2p; wt = o2; K = MLPD; N = HID;     tt = bid - 10368; }
    int nT = N >> 5;
    int n0 = (tt % nT) * 32, k0 = (tt / nT) * 32;
    int tx = threadIdx.x & 31, ty = threadIdx.x >> 5;
    #pragma unroll
    for (int j = 0; j < 32; j += 8)
        t[ty + j][tx] = w[(size_t)(k0 + ty + j) * N + n0 + tx];
    __syncthreads();
    #pragma unroll
    for (int j = 0; j < 32; j += 8)
        wt[(size_t)(n0 + ty + j) * K + k0 + tx] = __float2half(t[tx][ty + j]);
}

// ------- kernel 1: mod = swish(c) @ w_mod + b_mod (batch-reuse) -------------
#define MODKG 8
#define MODKL (HID / MODKG)      // 144
#define MOD_SMEM ((Bsz * HID + MODKG * 32 * Bsz) * 4)   // 90112 bytes
__global__ __launch_bounds__(256) void mod_kernel(
    const float* __restrict__ c, const float* __restrict__ w_mod,
    const float* __restrict__ b_mod, float* __restrict__ mod)
{
    extern __shared__ float sm[];
    float* sct = sm;                   // [1152][16] swish(c) transposed
    float* red = sm + Bsz * HID;       // [8][32][16] partials
    int tid = threadIdx.x;
    for (int i = tid; i < Bsz * HID; i += 256) {
        int b = i / HID, k = i - b * HID;
        float v = c[i];
        sct[k * Bsz + b] = v / (1.f + expf(-v));
    }
    __syncthreads();
    int cl = tid & 31;
    int kg = tid >> 5;                 // 0..7
    int col = blockIdx.x * 32 + cl;
    float acc[Bsz];
    #pragma unroll
    for (int b = 0; b < Bsz; ++b) acc[b] = 0.f;
    int k0 = kg * MODKL;
    for (int k = k0; k < k0 + MODKL; ++k) {
        float w = w_mod[(size_t)k * MODW + col];
        const float4* s4 = (const float4*)(sct + k * Bsz);
        #pragma unroll
        for (int b4 = 0; b4 < 4; ++b4) {
            float4 s = s4[b4];
            acc[4 * b4 + 0] = fmaf(s.x, w, acc[4 * b4 + 0]);
            acc[4 * b4 + 1] = fmaf(s.y, w, acc[4 * b4 + 1]);
            acc[4 * b4 + 2] = fmaf(s.z, w, acc[4 * b4 + 2]);
            acc[4 * b4 + 3] = fmaf(s.w, w, acc[4 * b4 + 3]);
        }
    }
    #pragma unroll
    for (int b = 0; b < Bsz; ++b)
        red[(kg * 32 + cl) * Bsz + b] = acc[b];
    __syncthreads();
    #pragma unroll
    for (int t = 0; t < 2; ++t) {
        int task = tid + t * 256;
        int tc = task >> 4;
        int tb = task & 15;
        float s = b_mod[blockIdx.x * 32 + tc];
        #pragma unroll
        for (int g = 0; g < MODKG; ++g)
            s += red[(g * 32 + tc) * Bsz + tb];
        mod[tb * MODW + blockIdx.x * 32 + tc] = s;
    }
}

// --------- kernel 2: LN(x) * (1+sc) + sh  (per row), fp16 output ------------
__global__ __launch_bounds__(256) void ln_mod_kernel(
    const float* __restrict__ x, const float* __restrict__ mod,
    int shOff, int scOff, __half* __restrict__ out)
{
    __shared__ float buf[HID];
    __shared__ float red[16];
    int row = blockIdx.x;
    int b = row >> 10;
    int tid = threadIdx.x;
    const float* xr = x + (size_t)row * HID;
    float s = 0.f, s2 = 0.f;
    for (int i = tid; i < 288; i += 256) {
        float4 v = *(const float4*)(xr + i * 4);
        *(float4*)(buf + i * 4) = v;
        s  += v.x + v.y + v.z + v.w;
        s2 += v.x * v.x + v.y * v.y + v.z * v.z + v.w * v.w;
    }
    #pragma unroll
    for (int o = 16; o; o >>= 1) {
        s  += __shfl_xor_sync(0xffffffffu, s,  o);
        s2 += __shfl_xor_sync(0xffffffffu, s2, o);
    }
    if ((tid & 31) == 0) { red[tid >> 5] = s; red[8 + (tid >> 5)] = s2; }
    __syncthreads();
    float S = 0.f, S2 = 0.f;
    #pragma unroll
    for (int w = 0; w < 8; ++w) { S += red[w]; S2 += red[8 + w]; }
    float mean = S * (1.f / HID);
    float var  = S2 * (1.f / HID) - mean * mean;
    float rstd = rsqrtf(var + EPS);
    const float* mrow = mod + b * MODW;
    __half* orow = out + (size_t)row * HID;
    for (int i = tid; i < 288; i += 256) {
        float4 v   = *(const float4*)(buf + i * 4);
        float4 sc4 = *(const float4*)(mrow + scOff + i * 4);
        float4 sh4 = *(const float4*)(mrow + shOff + i * 4);
        float o0 = fmaf((v.x - mean) * rstd, 1.f + sc4.x, sh4.x);
        float o1 = fmaf((v.y - mean) * rstd, 1.f + sc4.y, sh4.y);
        float o2 = fmaf((v.z - mean) * rstd, 1.f + sc4.z, sh4.z);
        float o3 = fmaf((v.w - mean) * rstd, 1.f + sc4.w, sh4.w);
        uint2 pk;
        pk.x = h2u(__floats2half2_rn(o0, o1));
        pk.y = h2u(__floats2half2_rn(o2, o3));
        *(uint2*)(orow + i * 4) = pk;
    }
}

// --------------- kernel 3: per-head LN of q and k (fp16, half2) -------------
__global__ __launch_bounds__(256) void qkln_kernel(
    __half* __restrict__ qkv, const float* __restrict__ g_q,
    const float* __restrict__ g_k)
{
    int warp = blockIdx.x * 8 + (threadIdx.x >> 5);
    int lane = threadIdx.x & 31;
    int h  = warp & 15;
    int qk = (warp >> 4) & 1;
    int bn = warp >> 5;
    __half2* p2 = (__half2*)(qkv + (size_t)bn * (3 * HID) + qk * HID + h * HD);
    float2 va = __half22float2(p2[lane]);
    float2 vb = (lane < 4) ? __half22float2(p2[32 + lane]) : make_float2(0.f, 0.f);
    float s  = va.x + va.y + vb.x + vb.y;
    float s2 = va.x * va.x + va.y * va.y + vb.x * vb.x + vb.y * vb.y;
    #pragma unroll
    for (int o = 16; o; o >>= 1) {
        s  += __shfl_xor_sync(0xffffffffu, s,  o);
        s2 += __shfl_xor_sync(0xffffffffu, s2, o);
    }
    float mean = s * (1.f / HD);
    float var  = s2 * (1.f / HD) - mean * mean;
    float rstd = rsqrtf(var + EPS);
    const float* g = qk ? g_k : g_q;
    float2 ga = *(const float2*)(g + 2 * lane);
    p2[lane] = __floats2half2_rn((va.x - mean) * rstd * ga.x,
                                 (va.y - mean) * rstd * ga.y);
    if (lane < 4) {
        float2 gb = *(const float2*)(g + 64 + 2 * lane);
        p2[32 + lane] = __floats2half2_rn((vb.x - mean) * rstd * gb.x,
                                          (vb.y - mean) * rstd * gb.y);
    }
}

// ------- kernel 4: flash attention (cp.async K/V pipeline + trans ldsm) -----
#define AQ 128
#define AK 64
#define QH 88     // halves stride for qs/ks/vs rows
#define KVBUF_H (AK * QH)                  // halves per K or V buffer
#define ATTN_SMEM ((AQ * QH + 4 * KVBUF_H) * 2)   // 67584 bytes

__global__ __launch_bounds__(256) void attn_kernel(
    const __half* __restrict__ qkv, __half* __restrict__ o)
{
    extern __shared__ __half smh[];
    __half* qs = smh;                      // [128][88]
    __half* kv = qs + AQ * QH;             // [2][ks 64x88, vs 64x88]

    int tid = threadIdx.x;
    int lane = tid & 31;
    int warp = tid >> 5;
    int grp = lane >> 2;
    int t4 = lane & 3;
    int m0 = warp * 16;
    int lsel = lane & 15;
    int ksel = (lane >> 4) * 8;

    int q0 = blockIdx.x * AQ;
    int h = blockIdx.y, b = blockIdx.z;
    const size_t baseBN = (size_t)b * SEQ * (3 * HID);
    const int hoff = h * HD;
    const float scale = 0.11785113019775793f;

    uint32_t qsA = smem_u32(qs);
    uint32_t kvA = smem_u32(kv);
    int vrow4 = ((lane >> 3) & 1) * 8 + (lane & 7);
    int vcol4 = (lane >> 4) * 8;
    uint32_t vrel4 = (uint32_t)(vrow4 * QH + vcol4) * 2;
    int vrow2 = (((lane & 15) >> 3) & 1) * 8 + (lane & 7);
    uint32_t vrel2 = (uint32_t)(vrow2 * QH + 64) * 2;

    for (int idx = tid; idx < AQ * 9; idx += 256) {
        int r = idx / 9, c = (idx - r * 9) * 8;
        *(float4*)(qs + r * QH + c) =
            *(const float4*)(qkv + baseBN + (size_t)(q0 + r) * (3 * HID) + hoff + c);
    }
    for (int idx = tid; idx < AQ + 2 * AK; idx += 256) {
        __half* base;
        if (idx < AQ)            base = qs + idx * QH;
        else if (idx < AQ + AK)  base = kv + (idx - AQ) * QH;
        else                     base = kv + 2 * KVBUF_H + (idx - AQ - AK) * QH;
        *(float4*)(base + 72) = make_float4(0.f, 0.f, 0.f, 0.f);
    }

    auto load_kv = [&](int kt, int bi) {
        uint32_t kD = kvA + (uint32_t)bi * (2 * KVBUF_H * 2);
        uint32_t vD = kD + KVBUF_H * 2;
        const __half* base = qkv + baseBN + (size_t)(kt * AK) * (3 * HID) + hoff;
        for (int idx = tid; idx < 1152; idx += 256) {
            int isv = idx >= 576;
            int j = isv ? idx - 576 : idx;
            int r = j / 9, c = (j - r * 9) * 8;
            const __half* src = base + (size_t)r * (3 * HID) + (isv ? 2 * HID : HID) + c;
            cp16s((isv ? vD : kD) + (uint32_t)(r * QH + c) * 2, src);
        }
    };

    float accO[9][4];
    #pragma unroll
    for (int di = 0; di < 9; ++di)
        #pragma unroll
        for (int e = 0; e < 4; ++e) accO[di][e] = 0.f;
    float mi0 = -INFINITY, mi1 = -INFINITY;
    float li0 = 0.f, li1 = 0.f;

    load_kv(0, 0);
    cp_commit();

    for (int kt = 0; kt < SEQ / AK; ++kt) {
        cp_wait<0>();
        __syncthreads();

        if (kt + 1 < SEQ / AK) {
            load_kv(kt + 1, (kt + 1) & 1);
        }
        cp_commit();

        uint32_t ksCur = kvA + (uint32_t)(kt & 1) * (2 * KVBUF_H * 2);
        uint32_t vsCur = ksCur + KVBUF_H * 2;

        // ---- S = Q K^T ----
        float sacc[8][4];
        #pragma unroll
        for (int ni = 0; ni < 8; ++ni)
            #pragma unroll
            for (int e = 0; e < 4; ++e) sacc[ni][e] = 0.f;
        #pragma unroll
        for (int ksb = 0; ksb < 5; ++ksb) {
            int k16 = ksb * 16;
            unsigned a0, a1, a2, a3;
            ldsm_x4(a0, a1, a2, a3, qsA + ((m0 + lsel) * QH + k16 + ksel) * 2);
            unsigned bf[8][2];
            #pragma unroll
            for (int p = 0; p < 4; ++p)
                ldsm_x4(bf[2 * p][0], bf[2 * p + 1][0], bf[2 * p][1], bf[2 * p + 1][1],
                        ksCur + ((p * 16 + lsel) * QH + k16 + ksel) * 2);
            #pragma unroll
            for (int ni = 0; ni < 8; ++ni)
                mma_f16(sacc[ni][0], sacc[ni][1], sacc[ni][2], sacc[ni][3],
                        a0, a1, a2, a3, bf[ni][0], bf[ni][1]);
        }

        // ---- online softmax ----
        float rmax0 = -INFINITY, rmax1 = -INFINITY;
        #pragma unroll
        for (int ni = 0; ni < 8; ++ni) {
            sacc[ni][0] *= scale; sacc[ni][1] *= scale;
            sacc[ni][2] *= scale; sacc[ni][3] *= scale;
            rmax0 = fmaxf(rmax0, fmaxf(sacc[ni][0], sacc[ni][1]));
            rmax1 = fmaxf(rmax1, fmaxf(sacc[ni][2], sacc[ni][3]));
        }
        #pragma unroll
        for (int off = 1; off < 4; off <<= 1) {
            rmax0 = fmaxf(rmax0, __shfl_xor_sync(0xffffffffu, rmax0, off));
            rmax1 = fmaxf(rmax1, __shfl_xor_sync(0xffffffffu, rmax1, off));
        }
        float newm0 = fmaxf(mi0, rmax0);
        float newm1 = fmaxf(mi1, rmax1);
        float alpha0 = __expf(mi0 - newm0);
        float alpha1 = __expf(mi1 - newm1);
        mi0 = newm0; mi1 = newm1;
        float rsum0 = 0.f, rsum1 = 0.f;
        unsigned ph0[8], ph1[8];
        #pragma unroll
        for (int ni = 0; ni < 8; ++ni) {
            float p0 = __expf(sacc[ni][0] - newm0);
            float p1 = __expf(sacc[ni][1] - newm0);
            float p2 = __expf(sacc[ni][2] - newm1);
            float p3 = __expf(sacc[ni][3] - newm1);
            rsum0 += p0 + p1; rsum1 += p2 + p3;
            ph0[ni] = h2u(__floats2half2_rn(p0, p1));
            ph1[ni] = h2u(__floats2half2_rn(p2, p3));
        }
        #pragma unroll
        for (int off = 1; off < 4; off <<= 1) {
            rsum0 += __shfl_xor_sync(0xffffffffu, rsum0, off);
            rsum1 += __shfl_xor_sync(0xffffffffu, rsum1, off);
        }
        li0 = li0 * alpha0 + rsum0;
        li1 = li1 * alpha1 + rsum1;
        #pragma unroll
        for (int di = 0; di < 9; ++di) {
            accO[di][0] *= alpha0; accO[di][1] *= alpha0;
            accO[di][2] *= alpha1; accO[di][3] *= alpha1;
        }

        // ---- O += P V ----
        #pragma unroll
        for (int kb = 0; kb < 4; ++kb) {
            unsigned a0 = ph0[2 * kb],     a2 = ph0[2 * kb + 1];
            unsigned a1 = ph1[2 * kb],     a3 = ph1[2 * kb + 1];
            uint32_t vkb = vsCur + (uint32_t)(kb * 16 * QH) * 2;
            unsigned vf[9][2];
            #pragma unroll
            for (int p = 0; p < 4; ++p)
                ldsm_x4t(vf[2 * p][0], vf[2 * p][1], vf[2 * p + 1][0], vf[2 * p + 1][1],
                         vkb + vrel4 + (uint32_t)(p * 16) * 2);
            ldsm_x2t(vf[8][0], vf[8][1], vkb + vrel2);
            #pragma unroll
            for (int di = 0; di < 9; ++di)
                mma_f16(accO[di][0], accO[di][1], accO[di][2], accO[di][3],
                        a0, a1, a2, a3, vf[di][0], vf[di][1]);
        }
    }

    float inv0 = 1.f / li0, inv1 = 1.f / li1;
    int row0 = q0 + m0 + grp;
    size_t b0a = ((size_t)b * SEQ + row0) * HID + hoff;
    size_t b1a = ((size_t)b * SEQ + row0 + 8) * HID + hoff;
    #pragma unroll
    for (int di = 0; di < 9; ++di) {
        int d = di * 8 + t4 * 2;
        *(__half2*)(o + b0a + d) = __floats2half2_rn(accO[di][0] * inv0, accO[di][1] * inv0);
        *(__half2*)(o + b1a + d) = __floats2half2_rn(accO[di][2] * inv1, accO[di][3] * inv1);
    }
}

// ----- kernel 5: FP16 GEMM 128x128x64, 3 stages, 512 thr, 32x32 warps -------
#define TBK 64
#define ASTRH 72                          // halves per smem row (64 + 8 pad)
#define TILE_H_BYTES (128 * ASTRH * 2)    // 18432
#define NSTAGE 3
#define GEMM_SMEM (NSTAGE * 2 * TILE_H_BYTES)   // 110592

template <int EPI, typename OutT>
__global__ __launch_bounds__(512, 2) void hgemm_kernel(
    const __half* __restrict__ A, const __half* __restrict__ BT,
    const float* __restrict__ bias, const float* __restrict__ res,
    const float* __restrict__ gate, OutT* __restrict__ C,
    int M, int N, int K)
{
    extern __shared__ char smc[];
    uint32_t sbase = smem_u32(smc);

    int tid = threadIdx.x;
    int lane = tid & 31;
    int warp = tid >> 5;             // 0..15
    int m0 = (warp & 3) * 32;        // 4 warps in M
    int n0 = (warp >> 2) * 32;       // 4 warps in N
    int grp = lane >> 2;
    int t4 = lane & 3;
    int lsel = lane & 15;
    int ksel = (lane >> 4) * 8;

    int cRow = blockIdx.y, cCol = blockIdx.x;
    const __half* Ab = A + (size_t)cRow * 128 * K;
    const __half* Bb = BT + (size_t)cCol * 128 * K;

    float acc[2][4][4];
    #pragma unroll
    for (int mi = 0; mi < 2; ++mi)
        #pragma unroll
        for (int ni = 0; ni < 4; ++ni)
            #pragma unroll
            for (int e = 0; e < 4; ++e) acc[mi][ni][e] = 0.f;

    int KT = K / TBK;    // 18 or 72

    // stage loader: A 128x64 halves = 1024 16B chunks; 2+2 cp.async/thread
    auto load_stage = [&](int kt, int s) {
        uint32_t aBase = sbase + s * TILE_H_BYTES;
        uint32_t bBase = sbase + (NSTAGE + s) * TILE_H_BYTES;
        const __half* Asrc = Ab + kt * TBK;
        const __half* Bsrc = Bb + kt * TBK;
        #pragma unroll
        for (int j = 0; j < 2; ++j) {
            int idx = tid + j * 512;
            int r = idx >> 3, c = idx & 7;
            cp16s(aBase + r * (ASTRH * 2) + c * 16, Asrc + (size_t)r * K + c * 8);
            cp16s(bBase + r * (ASTRH * 2) + c * 16, Bsrc + (size_t)r * K + c * 8);
        }
    };

    #pragma unroll
    for (int s = 0; s < NSTAGE - 1; ++s) {
        load_stage(s, s);
        cp_commit();
    }

    for (int kt = 0; kt < KT; ++kt) {
        cp_wait<NSTAGE - 2>();
        __syncthreads();

        int pf = kt + NSTAGE - 1;
        if (pf < KT) load_stage(pf, pf % NSTAGE);
        cp_commit();

        int st = kt % NSTAGE;
        uint32_t aBase = sbase + st * TILE_H_BYTES;
        uint32_t bBase = sbase + (NSTAGE + st) * TILE_H_BYTES;
        #pragma unroll
        for (int ks = 0; ks < 4; ++ks) {
            int k16 = ks * 16;
            unsigned af[2][4], bf[4][2];
            #pragma unroll
            for (int mi = 0; mi < 2; ++mi)
                ldsm_x4(af[mi][0], af[mi][1], af[mi][2], af[mi][3],
                        aBase + ((m0 + mi * 16 + lsel) * ASTRH + k16 + ksel) * 2);
            #pragma unroll
            for (int p = 0; p < 2; ++p)
                ldsm_x4(bf[2 * p][0], bf[2 * p + 1][0], bf[2 * p][1], bf[2 * p + 1][1],
                        bBase + ((n0 + p * 16 + lsel) * ASTRH + k16 + ksel) * 2);
            #pragma unroll
            for (int mi = 0; mi < 2; ++mi)
                #pragma unroll
                for (int ni = 0; ni < 4; ++ni)
                    mma_f16(acc[mi][ni][0], acc[mi][ni][1], acc[mi][ni][2], acc[mi][ni][3],
                            af[mi][0], af[mi][1], af[mi][2], af[mi][3],
                            bf[ni][0], bf[ni][1]);
        }
    }

    // ---- epilogue ----
    #pragma unroll
    for (int mi = 0; mi < 2; ++mi) {
        #pragma unroll
        for (int half_ = 0; half_ < 2; ++half_) {
            int row = cRow * 128 + m0 + mi * 16 + grp + half_ * 8;
            int gb = (row >> 10) * MODW;
            #pragma unroll
            for (int ni = 0; ni < 4; ++ni) {
                int col = cCol * 128 + n0 + ni * 8 + t4 * 2;
                float v0 = acc[mi][ni][half_ * 2 + 0] + bias[col];
                float v1 = acc[mi][ni][half_ * 2 + 1] + bias[col + 1];
                if (EPI == 1) {
                    float i0 = 0.7978845608028654f * (v0 + 0.044715f * v0 * v0 * v0);
                    float i1 = 0.7978845608028654f * (v1 + 0.044715f * v1 * v1 * v1);
                    v0 = v0 / (1.f + __expf(-2.f * i0));
                    v1 = v1 / (1.f + __expf(-2.f * i1));
                } else if (EPI == 2) {
                    v0 = fmaf(gate[gb + col],     v0, res[(size_t)row * N + col]);
                    v1 = fmaf(gate[gb + col + 1], v1, res[(size_t)row * N + col + 1]);
                }
                OutT* dst = C + (size_t)row * N + col;
                if (sizeof(OutT) == 2) {
                    *(__half2*)dst = __floats2half2_rn(v0, v1);
                } else {
                    *(float2*)dst = make_float2(v0, v1);
                }
            }
        }
    }
}

// ---------------------------- launcher --------------------------------------
extern "C" void kernel_launch(void* const* d_in, const int* in_sizes, int n_in,
                              void* d_out, int out_size)
{
    const float* x      = (const float*)d_in[0];
    const float* c      = (const float*)d_in[1];
    const float* w_mod  = (const float*)d_in[2];
    const float* b_mod  = (const float*)d_in[3];
    const float* w_qkv  = (const float*)d_in[4];
    const float* b_qkv  = (const float*)d_in[5];
    const float* gq     = (const float*)d_in[6];
    const float* gk     = (const float*)d_in[7];
    const float* w_proj = (const float*)d_in[8];
    const float* b_proj = (const float*)d_in[9];
    const float* w1     = (const float*)d_in[10];
    const float* b1     = (const float*)d_in[11];
    const float* w2     = (const float*)d_in[12];
    const float* b2     = (const float*)d_in[13];
    float* out = (float*)d_out;

    float *p_mod, *p_x1;
    __half *p_xn16, *p_qkv16, *p_o16, *p_h16, *p_wqkvT, *p_wprojT, *p_w1T, *p_w2T;
    cudaGetSymbolAddress((void**)&p_mod, g_mod);
    cudaGetSymbolAddress((void**)&p_xn16, g_xn16);
    cudaGetSymbolAddress((void**)&p_qkv16, g_qkv16);
    cudaGetSymbolAddress((void**)&p_o16, g_o16);
    cudaGetSymbolAddress((void**)&p_x1,  g_x1);
    cudaGetSymbolAddress((void**)&p_h16, g_h16);
    cudaGetSymbolAddress((void**)&p_wqkvT, g_wqkvT16);
    cudaGetSymbolAddress((void**)&p_wprojT, g_wprojT16);
    cudaGetSymbolAddress((void**)&p_w1T, g_w1T16);
    cudaGetSymbolAddress((void**)&p_w2T, g_w2T16);

    cudaFuncSetAttribute(attn_kernel,
                         cudaFuncAttributeMaxDynamicSharedMemorySize, ATTN_SMEM);
    cudaFuncSetAttribute(mod_kernel,
                         cudaFuncAttributeMaxDynamicSharedMemorySize, MOD_SMEM);
    cudaFuncSetAttribute(hgemm_kernel<0, __half>,
                         cudaFuncAttributeMaxDynamicSharedMemorySize, GEMM_SMEM);
    cudaFuncSetAttribute(hgemm_kernel<1, __half>,
                         cudaFuncAttributeMaxDynamicSharedMemorySize, GEMM_SMEM);
    cudaFuncSetAttribute(hgemm_kernel<2, float>,
                         cudaFuncAttributeMaxDynamicSharedMemorySize, GEMM_SMEM);

    // 0. convert+transpose ALL weights in one launch
    wcvt_all_kernel<<<WCVT_TILES, 256>>>(w_qkv, w_proj, w1, w2,
                                         p_wqkvT, p_wprojT, p_w1T, p_w2T);

    // 1. adaLN modulation (batch-reuse: w_mod read once)
    mod_kernel<<<MODW / 32, 256, MOD_SMEM>>>(c, w_mod, b_mod, p_mod);
    // 2. LN + modulate (MSA) -> fp16
    ln_mod_kernel<<<ROWS, 256>>>(x, p_mod, 0, HID, p_xn16);
    // 3. QKV GEMM -> fp16 qkv
    hgemm_kernel<0, __half><<<dim3(3 * HID / 128, ROWS / 128), 512, GEMM_SMEM>>>(
        p_xn16, p_wqkvT, b_qkv, nullptr, nullptr, p_qkv16, ROWS, 3 * HID, HID);
    // 4. per-head LN of q,k
    qkln_kernel<<<ROWS * 32 / 8, 256>>>(p_qkv16, gq, gk);
    // 5. attention -> fp16 o
    attn_kernel<<<dim3(SEQ / AQ, NH, Bsz), 256, ATTN_SMEM>>>(p_qkv16, p_o16);
    // 6. proj + gated residual -> fp32 x1
    hgemm_kernel<2, float><<<dim3(HID / 128, ROWS / 128), 512, GEMM_SMEM>>>(
        p_o16, p_wprojT, b_proj, x, p_mod + 2 * HID, p_x1, ROWS, HID, HID);
    // 7. LN + modulate (MLP) -> fp16
    ln_mod_kernel<<<ROWS, 256>>>(p_x1, p_mod, 3 * HID, 4 * HID, p_xn16);
    // 8. MLP up + gelu -> fp16 h
    hgemm_kernel<1, __half><<<dim3(MLPD / 128, ROWS / 128), 512, GEMM_SMEM>>>(
        p_xn16, p_w1T, b1, nullptr, nullptr, p_h16, ROWS, MLPD, HID);
    // 9. MLP down + gated residual -> fp32 out
    hgemm_kernel<2, float><<<dim3(HID / 128, ROWS / 128), 512, GEMM_SMEM>>>(
        p_h16, p_w2T, b2, p_x1, p_mod + 5 * HID, out, ROWS, HID, MLPD);
}

// round 15
// speedup vs baseline: 1.2089x; 1.0287x over previous
#include <cuda_runtime.h>
#include <cuda_fp16.h>
#include <math.h>
#include <stdint.h>

// Problem constants
#define Bsz 16
#define SEQ 1024
#define HID 1152
#define NH 16
#define HD 72
#define MLPD 4608
#define ROWS (Bsz * SEQ)          // 16384
#define MODW (6 * HID)            // 6912
#define EPS 1e-6f

// ---------------- scratch (device globals; allocation-free) ----------------
__device__ float  g_mod[Bsz * MODW];
__device__ __half g_xn16[ROWS * HID];
__device__ __half g_qkv16[ROWS * 3 * HID];
__device__ __half g_o16[ROWS * HID];
__device__ float  g_x1[ROWS * HID];
__device__ __half g_h16[ROWS * MLPD];
// fp16 transposed weights [N][K]
__device__ __half g_wqkvT16[3 * HID * HID];
__device__ __half g_wprojT16[HID * HID];
__device__ __half g_w1T16[HID * MLPD];
__device__ __half g_w2T16[MLPD * HID];

__device__ __forceinline__ void mma_f16(
    float& c0, float& c1, float& c2, float& c3,
    unsigned a0, unsigned a1, unsigned a2, unsigned a3,
    unsigned b0, unsigned b1)
{
    asm volatile(
        "mma.sync.aligned.m16n8k16.row.col.f32.f16.f16.f32 "
        "{%0,%1,%2,%3}, {%4,%5,%6,%7}, {%8,%9}, {%0,%1,%2,%3};"
        : "+f"(c0), "+f"(c1), "+f"(c2), "+f"(c3)
        : "r"(a0), "r"(a1), "r"(a2), "r"(a3), "r"(b0), "r"(b1));
}

__device__ __forceinline__ void ldsm_x4(
    unsigned& r0, unsigned& r1, unsigned& r2, unsigned& r3, uint32_t addr)
{
    asm volatile("ldmatrix.sync.aligned.m8n8.x4.shared.b16 {%0,%1,%2,%3}, [%4];"
                 : "=r"(r0), "=r"(r1), "=r"(r2), "=r"(r3) : "r"(addr));
}

__device__ __forceinline__ void ldsm_x4t(
    unsigned& r0, unsigned& r1, unsigned& r2, unsigned& r3, uint32_t addr)
{
    asm volatile("ldmatrix.sync.aligned.m8n8.x4.trans.shared.b16 {%0,%1,%2,%3}, [%4];"
                 : "=r"(r0), "=r"(r1), "=r"(r2), "=r"(r3) : "r"(addr));
}

__device__ __forceinline__ void ldsm_x2t(
    unsigned& r0, unsigned& r1, uint32_t addr)
{
    asm volatile("ldmatrix.sync.aligned.m8n8.x2.trans.shared.b16 {%0,%1}, [%2];"
                 : "=r"(r0), "=r"(r1) : "r"(addr));
}

__device__ __forceinline__ void cp16s(uint32_t dst, const void* src) {
    asm volatile("cp.async.cg.shared.global [%0], [%1], 16;" :: "r"(dst), "l"(src));
}
__device__ __forceinline__ void cp_commit() {
    asm volatile("cp.async.commit_group;");
}
template <int N> __device__ __forceinline__ void cp_wait() {
    asm volatile("cp.async.wait_group %0;" :: "n"(N));
}
__device__ __forceinline__ uint32_t smem_u32(const void* p) {
    uint32_t a;
    asm("{ .reg .u64 t; cvta.to.shared.u64 t, %1; cvt.u32.u64 %0, t; }"
        : "=r"(a) : "l"(p));
    return a;
}
__device__ __forceinline__ unsigned h2u(__half2 h) {
    return *reinterpret_cast<unsigned*>(&h);
}

// --- kernel 0: ALL weight converts+transposes fp32 [K][N] -> fp16 [N][K] ----
#define WCVT_TILES 15552
__global__ __launch_bounds__(256) void wcvt_all_kernel(
    const float* __restrict__ wq, const float* __restrict__ wp,
    const float* __restrict__ w1p, const float* __restrict__ w2p,
    __half* __restrict__ oq, __half* __restrict__ op,
    __half* __restrict__ o1, __half* __restrict__ o2)
{
    __shared__ float t[32][33];
    int bid = blockIdx.x;
    const float* w; __half* wt; int K, N, tt;
    if (bid < 3888)       { w = wq;  wt = oq; K = HID;  N = 3 * HID; tt = bid; }
    else if (bid < 5184)  { w = wp;  wt = op; K = HID;  N = HID;     tt = bid - 3888; }
    else if (bid < 10368) { w = w1p; wt = o1; K = HID;  N = MLPD;    tt = bid - 5184; }
    else                  { w = w2p; wt = o2; K = MLPD; N = HID;     tt = bid - 10368; }
    int nT = N >> 5;
    int n0 = (tt % nT) * 32, k0 = (tt / nT) * 32;
    int tx = threadIdx.x & 31, ty = threadIdx.x >> 5;
    #pragma unroll
    for (int j = 0; j < 32; j += 8)
        t[ty + j][tx] = w[(size_t)(k0 + ty + j) * N + n0 + tx];
    __syncthreads();
    #pragma unroll
    for (int j = 0; j < 32; j += 8)
        wt[(size_t)(n0 + ty + j) * K + k0 + tx] = __float2half(t[tx][ty + j]);
}

// ------- kernel 1: mod = swish(c) @ w_mod + b_mod (batch-reuse) -------------
#define MODKG 8
#define MODKL (HID / MODKG)      // 144
#define MOD_SMEM ((Bsz * HID + MODKG * 32 * Bsz) * 4)   // 90112 bytes
__global__ __launch_bounds__(256) void mod_kernel(
    const float* __restrict__ c, const float* __restrict__ w_mod,
    const float* __restrict__ b_mod, float* __restrict__ mod)
{
    extern __shared__ float sm[];
    float* sct = sm;                   // [1152][16] swish(c) transposed
    float* red = sm + Bsz * HID;       // [8][32][16] partials
    int tid = threadIdx.x;
    for (int i = tid; i < Bsz * HID; i += 256) {
        int b = i / HID, k = i - b * HID;
        float v = c[i];
        sct[k * Bsz + b] = v / (1.f + expf(-v));
    }
    __syncthreads();
    int cl = tid & 31;
    int kg = tid >> 5;                 // 0..7
    int col = blockIdx.x * 32 + cl;
    float acc[Bsz];
    #pragma unroll
    for (int b = 0; b < Bsz; ++b) acc[b] = 0.f;
    int k0 = kg * MODKL;
    for (int k = k0; k < k0 + MODKL; ++k) {
        float w = w_mod[(size_t)k * MODW + col];
        const float4* s4 = (const float4*)(sct + k * Bsz);
        #pragma unroll
        for (int b4 = 0; b4 < 4; ++b4) {
            float4 s = s4[b4];
            acc[4 * b4 + 0] = fmaf(s.x, w, acc[4 * b4 + 0]);
            acc[4 * b4 + 1] = fmaf(s.y, w, acc[4 * b4 + 1]);
            acc[4 * b4 + 2] = fmaf(s.z, w, acc[4 * b4 + 2]);
            acc[4 * b4 + 3] = fmaf(s.w, w, acc[4 * b4 + 3]);
        }
    }
    #pragma unroll
    for (int b = 0; b < Bsz; ++b)
        red[(kg * 32 + cl) * Bsz + b] = acc[b];
    __syncthreads();
    #pragma unroll
    for (int t = 0; t < 2; ++t) {
        int task = tid + t * 256;
        int tc = task >> 4;
        int tb = task & 15;
        float s = b_mod[blockIdx.x * 32 + tc];
        #pragma unroll
        for (int g = 0; g < MODKG; ++g)
            s += red[(g * 32 + tc) * Bsz + tb];
        mod[tb * MODW + blockIdx.x * 32 + tc] = s;
    }
}

// --------- kernel 2: LN(x) * (1+sc) + sh  (per row), fp16 output ------------
__global__ __launch_bounds__(256) void ln_mod_kernel(
    const float* __restrict__ x, const float* __restrict__ mod,
    int shOff, int scOff, __half* __restrict__ out)
{
    __shared__ float buf[HID];
    __shared__ float red[16];
    int row = blockIdx.x;
    int b = row >> 10;
    int tid = threadIdx.x;
    const float* xr = x + (size_t)row * HID;
    float s = 0.f, s2 = 0.f;
    for (int i = tid; i < 288; i += 256) {
        float4 v = *(const float4*)(xr + i * 4);
        *(float4*)(buf + i * 4) = v;
        s  += v.x + v.y + v.z + v.w;
        s2 += v.x * v.x + v.y * v.y + v.z * v.z + v.w * v.w;
    }
    #pragma unroll
    for (int o = 16; o; o >>= 1) {
        s  += __shfl_xor_sync(0xffffffffu, s,  o);
        s2 += __shfl_xor_sync(0xffffffffu, s2, o);
    }
    if ((tid & 31) == 0) { red[tid >> 5] = s; red[8 + (tid >> 5)] = s2; }
    __syncthreads();
    float S = 0.f, S2 = 0.f;
    #pragma unroll
    for (int w = 0; w < 8; ++w) { S += red[w]; S2 += red[8 + w]; }
    float mean = S * (1.f / HID);
    float var  = S2 * (1.f / HID) - mean * mean;
    float rstd = rsqrtf(var + EPS);
    const float* mrow = mod + b * MODW;
    __half* orow = out + (size_t)row * HID;
    for (int i = tid; i < 288; i += 256) {
        float4 v   = *(const float4*)(buf + i * 4);
        float4 sc4 = *(const float4*)(mrow + scOff + i * 4);
        float4 sh4 = *(const float4*)(mrow + shOff + i * 4);
        float o0 = fmaf((v.x - mean) * rstd, 1.f + sc4.x, sh4.x);
        float o1 = fmaf((v.y - mean) * rstd, 1.f + sc4.y, sh4.y);
        float o2 = fmaf((v.z - mean) * rstd, 1.f + sc4.z, sh4.z);
        float o3 = fmaf((v.w - mean) * rstd, 1.f + sc4.w, sh4.w);
        uint2 pk;
        pk.x = h2u(__floats2half2_rn(o0, o1));
        pk.y = h2u(__floats2half2_rn(o2, o3));
        *(uint2*)(orow + i * 4) = pk;
    }
}

// --------------- kernel 3: per-head LN of q and k (fp16, half2) -------------
__global__ __launch_bounds__(256) void qkln_kernel(
    __half* __restrict__ qkv, const float* __restrict__ g_q,
    const float* __restrict__ g_k)
{
    int warp = blockIdx.x * 8 + (threadIdx.x >> 5);
    int lane = threadIdx.x & 31;
    int h  = warp & 15;
    int qk = (warp >> 4) & 1;
    int bn = warp >> 5;
    __half2* p2 = (__half2*)(qkv + (size_t)bn * (3 * HID) + qk * HID + h * HD);
    float2 va = __half22float2(p2[lane]);
    float2 vb = (lane < 4) ? __half22float2(p2[32 + lane]) : make_float2(0.f, 0.f);
    float s  = va.x + va.y + vb.x + vb.y;
    float s2 = va.x * va.x + va.y * va.y + vb.x * vb.x + vb.y * vb.y;
    #pragma unroll
    for (int o = 16; o; o >>= 1) {
        s  += __shfl_xor_sync(0xffffffffu, s,  o);
        s2 += __shfl_xor_sync(0xffffffffu, s2, o);
    }
    float mean = s * (1.f / HD);
    float var  = s2 * (1.f / HD) - mean * mean;
    float rstd = rsqrtf(var + EPS);
    const float* g = qk ? g_k : g_q;
    float2 ga = *(const float2*)(g + 2 * lane);
    p2[lane] = __floats2half2_rn((va.x - mean) * rstd * ga.x,
                                 (va.y - mean) * rstd * ga.y);
    if (lane < 4) {
        float2 gb = *(const float2*)(g + 64 + 2 * lane);
        p2[32 + lane] = __floats2half2_rn((vb.x - mean) * rstd * gb.x,
                                          (vb.y - mean) * rstd * gb.y);
    }
}

// ------- kernel 4: flash attention (cp.async K/V pipeline + trans ldsm) -----
#define AQ 128
#define AK 64
#define QH 88     // halves stride for qs/ks/vs rows
#define KVBUF_H (AK * QH)                  // halves per K or V buffer
#define ATTN_SMEM ((AQ * QH + 4 * KVBUF_H) * 2)   // 67584 bytes

__global__ __launch_bounds__(256) void attn_kernel(
    const __half* __restrict__ qkv, __half* __restrict__ o)
{
    extern __shared__ __half smh[];
    __half* qs = smh;                      // [128][88]
    __half* kv = qs + AQ * QH;             // [2][ks 64x88, vs 64x88]

    int tid = threadIdx.x;
    int lane = tid & 31;
    int warp = tid >> 5;
    int grp = lane >> 2;
    int t4 = lane & 3;
    int m0 = warp * 16;
    int lsel = lane & 15;
    int ksel = (lane >> 4) * 8;

    int q0 = blockIdx.x * AQ;
    int h = blockIdx.y, b = blockIdx.z;
    const size_t baseBN = (size_t)b * SEQ * (3 * HID);
    const int hoff = h * HD;
    const float scale = 0.11785113019775793f;

    uint32_t qsA = smem_u32(qs);
    uint32_t kvA = smem_u32(kv);
    int vrow4 = ((lane >> 3) & 1) * 8 + (lane & 7);
    int vcol4 = (lane >> 4) * 8;
    uint32_t vrel4 = (uint32_t)(vrow4 * QH + vcol4) * 2;
    int vrow2 = (((lane & 15) >> 3) & 1) * 8 + (lane & 7);
    uint32_t vrel2 = (uint32_t)(vrow2 * QH + 64) * 2;

    for (int idx = tid; idx < AQ * 9; idx += 256) {
        int r = idx / 9, c = (idx - r * 9) * 8;
        *(float4*)(qs + r * QH + c) =
            *(const float4*)(qkv + baseBN + (size_t)(q0 + r) * (3 * HID) + hoff + c);
    }
    for (int idx = tid; idx < AQ + 2 * AK; idx += 256) {
        __half* base;
        if (idx < AQ)            base = qs + idx * QH;
        else if (idx < AQ + AK)  base = kv + (idx - AQ) * QH;
        else                     base = kv + 2 * KVBUF_H + (idx - AQ - AK) * QH;
        *(float4*)(base + 72) = make_float4(0.f, 0.f, 0.f, 0.f);
    }

    auto load_kv = [&](int kt, int bi) {
        uint32_t kD = kvA + (uint32_t)bi * (2 * KVBUF_H * 2);
        uint32_t vD = kD + KVBUF_H * 2;
        const __half* base = qkv + baseBN + (size_t)(kt * AK) * (3 * HID) + hoff;
        for (int idx = tid; idx < 1152; idx += 256) {
            int isv = idx >= 576;
            int j = isv ? idx - 576 : idx;
            int r = j / 9, c = (j - r * 9) * 8;
            const __half* src = base + (size_t)r * (3 * HID) + (isv ? 2 * HID : HID) + c;
            cp16s((isv ? vD : kD) + (uint32_t)(r * QH + c) * 2, src);
        }
    };

    float accO[9][4];
    #pragma unroll
    for (int di = 0; di < 9; ++di)
        #pragma unroll
        for (int e = 0; e < 4; ++e) accO[di][e] = 0.f;
    float mi0 = -INFINITY, mi1 = -INFINITY;
    float li0 = 0.f, li1 = 0.f;

    load_kv(0, 0);
    cp_commit();

    for (int kt = 0; kt < SEQ / AK; ++kt) {
        cp_wait<0>();
        __syncthreads();

        if (kt + 1 < SEQ / AK) {
            load_kv(kt + 1, (kt + 1) & 1);
        }
        cp_commit();

        uint32_t ksCur = kvA + (uint32_t)(kt & 1) * (2 * KVBUF_H * 2);
        uint32_t vsCur = ksCur + KVBUF_H * 2;

        // ---- S = Q K^T ----
        float sacc[8][4];
        #pragma unroll
        for (int ni = 0; ni < 8; ++ni)
            #pragma unroll
            for (int e = 0; e < 4; ++e) sacc[ni][e] = 0.f;
        #pragma unroll
        for (int ksb = 0; ksb < 5; ++ksb) {
            int k16 = ksb * 16;
            unsigned a0, a1, a2, a3;
            ldsm_x4(a0, a1, a2, a3, qsA + ((m0 + lsel) * QH + k16 + ksel) * 2);
            unsigned bf[8][2];
            #pragma unroll
            for (int p = 0; p < 4; ++p)
                ldsm_x4(bf[2 * p][0], bf[2 * p + 1][0], bf[2 * p][1], bf[2 * p + 1][1],
                        ksCur + ((p * 16 + lsel) * QH + k16 + ksel) * 2);
            #pragma unroll
            for (int ni = 0; ni < 8; ++ni)
                mma_f16(sacc[ni][0], sacc[ni][1], sacc[ni][2], sacc[ni][3],
                        a0, a1, a2, a3, bf[ni][0], bf[ni][1]);
        }

        // ---- online softmax ----
        float rmax0 = -INFINITY, rmax1 = -INFINITY;
        #pragma unroll
        for (int ni = 0; ni < 8; ++ni) {
            sacc[ni][0] *= scale; sacc[ni][1] *= scale;
            sacc[ni][2] *= scale; sacc[ni][3] *= scale;
            rmax0 = fmaxf(rmax0, fmaxf(sacc[ni][0], sacc[ni][1]));
            rmax1 = fmaxf(rmax1, fmaxf(sacc[ni][2], sacc[ni][3]));
        }
        #pragma unroll
        for (int off = 1; off < 4; off <<= 1) {
            rmax0 = fmaxf(rmax0, __shfl_xor_sync(0xffffffffu, rmax0, off));
            rmax1 = fmaxf(rmax1, __shfl_xor_sync(0xffffffffu, rmax1, off));
        }
        float newm0 = fmaxf(mi0, rmax0);
        float newm1 = fmaxf(mi1, rmax1);
        float alpha0 = __expf(mi0 - newm0);
        float alpha1 = __expf(mi1 - newm1);
        mi0 = newm0; mi1 = newm1;
        float rsum0 = 0.f, rsum1 = 0.f;
        unsigned ph0[8], ph1[8];
        #pragma unroll
        for (int ni = 0; ni < 8; ++ni) {
            float p0 = __expf(sacc[ni][0] - newm0);
            float p1 = __expf(sacc[ni][1] - newm0);
            float p2 = __expf(sacc[ni][2] - newm1);
            float p3 = __expf(sacc[ni][3] - newm1);
            rsum0 += p0 + p1; rsum1 += p2 + p3;
            ph0[ni] = h2u(__floats2half2_rn(p0, p1));
            ph1[ni] = h2u(__floats2half2_rn(p2, p3));
        }
        #pragma unroll
        for (int off = 1; off < 4; off <<= 1) {
            rsum0 += __shfl_xor_sync(0xffffffffu, rsum0, off);
            rsum1 += __shfl_xor_sync(0xffffffffu, rsum1, off);
        }
        li0 = li0 * alpha0 + rsum0;
        li1 = li1 * alpha1 + rsum1;
        #pragma unroll
        for (int di = 0; di < 9; ++di) {
            accO[di][0] *= alpha0; accO[di][1] *= alpha0;
            accO[di][2] *= alpha1; accO[di][3] *= alpha1;
        }

        // ---- O += P V ----
        #pragma unroll
        for (int kb = 0; kb < 4; ++kb) {
            unsigned a0 = ph0[2 * kb],     a2 = ph0[2 * kb + 1];
            unsigned a1 = ph1[2 * kb],     a3 = ph1[2 * kb + 1];
            uint32_t vkb = vsCur + (uint32_t)(kb * 16 * QH) * 2;
            unsigned vf[9][2];
            #pragma unroll
            for (int p = 0; p < 4; ++p)
                ldsm_x4t(vf[2 * p][0], vf[2 * p][1], vf[2 * p + 1][0], vf[2 * p + 1][1],
                         vkb + vrel4 + (uint32_t)(p * 16) * 2);
            ldsm_x2t(vf[8][0], vf[8][1], vkb + vrel2);
            #pragma unroll
            for (int di = 0; di < 9; ++di)
                mma_f16(accO[di][0], accO[di][1], accO[di][2], accO[di][3],
                        a0, a1, a2, a3, vf[di][0], vf[di][1]);
        }
    }

    float inv0 = 1.f / li0, inv1 = 1.f / li1;
    int row0 = q0 + m0 + grp;
    size_t b0a = ((size_t)b * SEQ + row0) * HID + hoff;
    size_t b1a = ((size_t)b * SEQ + row0 + 8) * HID + hoff;
    #pragma unroll
    for (int di = 0; di < 9; ++di) {
        int d = di * 8 + t4 * 2;
        *(__half2*)(o + b0a + d) = __floats2half2_rn(accO[di][0] * inv0, accO[di][1] * inv0);
        *(__half2*)(o + b1a + d) = __floats2half2_rn(accO[di][2] * inv1, accO[di][3] * inv1);
    }
}

// ----- kernel 5: FP16 GEMM 128x128x64, 2 stages, 128 thr, 64x64 warps -------
// 4 warps of 64x64 (best ldsm:mma economy), 3 CTAs/SM (73.7 KB smem).
#define TBK 64
#define ASTRH 72                          // halves per smem row (64 + 8 pad)
#define TILE_H_BYTES (128 * ASTRH * 2)    // 18432
#define NSTAGE 2
#define GEMM_SMEM (NSTAGE * 2 * TILE_H_BYTES)   // 73728

template <int EPI, typename OutT>
__global__ __launch_bounds__(128, 3) void hgemm_kernel(
    const __half* __restrict__ A, const __half* __restrict__ BT,
    const float* __restrict__ bias, const float* __restrict__ res,
    const float* __restrict__ gate, OutT* __restrict__ C,
    int M, int N, int K)
{
    extern __shared__ char smc[];
    uint32_t sbase = smem_u32(smc);

    int tid = threadIdx.x;
    int lane = tid & 31;
    int warp = tid >> 5;             // 0..3
    int m0 = (warp & 1) * 64;        // 2 warps in M
    int n0 = (warp >> 1) * 64;       // 2 warps in N
    int grp = lane >> 2;
    int t4 = lane & 3;
    int lsel = lane & 15;
    int ksel = (lane >> 4) * 8;

    int cRow = blockIdx.y, cCol = blockIdx.x;
    const __half* Ab = A + (size_t)cRow * 128 * K;
    const __half* Bb = BT + (size_t)cCol * 128 * K;

    float acc[4][8][4];
    #pragma unroll
    for (int mi = 0; mi < 4; ++mi)
        #pragma unroll
        for (int ni = 0; ni < 8; ++ni)
            #pragma unroll
            for (int e = 0; e < 4; ++e) acc[mi][ni][e] = 0.f;

    int KT = K / TBK;    // 18 or 72

    // stage loader: A 1024 + B 1024 16B-chunks over 128 threads = 8+8 each
    auto load_stage = [&](int kt, int s) {
        uint32_t aBase = sbase + s * TILE_H_BYTES;
        uint32_t bBase = sbase + (NSTAGE + s) * TILE_H_BYTES;
        const __half* Asrc = Ab + kt * TBK;
        const __half* Bsrc = Bb + kt * TBK;
        #pragma unroll
        for (int j = 0; j < 8; ++j) {
            int idx = tid + j * 128;
            int r = idx >> 3, c = idx & 7;
            cp16s(aBase + r * (ASTRH * 2) + c * 16, Asrc + (size_t)r * K + c * 8);
            cp16s(bBase + r * (ASTRH * 2) + c * 16, Bsrc + (size_t)r * K + c * 8);
        }
    };

    load_stage(0, 0);
    cp_commit();

    for (int kt = 0; kt < KT; ++kt) {
        cp_wait<0>();
        __syncthreads();

        if (kt + 1 < KT) load_stage(kt + 1, (kt + 1) & 1);
        cp_commit();

        int st = kt & 1;
        uint32_t aBase = sbase + st * TILE_H_BYTES;
        uint32_t bBase = sbase + (NSTAGE + st) * TILE_H_BYTES;
        #pragma unroll
        for (int ks = 0; ks < 4; ++ks) {
            int k16 = ks * 16;
            unsigned af[4][4], bf[8][2];
            #pragma unroll
            for (int mi = 0; mi < 4; ++mi)
                ldsm_x4(af[mi][0], af[mi][1], af[mi][2], af[mi][3],
                        aBase + ((m0 + mi * 16 + lsel) * ASTRH + k16 + ksel) * 2);
            #pragma unroll
            for (int p = 0; p < 4; ++p)
                ldsm_x4(bf[2 * p][0], bf[2 * p + 1][0], bf[2 * p][1], bf[2 * p + 1][1],
                        bBase + ((n0 + p * 16 + lsel) * ASTRH + k16 + ksel) * 2);
            #pragma unroll
            for (int mi = 0; mi < 4; ++mi)
                #pragma unroll
                for (int ni = 0; ni < 8; ++ni)
                    mma_f16(acc[mi][ni][0], acc[mi][ni][1], acc[mi][ni][2], acc[mi][ni][3],
                            af[mi][0], af[mi][1], af[mi][2], af[mi][3],
                            bf[ni][0], bf[ni][1]);
        }
    }

    // ---- epilogue ----
    #pragma unroll
    for (int mi = 0; mi < 4; ++mi) {
        #pragma unroll
        for (int half_ = 0; half_ < 2; ++half_) {
            int row = cRow * 128 + m0 + mi * 16 + grp + half_ * 8;
            int gb = (row >> 10) * MODW;
            #pragma unroll
            for (int ni = 0; ni < 8; ++ni) {
                int col = cCol * 128 + n0 + ni * 8 + t4 * 2;
                float v0 = acc[mi][ni][half_ * 2 + 0] + bias[col];
                float v1 = acc[mi][ni][half_ * 2 + 1] + bias[col + 1];
                if (EPI == 1) {
                    float i0 = 0.7978845608028654f * (v0 + 0.044715f * v0 * v0 * v0);
                    float i1 = 0.7978845608028654f * (v1 + 0.044715f * v1 * v1 * v1);
                    v0 = v0 / (1.f + __expf(-2.f * i0));
                    v1 = v1 / (1.f + __expf(-2.f * i1));
                } else if (EPI == 2) {
                    v0 = fmaf(gate[gb + col],     v0, res[(size_t)row * N + col]);
                    v1 = fmaf(gate[gb + col + 1], v1, res[(size_t)row * N + col + 1]);
                }
                OutT* dst = C + (size_t)row * N + col;
                if (sizeof(OutT) == 2) {
                    *(__half2*)dst = __floats2half2_rn(v0, v1);
                } else {
                    *(float2*)dst = make_float2(v0, v1);
                }
            }
        }
    }
}

// ---------------------------- launcher --------------------------------------
extern "C" void kernel_launch(void* const* d_in, const int* in_sizes, int n_in,
                              void* d_out, int out_size)
{
    const float* x      = (const float*)d_in[0];
    const float* c      = (const float*)d_in[1];
    const float* w_mod  = (const float*)d_in[2];
    const float* b_mod  = (const float*)d_in[3];
    const float* w_qkv  = (const float*)d_in[4];
    const float* b_qkv  = (const float*)d_in[5];
    const float* gq     = (const float*)d_in[6];
    const float* gk     = (const float*)d_in[7];
    const float* w_proj = (const float*)d_in[8];
    const float* b_proj = (const float*)d_in[9];
    const float* w1     = (const float*)d_in[10];
    const float* b1     = (const float*)d_in[11];
    const float* w2     = (const float*)d_in[12];
    const float* b2     = (const float*)d_in[13];
    float* out = (float*)d_out;

    float *p_mod, *p_x1;
    __half *p_xn16, *p_qkv16, *p_o16, *p_h16, *p_wqkvT, *p_wprojT, *p_w1T, *p_w2T;
    cudaGetSymbolAddress((void**)&p_mod, g_mod);
    cudaGetSymbolAddress((void**)&p_xn16, g_xn16);
    cudaGetSymbolAddress((void**)&p_qkv16, g_qkv16);
    cudaGetSymbolAddress((void**)&p_o16, g_o16);
    cudaGetSymbolAddress((void**)&p_x1,  g_x1);
    cudaGetSymbolAddress((void**)&p_h16, g_h16);
    cudaGetSymbolAddress((void**)&p_wqkvT, g_wqkvT16);
    cudaGetSymbolAddress((void**)&p_wprojT, g_wprojT16);
    cudaGetSymbolAddress((void**)&p_w1T, g_w1T16);
    cudaGetSymbolAddress((void**)&p_w2T, g_w2T16);

    cudaFuncSetAttribute(attn_kernel,
                         cudaFuncAttributeMaxDynamicSharedMemorySize, ATTN_SMEM);
    cudaFuncSetAttribute(mod_kernel,
                         cudaFuncAttributeMaxDynamicSharedMemorySize, MOD_SMEM);
    cudaFuncSetAttribute(hgemm_kernel<0, __half>,
                         cudaFuncAttributeMaxDynamicSharedMemorySize, GEMM_SMEM);
    cudaFuncSetAttribute(hgemm_kernel<1, __half>,
                         cudaFuncAttributeMaxDynamicSharedMemorySize, GEMM_SMEM);
    cudaFuncSetAttribute(hgemm_kernel<2, float>,
                         cudaFuncAttributeMaxDynamicSharedMemorySize, GEMM_SMEM);

    // 0. convert+transpose ALL weights in one launch
    wcvt_all_kernel<<<WCVT_TILES, 256>>>(w_qkv, w_proj, w1, w2,
                                         p_wqkvT, p_wprojT, p_w1T, p_w2T);

    // 1. adaLN modulation (batch-reuse: w_mod read once)
    mod_kernel<<<MODW / 32, 256, MOD_SMEM>>>(c, w_mod, b_mod, p_mod);
    // 2. LN + modulate (MSA) -> fp16
    ln_mod_kernel<<<ROWS, 256>>>(x, p_mod, 0, HID, p_xn16);
    // 3. QKV GEMM -> fp16 qkv
    hgemm_kernel<0, __half><<<dim3(3 * HID / 128, ROWS / 128), 128, GEMM_SMEM>>>(
        p_xn16, p_wqkvT, b_qkv, nullptr, nullptr, p_qkv16, ROWS, 3 * HID, HID);
    // 4. per-head LN of q,k
    qkln_kernel<<<ROWS * 32 / 8, 256>>>(p_qkv16, gq, gk);
    // 5. attention -> fp16 o
    attn_kernel<<<dim3(SEQ / AQ, NH, Bsz), 256, ATTN_SMEM>>>(p_qkv16, p_o16);
    // 6. proj + gated residual -> fp32 x1
    hgemm_kernel<2, float><<<dim3(HID / 128, ROWS / 128), 128, GEMM_SMEM>>>(
        p_o16, p_wprojT, b_proj, x, p_mod + 2 * HID, p_x1, ROWS, HID, HID);
    // 7. LN + modulate (MLP) -> fp16
    ln_mod_kernel<<<ROWS, 256>>>(p_x1, p_mod, 3 * HID, 4 * HID, p_xn16);
    // 8. MLP up + gelu -> fp16 h
    hgemm_kernel<1, __half><<<dim3(MLPD / 128, ROWS / 128), 128, GEMM_SMEM>>>(
        p_xn16, p_w1T, b1, nullptr, nullptr, p_h16, ROWS, MLPD, HID);
    // 9. MLP down + gated residual -> fp32 out
    hgemm_kernel<2, float><<<dim3(HID / 128, ROWS / 128), 128, GEMM_SMEM>>>(
        p_h16, p_w2T, b2, p_x1, p_mod + 5 * HID, out, ROWS, HID, MLPD);
}

// round 16
// speedup vs baseline: 1.2226x; 1.0113x over previous
#include <cuda_runtime.h>
#include <cuda_fp16.h>
#include <math.h>
#include <stdint.h>

// Problem constants
#define Bsz 16
#define SEQ 1024
#define HID 1152
#define NH 16
#define HD 72
#define MLPD 4608
#define ROWS (Bsz * SEQ)          // 16384
#define MODW (6 * HID)            // 6912
#define EPS 1e-6f

// ---------------- scratch (device globals; allocation-free) ----------------
__device__ float  g_mod[Bsz * MODW];
__device__ __half g_xn16[ROWS * HID];
__device__ __half g_qkv16[ROWS * 3 * HID];
__device__ __half g_o16[ROWS * HID];
__device__ float  g_x1[ROWS * HID];
__device__ __half g_h16[ROWS * MLPD];
// fp16 transposed weights [N][K]
__device__ __half g_wqkvT16[3 * HID * HID];
__device__ __half g_wprojT16[HID * HID];
__device__ __half g_w1T16[HID * MLPD];
__device__ __half g_w2T16[MLPD * HID];

__device__ __forceinline__ void mma_f16(
    float& c0, float& c1, float& c2, float& c3,
    unsigned a0, unsigned a1, unsigned a2, unsigned a3,
    unsigned b0, unsigned b1)
{
    asm volatile(
        "mma.sync.aligned.m16n8k16.row.col.f32.f16.f16.f32 "
        "{%0,%1,%2,%3}, {%4,%5,%6,%7}, {%8,%9}, {%0,%1,%2,%3};"
        : "+f"(c0), "+f"(c1), "+f"(c2), "+f"(c3)
        : "r"(a0), "r"(a1), "r"(a2), "r"(a3), "r"(b0), "r"(b1));
}

__device__ __forceinline__ void ldsm_x4(
    unsigned& r0, unsigned& r1, unsigned& r2, unsigned& r3, uint32_t addr)
{
    asm volatile("ldmatrix.sync.aligned.m8n8.x4.shared.b16 {%0,%1,%2,%3}, [%4];"
                 : "=r"(r0), "=r"(r1), "=r"(r2), "=r"(r3) : "r"(addr));
}

__device__ __forceinline__ void ldsm_x4t(
    unsigned& r0, unsigned& r1, unsigned& r2, unsigned& r3, uint32_t addr)
{
    asm volatile("ldmatrix.sync.aligned.m8n8.x4.trans.shared.b16 {%0,%1,%2,%3}, [%4];"
                 : "=r"(r0), "=r"(r1), "=r"(r2), "=r"(r3) : "r"(addr));
}

__device__ __forceinline__ void ldsm_x2t(
    unsigned& r0, unsigned& r1, uint32_t addr)
{
    asm volatile("ldmatrix.sync.aligned.m8n8.x2.trans.shared.b16 {%0,%1}, [%2];"
                 : "=r"(r0), "=r"(r1) : "r"(addr));
}

__device__ __forceinline__ void cp16s(uint32_t dst, const void* src) {
    asm volatile("cp.async.cg.shared.global [%0], [%1], 16;" :: "r"(dst), "l"(src));
}
__device__ __forceinline__ void cp_commit() {
    asm volatile("cp.async.commit_group;");
}
template <int N> __device__ __forceinline__ void cp_wait() {
    asm volatile("cp.async.wait_group %0;" :: "n"(N));
}
__device__ __forceinline__ uint32_t smem_u32(const void* p) {
    uint32_t a;
    asm("{ .reg .u64 t; cvta.to.shared.u64 t, %1; cvt.u32.u64 %0, t; }"
        : "=r"(a) : "l"(p));
    return a;
}
__device__ __forceinline__ unsigned h2u(__half2 h) {
    return *reinterpret_cast<unsigned*>(&h);
}

// --- kernel 0: ALL weight converts+transposes fp32 [K][N] -> fp16 [N][K] ----
#define WCVT_TILES 15552
__global__ __launch_bounds__(256) void wcvt_all_kernel(
    const float* __restrict__ wq, const float* __restrict__ wp,
    const float* __restrict__ w1p, const float* __restrict__ w2p,
    __half* __restrict__ oq, __half* __restrict__ op,
    __half* __restrict__ o1, __half* __restrict__ o2)
{
    __shared__ float t[32][33];
    int bid = blockIdx.x;
    const float* w; __half* wt; int K, N, tt;
    if (bid < 3888)       { w = wq;  wt = oq; K = HID;  N = 3 * HID; tt = bid; }
    else if (bid < 5184)  { w = wp;  wt = op; K = HID;  N = HID;     tt = bid - 3888; }
    else if (bid < 10368) { w = w1p; wt = o1; K = HID;  N = MLPD;    tt = bid - 5184; }
    else                  { w = w2p; wt = o2; K = MLPD; N = HID;     tt = bid - 10368; }
    int nT = N >> 5;
    int n0 = (tt % nT) * 32, k0 = (tt / nT) * 32;
    int tx = threadIdx.x & 31, ty = threadIdx.x >> 5;
    #pragma unroll
    for (int j = 0; j < 32; j += 8)
        t[ty + j][tx] = w[(size_t)(k0 + ty + j) * N + n0 + tx];
    __syncthreads();
    #pragma unroll
    for (int j = 0; j < 32; j += 8)
        wt[(size_t)(n0 + ty + j) * K + k0 + tx] = __float2half(t[tx][ty + j]);
}

// ------- kernel 1: mod = swish(c) @ w_mod + b_mod (batch-reuse) -------------
#define MODKG 8
#define MODKL (HID / MODKG)      // 144
#define MOD_SMEM ((Bsz * HID + MODKG * 32 * Bsz) * 4)   // 90112 bytes
__global__ __launch_bounds__(256) void mod_kernel(
    const float* __restrict__ c, const float* __restrict__ w_mod,
    const float* __restrict__ b_mod, float* __restrict__ mod)
{
    extern __shared__ float sm[];
    float* sct = sm;                   // [1152][16] swish(c) transposed
    float* red = sm + Bsz * HID;       // [8][32][16] partials
    int tid = threadIdx.x;
    for (int i = tid; i < Bsz * HID; i += 256) {
        int b = i / HID, k = i - b * HID;
        float v = c[i];
        sct[k * Bsz + b] = v / (1.f + expf(-v));
    }
    __syncthreads();
    int cl = tid & 31;
    int kg = tid >> 5;                 // 0..7
    int col = blockIdx.x * 32 + cl;
    float acc[Bsz];
    #pragma unroll
    for (int b = 0; b < Bsz; ++b) acc[b] = 0.f;
    int k0 = kg * MODKL;
    for (int k = k0; k < k0 + MODKL; ++k) {
        float w = w_mod[(size_t)k * MODW + col];
        const float4* s4 = (const float4*)(sct + k * Bsz);
        #pragma unroll
        for (int b4 = 0; b4 < 4; ++b4) {
            float4 s = s4[b4];
            acc[4 * b4 + 0] = fmaf(s.x, w, acc[4 * b4 + 0]);
            acc[4 * b4 + 1] = fmaf(s.y, w, acc[4 * b4 + 1]);
            acc[4 * b4 + 2] = fmaf(s.z, w, acc[4 * b4 + 2]);
            acc[4 * b4 + 3] = fmaf(s.w, w, acc[4 * b4 + 3]);
        }
    }
    #pragma unroll
    for (int b = 0; b < Bsz; ++b)
        red[(kg * 32 + cl) * Bsz + b] = acc[b];
    __syncthreads();
    #pragma unroll
    for (int t = 0; t < 2; ++t) {
        int task = tid + t * 256;
        int tc = task >> 4;
        int tb = task & 15;
        float s = b_mod[blockIdx.x * 32 + tc];
        #pragma unroll
        for (int g = 0; g < MODKG; ++g)
            s += red[(g * 32 + tc) * Bsz + tb];
        mod[tb * MODW + blockIdx.x * 32 + tc] = s;
    }
}

// --------- kernel 2: LN(x) * (1+sc) + sh  (per row), fp16 output ------------
__global__ __launch_bounds__(256) void ln_mod_kernel(
    const float* __restrict__ x, const float* __restrict__ mod,
    int shOff, int scOff, __half* __restrict__ out)
{
    __shared__ float buf[HID];
    __shared__ float red[16];
    int row = blockIdx.x;
    int b = row >> 10;
    int tid = threadIdx.x;
    const float* xr = x + (size_t)row * HID;
    float s = 0.f, s2 = 0.f;
    for (int i = tid; i < 288; i += 256) {
        float4 v = *(const float4*)(xr + i * 4);
        *(float4*)(buf + i * 4) = v;
        s  += v.x + v.y + v.z + v.w;
        s2 += v.x * v.x + v.y * v.y + v.z * v.z + v.w * v.w;
    }
    #pragma unroll
    for (int o = 16; o; o >>= 1) {
        s  += __shfl_xor_sync(0xffffffffu, s,  o);
        s2 += __shfl_xor_sync(0xffffffffu, s2, o);
    }
    if ((tid & 31) == 0) { red[tid >> 5] = s; red[8 + (tid >> 5)] = s2; }
    __syncthreads();
    float S = 0.f, S2 = 0.f;
    #pragma unroll
    for (int w = 0; w < 8; ++w) { S += red[w]; S2 += red[8 + w]; }
    float mean = S * (1.f / HID);
    float var  = S2 * (1.f / HID) - mean * mean;
    float rstd = rsqrtf(var + EPS);
    const float* mrow = mod + b * MODW;
    __half* orow = out + (size_t)row * HID;
    for (int i = tid; i < 288; i += 256) {
        float4 v   = *(const float4*)(buf + i * 4);
        float4 sc4 = *(const float4*)(mrow + scOff + i * 4);
        float4 sh4 = *(const float4*)(mrow + shOff + i * 4);
        float o0 = fmaf((v.x - mean) * rstd, 1.f + sc4.x, sh4.x);
        float o1 = fmaf((v.y - mean) * rstd, 1.f + sc4.y, sh4.y);
        float o2 = fmaf((v.z - mean) * rstd, 1.f + sc4.z, sh4.z);
        float o3 = fmaf((v.w - mean) * rstd, 1.f + sc4.w, sh4.w);
        uint2 pk;
        pk.x = h2u(__floats2half2_rn(o0, o1));
        pk.y = h2u(__floats2half2_rn(o2, o3));
        *(uint2*)(orow + i * 4) = pk;
    }
}

// --------------- kernel 3: per-head LN of q and k (fp16, half2) -------------
__global__ __launch_bounds__(256) void qkln_kernel(
    __half* __restrict__ qkv, const float* __restrict__ g_q,
    const float* __restrict__ g_k)
{
    int warp = blockIdx.x * 8 + (threadIdx.x >> 5);
    int lane = threadIdx.x & 31;
    int h  = warp & 15;
    int qk = (warp >> 4) & 1;
    int bn = warp >> 5;
    __half2* p2 = (__half2*)(qkv + (size_t)bn * (3 * HID) + qk * HID + h * HD);
    float2 va = __half22float2(p2[lane]);
    float2 vb = (lane < 4) ? __half22float2(p2[32 + lane]) : make_float2(0.f, 0.f);
    float s  = va.x + va.y + vb.x + vb.y;
    float s2 = va.x * va.x + va.y * va.y + vb.x * vb.x + vb.y * vb.y;
    #pragma unroll
    for (int o = 16; o; o >>= 1) {
        s  += __shfl_xor_sync(0xffffffffu, s,  o);
        s2 += __shfl_xor_sync(0xffffffffu, s2, o);
    }
    float mean = s * (1.f / HD);
    float var  = s2 * (1.f / HD) - mean * mean;
    float rstd = rsqrtf(var + EPS);
    const float* g = qk ? g_k : g_q;
    float2 ga = *(const float2*)(g + 2 * lane);
    p2[lane] = __floats2half2_rn((va.x - mean) * rstd * ga.x,
                                 (va.y - mean) * rstd * ga.y);
    if (lane < 4) {
        float2 gb = *(const float2*)(g + 64 + 2 * lane);
        p2[32 + lane] = __floats2half2_rn((vb.x - mean) * rstd * gb.x,
                                          (vb.y - mean) * rstd * gb.y);
    }
}

// ------- kernel 4: flash attention (cp.async K/V pipeline + trans ldsm) -----
#define AQ 128
#define AK 64
#define QH 88     // halves stride for qs/ks/vs rows
#define KVBUF_H (AK * QH)                  // halves per K or V buffer
#define ATTN_SMEM ((AQ * QH + 4 * KVBUF_H) * 2)   // 67584 bytes

__global__ __launch_bounds__(256) void attn_kernel(
    const __half* __restrict__ qkv, __half* __restrict__ o)
{
    extern __shared__ __half smh[];
    __half* qs = smh;                      // [128][88]
    __half* kv = qs + AQ * QH;             // [2][ks 64x88, vs 64x88]

    int tid = threadIdx.x;
    int lane = tid & 31;
    int warp = tid >> 5;
    int grp = lane >> 2;
    int t4 = lane & 3;
    int m0 = warp * 16;
    int lsel = lane & 15;
    int ksel = (lane >> 4) * 8;

    int q0 = blockIdx.x * AQ;
    int h = blockIdx.y, b = blockIdx.z;
    const size_t baseBN = (size_t)b * SEQ * (3 * HID);
    const int hoff = h * HD;
    const float scale = 0.11785113019775793f;

    uint32_t qsA = smem_u32(qs);
    uint32_t kvA = smem_u32(kv);
    int vrow4 = ((lane >> 3) & 1) * 8 + (lane & 7);
    int vcol4 = (lane >> 4) * 8;
    uint32_t vrel4 = (uint32_t)(vrow4 * QH + vcol4) * 2;
    int vrow2 = (((lane & 15) >> 3) & 1) * 8 + (lane & 7);
    uint32_t vrel2 = (uint32_t)(vrow2 * QH + 64) * 2;

    for (int idx = tid; idx < AQ * 9; idx += 256) {
        int r = idx / 9, c = (idx - r * 9) * 8;
        *(float4*)(qs + r * QH + c) =
            *(const float4*)(qkv + baseBN + (size_t)(q0 + r) * (3 * HID) + hoff + c);
    }
    for (int idx = tid; idx < AQ + 2 * AK; idx += 256) {
        __half* base;
        if (idx < AQ)            base = qs + idx * QH;
        else if (idx < AQ + AK)  base = kv + (idx - AQ) * QH;
        else                     base = kv + 2 * KVBUF_H + (idx - AQ - AK) * QH;
        *(float4*)(base + 72) = make_float4(0.f, 0.f, 0.f, 0.f);
    }

    auto load_kv = [&](int kt, int bi) {
        uint32_t kD = kvA + (uint32_t)bi * (2 * KVBUF_H * 2);
        uint32_t vD = kD + KVBUF_H * 2;
        const __half* base = qkv + baseBN + (size_t)(kt * AK) * (3 * HID) + hoff;
        for (int idx = tid; idx < 1152; idx += 256) {
            int isv = idx >= 576;
            int j = isv ? idx - 576 : idx;
            int r = j / 9, c = (j - r * 9) * 8;
            const __half* src = base + (size_t)r * (3 * HID) + (isv ? 2 * HID : HID) + c;
            cp16s((isv ? vD : kD) + (uint32_t)(r * QH + c) * 2, src);
        }
    };

    float accO[9][4];
    #pragma unroll
    for (int di = 0; di < 9; ++di)
        #pragma unroll
        for (int e = 0; e < 4; ++e) accO[di][e] = 0.f;
    float mi0 = -INFINITY, mi1 = -INFINITY;
    float li0 = 0.f, li1 = 0.f;

    load_kv(0, 0);
    cp_commit();

    for (int kt = 0; kt < SEQ / AK; ++kt) {
        cp_wait<0>();
        __syncthreads();

        if (kt + 1 < SEQ / AK) {
            load_kv(kt + 1, (kt + 1) & 1);
        }
        cp_commit();

        uint32_t ksCur = kvA + (uint32_t)(kt & 1) * (2 * KVBUF_H * 2);
        uint32_t vsCur = ksCur + KVBUF_H * 2;

        // ---- S = Q K^T ----
        float sacc[8][4];
        #pragma unroll
        for (int ni = 0; ni < 8; ++ni)
            #pragma unroll
            for (int e = 0; e < 4; ++e) sacc[ni][e] = 0.f;
        #pragma unroll
        for (int ksb = 0; ksb < 5; ++ksb) {
            int k16 = ksb * 16;
            unsigned a0, a1, a2, a3;
            ldsm_x4(a0, a1, a2, a3, qsA + ((m0 + lsel) * QH + k16 + ksel) * 2);
            unsigned bf[8][2];
            #pragma unroll
            for (int p = 0; p < 4; ++p)
                ldsm_x4(bf[2 * p][0], bf[2 * p + 1][0], bf[2 * p][1], bf[2 * p + 1][1],
                        ksCur + ((p * 16 + lsel) * QH + k16 + ksel) * 2);
            #pragma unroll
            for (int ni = 0; ni < 8; ++ni)
                mma_f16(sacc[ni][0], sacc[ni][1], sacc[ni][2], sacc[ni][3],
                        a0, a1, a2, a3, bf[ni][0], bf[ni][1]);
        }

        // ---- online softmax ----
        float rmax0 = -INFINITY, rmax1 = -INFINITY;
        #pragma unroll
        for (int ni = 0; ni < 8; ++ni) {
            sacc[ni][0] *= scale; sacc[ni][1] *= scale;
            sacc[ni][2] *= scale; sacc[ni][3] *= scale;
            rmax0 = fmaxf(rmax0, fmaxf(sacc[ni][0], sacc[ni][1]));
            rmax1 = fmaxf(rmax1, fmaxf(sacc[ni][2], sacc[ni][3]));
        }
        #pragma unroll
        for (int off = 1; off < 4; off <<= 1) {
            rmax0 = fmaxf(rmax0, __shfl_xor_sync(0xffffffffu, rmax0, off));
            rmax1 = fmaxf(rmax1, __shfl_xor_sync(0xffffffffu, rmax1, off));
        }
        float newm0 = fmaxf(mi0, rmax0);
        float newm1 = fmaxf(mi1, rmax1);
        float alpha0 = __expf(mi0 - newm0);
        float alpha1 = __expf(mi1 - newm1);
        mi0 = newm0; mi1 = newm1;
        float rsum0 = 0.f, rsum1 = 0.f;
        unsigned ph0[8], ph1[8];
        #pragma unroll
        for (int ni = 0; ni < 8; ++ni) {
            float p0 = __expf(sacc[ni][0] - newm0);
            float p1 = __expf(sacc[ni][1] - newm0);
            float p2 = __expf(sacc[ni][2] - newm1);
            float p3 = __expf(sacc[ni][3] - newm1);
            rsum0 += p0 + p1; rsum1 += p2 + p3;
            ph0[ni] = h2u(__floats2half2_rn(p0, p1));
            ph1[ni] = h2u(__floats2half2_rn(p2, p3));
        }
        #pragma unroll
        for (int off = 1; off < 4; off <<= 1) {
            rsum0 += __shfl_xor_sync(0xffffffffu, rsum0, off);
            rsum1 += __shfl_xor_sync(0xffffffffu, rsum1, off);
        }
        li0 = li0 * alpha0 + rsum0;
        li1 = li1 * alpha1 + rsum1;
        #pragma unroll
        for (int di = 0; di < 9; ++di) {
            accO[di][0] *= alpha0; accO[di][1] *= alpha0;
            accO[di][2] *= alpha1; accO[di][3] *= alpha1;
        }

        // ---- O += P V ----
        #pragma unroll
        for (int kb = 0; kb < 4; ++kb) {
            unsigned a0 = ph0[2 * kb],     a2 = ph0[2 * kb + 1];
            unsigned a1 = ph1[2 * kb],     a3 = ph1[2 * kb + 1];
            uint32_t vkb = vsCur + (uint32_t)(kb * 16 * QH) * 2;
            unsigned vf[9][2];
            #pragma unroll
            for (int p = 0; p < 4; ++p)
                ldsm_x4t(vf[2 * p][0], vf[2 * p][1], vf[2 * p + 1][0], vf[2 * p + 1][1],
                         vkb + vrel4 + (uint32_t)(p * 16) * 2);
            ldsm_x2t(vf[8][0], vf[8][1], vkb + vrel2);
            #pragma unroll
            for (int di = 0; di < 9; ++di)
                mma_f16(accO[di][0], accO[di][1], accO[di][2], accO[di][3],
                        a0, a1, a2, a3, vf[di][0], vf[di][1]);
        }
    }

    float inv0 = 1.f / li0, inv1 = 1.f / li1;
    int row0 = q0 + m0 + grp;
    size_t b0a = ((size_t)b * SEQ + row0) * HID + hoff;
    size_t b1a = ((size_t)b * SEQ + row0 + 8) * HID + hoff;
    #pragma unroll
    for (int di = 0; di < 9; ++di) {
        int d = di * 8 + t4 * 2;
        *(__half2*)(o + b0a + d) = __floats2half2_rn(accO[di][0] * inv0, accO[di][1] * inv0);
        *(__half2*)(o + b1a + d) = __floats2half2_rn(accO[di][2] * inv1, accO[di][3] * inv1);
    }
}

// ----- kernel 5: FP16 GEMM 128x128x64, 2 stages, 128 thr, 64x64 warps -------
#define TBK 64
#define ASTRH 72                          // halves per smem row (64 + 8 pad)
#define TILE_H_BYTES (128 * ASTRH * 2)    // 18432
#define NSTAGE 2
#define GEMM_SMEM (NSTAGE * 2 * TILE_H_BYTES)   // 73728

template <int EPI, typename OutT>
__global__ __launch_bounds__(128, 3) void hgemm_kernel(
    const __half* __restrict__ A, const __half* __restrict__ BT,
    const float* __restrict__ bias, const float* __restrict__ res,
    const float* __restrict__ gate, OutT* __restrict__ C,
    int M, int N, int K)
{
    extern __shared__ char smc[];
    uint32_t sbase = smem_u32(smc);

    int tid = threadIdx.x;
    int lane = tid & 31;
    int warp = tid >> 5;             // 0..3
    int m0 = (warp & 1) * 64;        // 2 warps in M
    int n0 = (warp >> 1) * 64;       // 2 warps in N
    int grp = lane >> 2;
    int t4 = lane & 3;
    int lsel = lane & 15;
    int ksel = (lane >> 4) * 8;

    int cRow = blockIdx.y, cCol = blockIdx.x;
    const __half* Ab = A + (size_t)cRow * 128 * K;
    const __half* Bb = BT + (size_t)cCol * 128 * K;

    float acc[4][8][4];
    #pragma unroll
    for (int mi = 0; mi < 4; ++mi)
        #pragma unroll
        for (int ni = 0; ni < 8; ++ni)
            #pragma unroll
            for (int e = 0; e < 4; ++e) acc[mi][ni][e] = 0.f;

    int KT = K / TBK;

    auto load_stage = [&](int kt, int s) {
        uint32_t aBase = sbase + s * TILE_H_BYTES;
        uint32_t bBase = sbase + (NSTAGE + s) * TILE_H_BYTES;
        const __half* Asrc = Ab + kt * TBK;
        const __half* Bsrc = Bb + kt * TBK;
        #pragma unroll
        for (int j = 0; j < 8; ++j) {
            int idx = tid + j * 128;
            int r = idx >> 3, c = idx & 7;
            cp16s(aBase + r * (ASTRH * 2) + c * 16, Asrc + (size_t)r * K + c * 8);
            cp16s(bBase + r * (ASTRH * 2) + c * 16, Bsrc + (size_t)r * K + c * 8);
        }
    };

    load_stage(0, 0);
    cp_commit();

    for (int kt = 0; kt < KT; ++kt) {
        cp_wait<0>();
        __syncthreads();

        if (kt + 1 < KT) load_stage(kt + 1, (kt + 1) & 1);
        cp_commit();

        int st = kt & 1;
        uint32_t aBase = sbase + st * TILE_H_BYTES;
        uint32_t bBase = sbase + (NSTAGE + st) * TILE_H_BYTES;
        #pragma unroll
        for (int ks = 0; ks < 4; ++ks) {
            int k16 = ks * 16;
            unsigned af[4][4], bf[8][2];
            #pragma unroll
            for (int mi = 0; mi < 4; ++mi)
                ldsm_x4(af[mi][0], af[mi][1], af[mi][2], af[mi][3],
                        aBase + ((m0 + mi * 16 + lsel) * ASTRH + k16 + ksel) * 2);
            #pragma unroll
            for (int p = 0; p < 4; ++p)
                ldsm_x4(bf[2 * p][0], bf[2 * p + 1][0], bf[2 * p][1], bf[2 * p + 1][1],
                        bBase + ((n0 + p * 16 + lsel) * ASTRH + k16 + ksel) * 2);
            #pragma unroll
            for (int mi = 0; mi < 4; ++mi)
                #pragma unroll
                for (int ni = 0; ni < 8; ++ni)
                    mma_f16(acc[mi][ni][0], acc[mi][ni][1], acc[mi][ni][2], acc[mi][ni][3],
                            af[mi][0], af[mi][1], af[mi][2], af[mi][3],
                            bf[ni][0], bf[ni][1]);
        }
    }

    // ---- epilogue ----
    #pragma unroll
    for (int mi = 0; mi < 4; ++mi) {
        #pragma unroll
        for (int half_ = 0; half_ < 2; ++half_) {
            int row = cRow * 128 + m0 + mi * 16 + grp + half_ * 8;
            int gb = (row >> 10) * MODW;
            #pragma unroll
            for (int ni = 0; ni < 8; ++ni) {
                int col = cCol * 128 + n0 + ni * 8 + t4 * 2;
                float v0 = acc[mi][ni][half_ * 2 + 0] + bias[col];
                float v1 = acc[mi][ni][half_ * 2 + 1] + bias[col + 1];
                if (EPI == 1) {
                    float i0 = 0.7978845608028654f * (v0 + 0.044715f * v0 * v0 * v0);
                    float i1 = 0.7978845608028654f * (v1 + 0.044715f * v1 * v1 * v1);
                    v0 = v0 / (1.f + __expf(-2.f * i0));
                    v1 = v1 / (1.f + __expf(-2.f * i1));
                } else if (EPI == 2) {
                    v0 = fmaf(gate[gb + col],     v0, res[(size_t)row * N + col]);
                    v1 = fmaf(gate[gb + col + 1], v1, res[(size_t)row * N + col + 1]);
                }
                OutT* dst = C + (size_t)row * N + col;
                if (sizeof(OutT) == 2) {
                    *(__half2*)dst = __floats2half2_rn(v0, v1);
                } else {
                    *(float2*)dst = make_float2(v0, v1);
                }
            }
        }
    }
}

// ----- kernel 5b: FP16 GEMM 64x128x64 (small-grid variant for proj/mlp2) ----
// 128 thr, 4 warps of 32x64, NSTAGE=2, 55.3 KB smem -> 4 CTAs/SM (16 warps).
// Same K accumulation order per output -> bit-identical results.
#define A64_TILE_B (64 * ASTRH * 2)       // 9216
#define G64_SMEM (NSTAGE * (A64_TILE_B + TILE_H_BYTES))   // 55296

template <int EPI, typename OutT>
__global__ __launch_bounds__(128, 4) void hgemm64_kernel(
    const __half* __restrict__ A, const __half* __restrict__ BT,
    const float* __restrict__ bias, const float* __restrict__ res,
    const float* __restrict__ gate, OutT* __restrict__ C,
    int M, int N, int K)
{
    extern __shared__ char smc[];
    uint32_t sbase = smem_u32(smc);

    int tid = threadIdx.x;
    int lane = tid & 31;
    int warp = tid >> 5;             // 0..3
    int m0 = (warp & 1) * 32;        // 2 warps in M
    int n0 = (warp >> 1) * 64;       // 2 warps in N
    int grp = lane >> 2;
    int t4 = lane & 3;
    int lsel = lane & 15;
    int ksel = (lane >> 4) * 8;

    int cRow = blockIdx.y, cCol = blockIdx.x;
    const __half* Ab = A + (size_t)cRow * 64 * K;
    const __half* Bb = BT + (size_t)cCol * 128 * K;

    float acc[2][8][4];
    #pragma unroll
    for (int mi = 0; mi < 2; ++mi)
        #pragma unroll
        for (int ni = 0; ni < 8; ++ni)
            #pragma unroll
            for (int e = 0; e < 4; ++e) acc[mi][ni][e] = 0.f;

    int KT = K / TBK;

    // A: 64x8 = 512 chunks (4/thr); B: 128x8 = 1024 chunks (8/thr)
    auto load_stage = [&](int kt, int s) {
        uint32_t aBase = sbase + s * A64_TILE_B;
        uint32_t bBase = sbase + NSTAGE * A64_TILE_B + s * TILE_H_BYTES;
        const __half* Asrc = Ab + kt * TBK;
        const __half* Bsrc = Bb + kt * TBK;
        #pragma unroll
        for (int j = 0; j < 4; ++j) {
            int idx = tid + j * 128;
            int r = idx >> 3, c = idx & 7;
            cp16s(aBase + r * (ASTRH * 2) + c * 16, Asrc + (size_t)r * K + c * 8);
        }
        #pragma unroll
        for (int j = 0; j < 8; ++j) {
            int idx = tid + j * 128;
            int r = idx >> 3, c = idx & 7;
            cp16s(bBase + r * (ASTRH * 2) + c * 16, Bsrc + (size_t)r * K + c * 8);
        }
    };

    load_stage(0, 0);
    cp_commit();

    for (int kt = 0; kt < KT; ++kt) {
        cp_wait<0>();
        __syncthreads();

        if (kt + 1 < KT) load_stage(kt + 1, (kt + 1) & 1);
        cp_commit();

        int st = kt & 1;
        uint32_t aBase = sbase + st * A64_TILE_B;
        uint32_t bBase = sbase + NSTAGE * A64_TILE_B + st * TILE_H_BYTES;
        #pragma unroll
        for (int ks = 0; ks < 4; ++ks) {
            int k16 = ks * 16;
            unsigned af[2][4], bf[8][2];
            #pragma unroll
            for (int mi = 0; mi < 2; ++mi)
                ldsm_x4(af[mi][0], af[mi][1], af[mi][2], af[mi][3],
                        aBase + ((m0 + mi * 16 + lsel) * ASTRH + k16 + ksel) * 2);
            #pragma unroll
            for (int p = 0; p < 4; ++p)
                ldsm_x4(bf[2 * p][0], bf[2 * p + 1][0], bf[2 * p][1], bf[2 * p + 1][1],
                        bBase + ((n0 + p * 16 + lsel) * ASTRH + k16 + ksel) * 2);
            #pragma unroll
            for (int mi = 0; mi < 2; ++mi)
                #pragma unroll
                for (int ni = 0; ni < 8; ++ni)
                    mma_f16(acc[mi][ni][0], acc[mi][ni][1], acc[mi][ni][2], acc[mi][ni][3],
                            af[mi][0], af[mi][1], af[mi][2], af[mi][3],
                            bf[ni][0], bf[ni][1]);
        }
    }

    // ---- epilogue ----
    #pragma unroll
    for (int mi = 0; mi < 2; ++mi) {
        #pragma unroll
        for (int half_ = 0; half_ < 2; ++half_) {
            int row = cRow * 64 + m0 + mi * 16 + grp + half_ * 8;
            int gb = (row >> 10) * MODW;
            #pragma unroll
            for (int ni = 0; ni < 8; ++ni) {
                int col = cCol * 128 + n0 + ni * 8 + t4 * 2;
                float v0 = acc[mi][ni][half_ * 2 + 0] + bias[col];
                float v1 = acc[mi][ni][half_ * 2 + 1] + bias[col + 1];
                if (EPI == 1) {
                    float i0 = 0.7978845608028654f * (v0 + 0.044715f * v0 * v0 * v0);
                    float i1 = 0.7978845608028654f * (v1 + 0.044715f * v1 * v1 * v1);
                    v0 = v0 / (1.f + __expf(-2.f * i0));
                    v1 = v1 / (1.f + __expf(-2.f * i1));
                } else if (EPI == 2) {
                    v0 = fmaf(gate[gb + col],     v0, res[(size_t)row * N + col]);
                    v1 = fmaf(gate[gb + col + 1], v1, res[(size_t)row * N + col + 1]);
                }
                OutT* dst = C + (size_t)row * N + col;
                if (sizeof(OutT) == 2) {
                    *(__half2*)dst = __floats2half2_rn(v0, v1);
                } else {
                    *(float2*)dst = make_float2(v0, v1);
                }
            }
        }
    }
}

// ---------------------------- launcher --------------------------------------
extern "C" void kernel_launch(void* const* d_in, const int* in_sizes, int n_in,
                              void* d_out, int out_size)
{
    const float* x      = (const float*)d_in[0];
    const float* c      = (const float*)d_in[1];
    const float* w_mod  = (const float*)d_in[2];
    const float* b_mod  = (const float*)d_in[3];
    const float* w_qkv  = (const float*)d_in[4];
    const float* b_qkv  = (const float*)d_in[5];
    const float* gq     = (const float*)d_in[6];
    const float* gk     = (const float*)d_in[7];
    const float* w_proj = (const float*)d_in[8];
    const float* b_proj = (const float*)d_in[9];
    const float* w1     = (const float*)d_in[10];
    const float* b1     = (const float*)d_in[11];
    const float* w2     = (const float*)d_in[12];
    const float* b2     = (const float*)d_in[13];
    float* out = (float*)d_out;

    float *p_mod, *p_x1;
    __half *p_xn16, *p_qkv16, *p_o16, *p_h16, *p_wqkvT, *p_wprojT, *p_w1T, *p_w2T;
    cudaGetSymbolAddress((void**)&p_mod, g_mod);
    cudaGetSymbolAddress((void**)&p_xn16, g_xn16);
    cudaGetSymbolAddress((void**)&p_qkv16, g_qkv16);
    cudaGetSymbolAddress((void**)&p_o16, g_o16);
    cudaGetSymbolAddress((void**)&p_x1,  g_x1);
    cudaGetSymbolAddress((void**)&p_h16, g_h16);
    cudaGetSymbolAddress((void**)&p_wqkvT, g_wqkvT16);
    cudaGetSymbolAddress((void**)&p_wprojT, g_wprojT16);
    cudaGetSymbolAddress((void**)&p_w1T, g_w1T16);
    cudaGetSymbolAddress((void**)&p_w2T, g_w2T16);

    cudaFuncSetAttribute(attn_kernel,
                         cudaFuncAttributeMaxDynamicSharedMemorySize, ATTN_SMEM);
    cudaFuncSetAttribute(mod_kernel,
                         cudaFuncAttributeMaxDynamicSharedMemorySize, MOD_SMEM);
    cudaFuncSetAttribute(hgemm_kernel<0, __half>,
                         cudaFuncAttributeMaxDynamicSharedMemorySize, GEMM_SMEM);
    cudaFuncSetAttribute(hgemm_kernel<1, __half>,
                         cudaFuncAttributeMaxDynamicSharedMemorySize, GEMM_SMEM);
    cudaFuncSetAttribute(hgemm64_kernel<2, float>,
                         cudaFuncAttributeMaxDynamicSharedMemorySize, G64_SMEM);

    // 0. convert+transpose ALL weights in one launch
    wcvt_all_kernel<<<WCVT_TILES, 256>>>(w_qkv, w_proj, w1, w2,
                                         p_wqkvT, p_wprojT, p_w1T, p_w2T);

    // 1. adaLN modulation (batch-reuse: w_mod read once)
    mod_kernel<<<MODW / 32, 256, MOD_SMEM>>>(c, w_mod, b_mod, p_mod);
    // 2. LN + modulate (MSA) -> fp16
    ln_mod_kernel<<<ROWS, 256>>>(x, p_mod, 0, HID, p_xn16);
    // 3. QKV GEMM -> fp16 qkv
    hgemm_kernel<0, __half><<<dim3(3 * HID / 128, ROWS / 128), 128, GEMM_SMEM>>>(
        p_xn16, p_wqkvT, b_qkv, nullptr, nullptr, p_qkv16, ROWS, 3 * HID, HID);
    // 4. per-head LN of q,k
    qkln_kernel<<<ROWS * 32 / 8, 256>>>(p_qkv16, gq, gk);
    // 5. attention -> fp16 o
    attn_kernel<<<dim3(SEQ / AQ, NH, Bsz), 256, ATTN_SMEM>>>(p_qkv16, p_o16);
    // 6. proj + gated residual -> fp32 x1 (M=64 variant: 2304 CTAs)
    hgemm64_kernel<2, float><<<dim3(HID / 128, ROWS / 64), 128, G64_SMEM>>>(
        p_o16, p_wprojT, b_proj, x, p_mod + 2 * HID, p_x1, ROWS, HID, HID);
    // 7. LN + modulate (MLP) -> fp16
    ln_mod_kernel<<<ROWS, 256>>>(p_x1, p_mod, 3 * HID, 4 * HID, p_xn16);
    // 8. MLP up + gelu -> fp16 h
    hgemm_kernel<1, __half><<<dim3(MLPD / 128, ROWS / 128), 128, GEMM_SMEM>>>(
        p_xn16, p_w1T, b1, nullptr, nullptr, p_h16, ROWS, MLPD, HID);
    // 9. MLP down + gated residual -> fp32 out (M=64 variant)
    hgemm64_kernel<2, float><<<dim3(HID / 128, ROWS / 64), 128, G64_SMEM>>>(
        p_h16, p_w2T, b2, p_x1, p_mod + 5 * HID, out, ROWS, HID, MLPD);
}